// round 7
// baseline (speedup 1.0000x reference)
#include <cuda_runtime.h>
#include <cuda_bf16.h>
#include <cstdint>

#define BB   2
#define TT   2048
#define KK   1024
#define HH   16
#define SS   64
#define MROWS (BB*TT)   // 4096

// ---- scratch (static device globals; no allocation allowed) ----
__device__ __nv_bfloat16 g_xh[MROWS*KK], g_xl[MROWS*KK];
__device__ __nv_bfloat16 g_Wqh[KK*KK],  g_Wql[KK*KK];
__device__ __nv_bfloat16 g_Wkh[KK*KK],  g_Wkl[KK*KK];
__device__ __nv_bfloat16 g_Qh[MROWS*KK], g_Ql[MROWS*KK];
__device__ __nv_bfloat16 g_Kh[MROWS*KK], g_Kl[MROWS*KK];
__device__ __nv_bfloat16 g_Vh[MROWS*KK], g_Vl[MROWS*KK];
__device__ float g_ys[MROWS*KK];
// int8 two-digit operands + row scales
__device__ int8_t g_x1[MROWS*KK], g_x2[MROWS*KK];
__device__ int8_t g_Wv1[KK*KK],   g_Wv2[KK*KK];
__device__ int8_t g_Wu1[KK*KK],   g_Wu2[KK*KK];
__device__ int8_t g_y1[MROWS*KK], g_y2[MROWS*KK];
__device__ float g_sx[MROWS], g_swv[KK], g_swu[KK], g_sy[MROWS];
__device__ int g_idx[BB*TT];
__device__ int g_nv [BB];

// ============================================================================
// helpers
// ============================================================================
__device__ __forceinline__ uint32_t smem_u32(const void* p) {
    uint32_t a;
    asm("{ .reg .u64 t; cvta.to.shared.u64 t, %1; cvt.u32.u64 %0, t; }"
        : "=r"(a) : "l"(p));
    return a;
}

__device__ __forceinline__ void mma_bf16(float d[4],
                                         uint32_t a0, uint32_t a1, uint32_t a2, uint32_t a3,
                                         uint32_t b0, uint32_t b1) {
    asm volatile(
        "mma.sync.aligned.m16n8k16.row.col.f32.bf16.bf16.f32 "
        "{%0,%1,%2,%3}, {%4,%5,%6,%7}, {%8,%9}, {%0,%1,%2,%3};"
        : "+f"(d[0]), "+f"(d[1]), "+f"(d[2]), "+f"(d[3])
        : "r"(a0), "r"(a1), "r"(a2), "r"(a3), "r"(b0), "r"(b1));
}

__device__ __forceinline__ void mma_s8(int d[4],
                                       uint32_t a0, uint32_t a1, uint32_t a2, uint32_t a3,
                                       uint32_t b0, uint32_t b1) {
    asm volatile(
        "mma.sync.aligned.m16n8k32.row.col.s32.s8.s8.s32 "
        "{%0,%1,%2,%3}, {%4,%5,%6,%7}, {%8,%9}, {%0,%1,%2,%3};"
        : "+r"(d[0]), "+r"(d[1]), "+r"(d[2]), "+r"(d[3])
        : "r"(a0), "r"(a1), "r"(a2), "r"(a3), "r"(b0), "r"(b1));
}

#define LDSM4(r0, r1, r2, r3, addr) \
    asm volatile("ldmatrix.sync.aligned.m8n8.x4.shared.b16 {%0,%1,%2,%3}, [%4];" \
                 : "=r"(r0), "=r"(r1), "=r"(r2), "=r"(r3) : "r"(addr))

__device__ __forceinline__ void split2(float2 f, uint32_t& h, uint32_t& l) {
    __nv_bfloat162 hh = __float22bfloat162_rn(f);
    float2 hf = __bfloat1622float2(hh);
    __nv_bfloat162 ll = __float22bfloat162_rn(make_float2(f.x - hf.x, f.y - hf.y));
    h = *(uint32_t*)&hh;
    l = *(uint32_t*)&ll;
}

// ============================================================================
// preprocessing: fp32 -> (hi, lo) bf16
// ============================================================================
__global__ __launch_bounds__(256)
void split_kernel(const float* __restrict__ in,
                  __nv_bfloat16* __restrict__ hi,
                  __nv_bfloat16* __restrict__ lo, int n2)
{
    for (int i = blockIdx.x * blockDim.x + threadIdx.x; i < n2;
         i += gridDim.x * blockDim.x) {
        float2 f = ((const float2*)in)[i];
        uint32_t h, l;
        split2(f, h, l);
        ((uint32_t*)hi)[i] = h;
        ((uint32_t*)lo)[i] = l;
    }
}

// ============================================================================
// preprocessing: fp32 row -> two-digit base-128 int8 + fp32 row scale.
// One warp per row of 1024 elements.
// ============================================================================
__global__ __launch_bounds__(256)
void quant_kernel(const float* __restrict__ in,
                  int8_t* __restrict__ d1, int8_t* __restrict__ d2,
                  float* __restrict__ scale, int rows)
{
    const int warp = blockIdx.x * 8 + (threadIdx.x >> 5);
    const int lane = threadIdx.x & 31;
    if (warp >= rows) return;
    const float4* p = (const float4*)(in + (size_t)warp * KK);
    float4 v[8];
    float mx = 0.f;
#pragma unroll
    for (int j = 0; j < 8; j++) {
        v[j] = p[lane + 32 * j];
        mx = fmaxf(mx, fmaxf(fmaxf(fabsf(v[j].x), fabsf(v[j].y)),
                             fmaxf(fabsf(v[j].z), fabsf(v[j].w))));
    }
#pragma unroll
    for (int o = 16; o > 0; o >>= 1)
        mx = fmaxf(mx, __shfl_xor_sync(0xffffffffu, mx, o));
    const float s   = (mx > 0.f) ? mx / 126.f : 1.f;
    const float inv = (mx > 0.f) ? 126.f / mx : 0.f;
    if (lane == 0) scale[warp] = s;
    char4* o1 = (char4*)(d1 + (size_t)warp * KK);
    char4* o2 = (char4*)(d2 + (size_t)warp * KK);
#pragma unroll
    for (int j = 0; j < 8; j++) {
        float q[4] = { v[j].x * inv, v[j].y * inv, v[j].z * inv, v[j].w * inv };
        int i1[4], i2[4];
#pragma unroll
        for (int c = 0; c < 4; c++) {
            i1[c] = __float2int_rn(q[c]);
            i2[c] = __float2int_rn((q[c] - (float)i1[c]) * 128.f);
        }
        o1[lane + 32 * j] = make_char4((char)i1[0], (char)i1[1], (char)i1[2], (char)i1[3]);
        o2[lane + 32 * j] = make_char4((char)i2[0], (char)i2[1], (char)i2[2], (char)i2[3]);
    }
}

// ============================================================================
// mask compaction (unchanged, proven)
// ============================================================================
__global__ __launch_bounds__(1024)
void compact_kernel(const int* __restrict__ mask, int* __restrict__ idx,
                    int* __restrict__ nv)
{
    __shared__ int s[1024];
    const int b = blockIdx.x;
    const int t = threadIdx.x;
    const int m0 = mask[b * TT + 2 * t];
    const int m1 = mask[b * TT + 2 * t + 1];
    const int c  = m0 + m1;
    s[t] = c;
    __syncthreads();
    for (int off = 1; off < 1024; off <<= 1) {
        int v = s[t];
        int u = (t >= off) ? s[t - off] : 0;
        __syncthreads();
        s[t] = v + u;
        __syncthreads();
    }
    const int incl = s[t];
    const int excl = incl - c;
    if (m0) idx[b * TT + excl] = 2 * t;
    if (m1) idx[b * TT + excl + m0] = 2 * t + 1;
    if (t == 1023) nv[b] = incl;
}

// ============================================================================
// Split-bf16 GEMM (round-6 body, but 1 CTA/SM: no forced register spills).
// ============================================================================
#define GBK 32
#define NIT (KK / GBK)          // 32
#define BKP 40                  // bf16 row stride (80 B)
#define ATILE (128 * BKP)
#define GEMM_SMEM (8 * ATILE * 2)   // 81920 B

__global__ void __launch_bounds__(256)
gemm_bf16_kernel(const __nv_bfloat16* __restrict__ Agh,
                 const __nv_bfloat16* __restrict__ Agl,
                 const __nv_bfloat16* __restrict__ Bgh,
                 const __nv_bfloat16* __restrict__ Bgl,
                 __nv_bfloat16* __restrict__ Ch,
                 __nv_bfloat16* __restrict__ Cl,
                 int M, int N)
{
    extern __shared__ __nv_bfloat16 sm[];
    const uint32_t sbase = smem_u32(sm);

    const int tid  = threadIdx.x;
    const int lane = tid & 31;
    const int wid  = tid >> 5;
    const int g    = lane >> 2;
    const int tg   = lane & 3;
    const int wm   = wid & 1;
    const int wn   = wid >> 1;
    const int m0   = blockIdx.y * 128;
    const int n0   = blockIdx.x * 128;

    const __nv_bfloat16* gsrc[4] = {
        Agh + (size_t)m0 * KK, Agl + (size_t)m0 * KK,
        Bgh + (size_t)n0 * KK, Bgl + (size_t)n0 * KK };

    const uint32_t aoff = (uint32_t)((wm * 64 + (lane & 15)) * BKP + ((lane & 16) ? 8 : 0));
    const uint32_t boff = (uint32_t)((wn * 32 + (lane & 7) + ((lane & 16) ? 8 : 0)) * BKP
                                     + ((lane & 8) ? 8 : 0));

#define GISSUE(k0, bsel) do { \
    _Pragma("unroll") \
    for (int a = 0; a < 4; a++) { \
        uint32_t sd = sbase + (uint32_t)(((bsel) * 4 + a) * ATILE) * 2; \
        _Pragma("unroll") \
        for (int j = 0; j < 2; j++) { \
            int row = j * 64 + (tid >> 2); int cc = tid & 3; \
            uint32_t s = sd + (uint32_t)(row * BKP + cc * 8) * 2; \
            const __nv_bfloat16* gp = gsrc[a] + (size_t)row * KK + (k0) + cc * 8; \
            asm volatile("cp.async.cg.shared.global [%0], [%1], 16;" :: "r"(s), "l"(gp)); \
        } \
    } \
    asm volatile("cp.async.commit_group;"); \
} while (0)

    float acc[4][4][4];
#pragma unroll
    for (int i = 0; i < 4; i++)
#pragma unroll
        for (int j = 0; j < 4; j++)
#pragma unroll
            for (int r = 0; r < 4; r++) acc[i][j][r] = 0.f;

    GISSUE(0, 0);

    for (int it = 0; it < NIT; it++) {
        const int buf = it & 1;
        asm volatile("cp.async.wait_group 0;");
        __syncthreads();
        if (it + 1 < NIT) GISSUE((it + 1) * GBK, buf ^ 1);

        const uint32_t bb = sbase + (uint32_t)(buf * 4 * ATILE) * 2;
#pragma unroll
        for (int ks = 0; ks < 2; ks++) {
            const uint32_t ko = ks * 32;
            uint32_t bh[4][2], bl[4][2];
            LDSM4(bh[0][0], bh[0][1], bh[1][0], bh[1][1],
                  bb + 2 * ATILE * 2 + boff * 2 + ko);
            LDSM4(bh[2][0], bh[2][1], bh[3][0], bh[3][1],
                  bb + 2 * ATILE * 2 + (boff + 16 * BKP) * 2 + ko);
            LDSM4(bl[0][0], bl[0][1], bl[1][0], bl[1][1],
                  bb + 3 * ATILE * 2 + boff * 2 + ko);
            LDSM4(bl[2][0], bl[2][1], bl[3][0], bl[3][1],
                  bb + 3 * ATILE * 2 + (boff + 16 * BKP) * 2 + ko);
#pragma unroll
            for (int mf = 0; mf < 4; mf++) {
                uint32_t ah0, ah1, ah2, ah3, al0, al1, al2, al3;
                LDSM4(ah0, ah1, ah2, ah3, bb + (aoff + mf * 16 * BKP) * 2 + ko);
                LDSM4(al0, al1, al2, al3, bb + ATILE * 2 + (aoff + mf * 16 * BKP) * 2 + ko);
#pragma unroll
                for (int nf = 0; nf < 4; nf++) {
                    mma_bf16(acc[mf][nf], ah0, ah1, ah2, ah3, bh[nf][0], bh[nf][1]);
                    mma_bf16(acc[mf][nf], ah0, ah1, ah2, ah3, bl[nf][0], bl[nf][1]);
                    mma_bf16(acc[mf][nf], al0, al1, al2, al3, bh[nf][0], bh[nf][1]);
                }
            }
        }
    }
#undef GISSUE

    // epilogue: split-bf16 output
#pragma unroll
    for (int mf = 0; mf < 4; mf++) {
        int r0 = m0 + wm * 64 + mf * 16 + g;
#pragma unroll
        for (int nf = 0; nf < 4; nf++) {
            int col = n0 + wn * 32 + nf * 8 + tg * 2;
            uint32_t h0, l0, h1, l1;
            split2(make_float2(acc[mf][nf][0], acc[mf][nf][1]), h0, l0);
            split2(make_float2(acc[mf][nf][2], acc[mf][nf][3]), h1, l1);
            *(uint32_t*)&Ch[(size_t)r0 * N + col]       = h0;
            *(uint32_t*)&Cl[(size_t)r0 * N + col]       = l0;
            *(uint32_t*)&Ch[(size_t)(r0 + 8) * N + col] = h1;
            *(uint32_t*)&Cl[(size_t)(r0 + 8) * N + col] = l1;
        }
    }
}

// ============================================================================
// Two-digit int8 GEMM: C = (sa.sb) * [A1B1 + (A1B2 + A2B1)/128]
// mma.m16n8k32.s8 (4096 MACs/instr). CTA 128x128, chunk k=64, double buffer.
// Output: fp32(+bias) or split-bf16.
// ============================================================================
#define IKP 80                   // byte row stride (64 data + 16 pad)
#define ITILE (128 * IKP)        // 10240 B per array-tile
#define INITC (KK / 64)          // 16 chunks

__global__ void __launch_bounds__(256)
gemm_s8_kernel(const int8_t* __restrict__ A1, const int8_t* __restrict__ A2,
               const int8_t* __restrict__ B1, const int8_t* __restrict__ B2,
               const float* __restrict__ sa, const float* __restrict__ sb,
               const float* __restrict__ bias,
               float* __restrict__ Cf,
               __nv_bfloat16* __restrict__ Ch, __nv_bfloat16* __restrict__ Cl,
               int M, int N)
{
    extern __shared__ char smc[];
    const uint32_t sbase = smem_u32(smc);

    const int tid  = threadIdx.x;
    const int lane = tid & 31;
    const int wid  = tid >> 5;
    const int g    = lane >> 2;
    const int tg   = lane & 3;
    const int wm   = wid & 1;
    const int wn   = wid >> 1;
    const int m0   = blockIdx.y * 128;
    const int n0   = blockIdx.x * 128;

    const int8_t* gsrc[4] = {
        A1 + (size_t)m0 * KK, A2 + (size_t)m0 * KK,
        B1 + (size_t)n0 * KK, B2 + (size_t)n0 * KK };

    // byte offsets for ldmatrix
    const uint32_t aoff = (uint32_t)((wm * 64 + (lane & 15)) * IKP + ((lane & 16) ? 16 : 0));
    const uint32_t boff = (uint32_t)((wn * 32 + (lane & 7) + ((lane & 16) ? 8 : 0)) * IKP
                                     + ((lane & 8) ? 16 : 0));

#define IISSUE(k0, bsel) do { \
    _Pragma("unroll") \
    for (int a = 0; a < 4; a++) { \
        uint32_t sd = sbase + (uint32_t)(((bsel) * 4 + a) * ITILE); \
        _Pragma("unroll") \
        for (int j = 0; j < 2; j++) { \
            int row = j * 64 + (tid >> 2); int cc = tid & 3; \
            uint32_t s = sd + (uint32_t)(row * IKP + cc * 16); \
            const int8_t* gp = gsrc[a] + (size_t)row * KK + (k0) + cc * 16; \
            asm volatile("cp.async.cg.shared.global [%0], [%1], 16;" :: "r"(s), "l"(gp)); \
        } \
    } \
    asm volatile("cp.async.commit_group;"); \
} while (0)

    int acc1[4][4][4], acc2[4][4][4];
#pragma unroll
    for (int i = 0; i < 4; i++)
#pragma unroll
        for (int j = 0; j < 4; j++)
#pragma unroll
            for (int r = 0; r < 4; r++) { acc1[i][j][r] = 0; acc2[i][j][r] = 0; }

    IISSUE(0, 0);

    for (int it = 0; it < INITC; it++) {
        const int buf = it & 1;
        asm volatile("cp.async.wait_group 0;");
        __syncthreads();
        if (it + 1 < INITC) IISSUE((it + 1) * 64, buf ^ 1);

        const uint32_t bb = sbase + (uint32_t)(buf * 4 * ITILE);
#pragma unroll
        for (int ks = 0; ks < 2; ks++) {
            const uint32_t ko = ks * 32;
            uint32_t b1f[4][2], b2f[4][2];
            LDSM4(b1f[0][0], b1f[0][1], b1f[1][0], b1f[1][1],
                  bb + 2 * ITILE + boff + ko);
            LDSM4(b1f[2][0], b1f[2][1], b1f[3][0], b1f[3][1],
                  bb + 2 * ITILE + boff + 16 * IKP + ko);
            LDSM4(b2f[0][0], b2f[0][1], b2f[1][0], b2f[1][1],
                  bb + 3 * ITILE + boff + ko);
            LDSM4(b2f[2][0], b2f[2][1], b2f[3][0], b2f[3][1],
                  bb + 3 * ITILE + boff + 16 * IKP + ko);
#pragma unroll
            for (int mf = 0; mf < 4; mf++) {
                uint32_t p0, p1, p2, p3, q0, q1, q2, q3;
                LDSM4(p0, p1, p2, p3, bb + aoff + mf * 16 * IKP + ko);
                LDSM4(q0, q1, q2, q3, bb + ITILE + aoff + mf * 16 * IKP + ko);
#pragma unroll
                for (int nf = 0; nf < 4; nf++) {
                    mma_s8(acc1[mf][nf], p0, p1, p2, p3, b1f[nf][0], b1f[nf][1]);
                    mma_s8(acc2[mf][nf], p0, p1, p2, p3, b2f[nf][0], b2f[nf][1]);
                    mma_s8(acc2[mf][nf], q0, q1, q2, q3, b1f[nf][0], b1f[nf][1]);
                }
            }
        }
    }
#undef IISSUE

    // epilogue
#pragma unroll
    for (int mf = 0; mf < 4; mf++) {
        const int r0 = m0 + wm * 64 + mf * 16 + g;
        const float sa0 = sa[r0], sa8 = sa[r0 + 8];
#pragma unroll
        for (int nf = 0; nf < 4; nf++) {
            const int col = n0 + wn * 32 + nf * 8 + tg * 2;
            const float sb0 = sb[col], sb1 = sb[col + 1];
            float v00 = sa0 * sb0 * ((float)acc1[mf][nf][0] + (float)acc2[mf][nf][0] * 0.0078125f);
            float v01 = sa0 * sb1 * ((float)acc1[mf][nf][1] + (float)acc2[mf][nf][1] * 0.0078125f);
            float v10 = sa8 * sb0 * ((float)acc1[mf][nf][2] + (float)acc2[mf][nf][2] * 0.0078125f);
            float v11 = sa8 * sb1 * ((float)acc1[mf][nf][3] + (float)acc2[mf][nf][3] * 0.0078125f);
            if (Cf) {
                float b0 = 0.f, b1 = 0.f;
                if (bias) { b0 = __ldg(&bias[col]); b1 = __ldg(&bias[col + 1]); }
                float2 o0 = { v00 + b0, v01 + b1 };
                float2 o1 = { v10 + b0, v11 + b1 };
                *(float2*)&Cf[(size_t)r0 * N + col]       = o0;
                *(float2*)&Cf[(size_t)(r0 + 8) * N + col] = o1;
            } else {
                uint32_t h0, l0, h1, l1;
                split2(make_float2(v00, v01), h0, l0);
                split2(make_float2(v10, v11), h1, l1);
                *(uint32_t*)&Ch[(size_t)r0 * N + col]       = h0;
                *(uint32_t*)&Cl[(size_t)r0 * N + col]       = l0;
                *(uint32_t*)&Ch[(size_t)(r0 + 8) * N + col] = h1;
                *(uint32_t*)&Cl[(size_t)(r0 + 8) * N + col] = l1;
            }
        }
    }
}

// ============================================================================
// Tensor-core flash attention (split-bf16), compacted keys. fp32 ys output.
// ============================================================================
#define AST 72

__global__ __launch_bounds__(128, 2)
void attn_tc_kernel(const __nv_bfloat16* __restrict__ Qh_,
                    const __nv_bfloat16* __restrict__ Ql_,
                    const __nv_bfloat16* __restrict__ Kh_,
                    const __nv_bfloat16* __restrict__ Kl_,
                    const __nv_bfloat16* __restrict__ Vh_,
                    const __nv_bfloat16* __restrict__ Vl_,
                    const int* __restrict__ idx,
                    const int* __restrict__ nvp,
                    float* __restrict__ ys)
{
    __shared__ __nv_bfloat16 kh[64 * AST], kl[64 * AST];
    __shared__ __nv_bfloat16 vh[64 * AST], vl[64 * AST];

    const int tid  = threadIdx.x;
    const int lane = tid & 31;
    const int w    = tid >> 5;
    const int g    = lane >> 2;
    const int tg   = lane & 3;
    const int b    = blockIdx.z;
    const int h    = blockIdx.y;
    const int q0   = blockIdx.x * 128;

    const int nvb    = nvp[b];
    const int ntiles = (nvb + 63) >> 6;

    const __nv_bfloat16* Qhb = Qh_ + (size_t)(b * TT + q0 + w * 32) * KK + h * SS;
    const __nv_bfloat16* Qlb = Ql_ + (size_t)(b * TT + q0 + w * 32) * KK + h * SS;
    uint32_t qh_[2][4][4], ql_[2][4][4];
#pragma unroll
    for (int m = 0; m < 2; m++) {
#pragma unroll
        for (int ks = 0; ks < 4; ks++) {
            int r0 = m * 16 + g, r1 = r0 + 8;
            int d0 = ks * 16 + 2 * tg;
            qh_[m][ks][0] = *(const uint32_t*)(Qhb + (size_t)r0 * KK + d0);
            qh_[m][ks][1] = *(const uint32_t*)(Qhb + (size_t)r1 * KK + d0);
            qh_[m][ks][2] = *(const uint32_t*)(Qhb + (size_t)r0 * KK + d0 + 8);
            qh_[m][ks][3] = *(const uint32_t*)(Qhb + (size_t)r1 * KK + d0 + 8);
            ql_[m][ks][0] = *(const uint32_t*)(Qlb + (size_t)r0 * KK + d0);
            ql_[m][ks][1] = *(const uint32_t*)(Qlb + (size_t)r1 * KK + d0);
            ql_[m][ks][2] = *(const uint32_t*)(Qlb + (size_t)r0 * KK + d0 + 8);
            ql_[m][ks][3] = *(const uint32_t*)(Qlb + (size_t)r1 * KK + d0 + 8);
        }
    }

    float o[2][8][4];
#pragma unroll
    for (int m = 0; m < 2; m++)
#pragma unroll
        for (int nt = 0; nt < 8; nt++)
#pragma unroll
            for (int c = 0; c < 4; c++) o[m][nt][c] = 0.f;
    float mr[2][2] = { {-1e30f, -1e30f}, {-1e30f, -1e30f} };
    float lr[2][2] = { {0.f, 0.f}, {0.f, 0.f} };

    const int* idxb = idx + b * TT;
    const __nv_bfloat16* Khb = Kh_ + (size_t)b * TT * KK + h * SS;
    const __nv_bfloat16* Klb = Kl_ + (size_t)b * TT * KK + h * SS;
    const __nv_bfloat16* Vhb = Vh_ + (size_t)b * TT * KK + h * SS;
    const __nv_bfloat16* Vlb = Vl_ + (size_t)b * TT * KK + h * SS;

    const int ikey = tid >> 1;
    const int half = tid & 1;

    for (int kt = 0; kt < ntiles; kt++) {
        __syncthreads();
        int slot = kt * 64 + ikey;
        int r = (slot < nvb) ? idxb[slot] : 0;
        {
            const uint4* kph = (const uint4*)(Khb + (size_t)r * KK + half * 32);
            const uint4* kpl = (const uint4*)(Klb + (size_t)r * KK + half * 32);
            int dst = ikey * AST + half * 32;
#pragma unroll
            for (int j = 0; j < 4; j++) {
                *(uint4*)&kh[dst + j * 8] = kph[j];
                *(uint4*)&kl[dst + j * 8] = kpl[j];
            }
        }
        {
            const __nv_bfloat162* vph = (const __nv_bfloat162*)(Vhb + (size_t)r * KK + half * 32);
            const __nv_bfloat162* vpl = (const __nv_bfloat162*)(Vlb + (size_t)r * KK + half * 32);
#pragma unroll
            for (int jj = 0; jj < 16; jj++) {
                int dd = half * 32 + 2 * jj;
                __nv_bfloat162 ph = vph[jj];
                __nv_bfloat162 pl = vpl[jj];
                vh[dd * AST + ikey]       = ph.x;
                vh[(dd + 1) * AST + ikey] = ph.y;
                vl[dd * AST + ikey]       = pl.x;
                vl[(dd + 1) * AST + ikey] = pl.y;
            }
        }
        __syncthreads();

        float s[2][8][4];
#pragma unroll
        for (int m = 0; m < 2; m++)
#pragma unroll
            for (int nt = 0; nt < 8; nt++)
#pragma unroll
                for (int c = 0; c < 4; c++) s[m][nt][c] = 0.f;

#pragma unroll
        for (int ks = 0; ks < 4; ks++) {
            const int kk = ks * 16 + 2 * tg;
#pragma unroll
            for (int nt = 0; nt < 8; nt++) {
                const int rr = (nt * 8 + g) * AST + kk;
                uint32_t bh0 = *(const uint32_t*)&kh[rr];
                uint32_t bh1 = *(const uint32_t*)&kh[rr + 8];
                uint32_t bl0 = *(const uint32_t*)&kl[rr];
                uint32_t bl1 = *(const uint32_t*)&kl[rr + 8];
#pragma unroll
                for (int m = 0; m < 2; m++) {
                    mma_bf16(s[m][nt], qh_[m][ks][0], qh_[m][ks][1], qh_[m][ks][2], qh_[m][ks][3], bh0, bh1);
                    mma_bf16(s[m][nt], qh_[m][ks][0], qh_[m][ks][1], qh_[m][ks][2], qh_[m][ks][3], bl0, bl1);
                    mma_bf16(s[m][nt], ql_[m][ks][0], ql_[m][ks][1], ql_[m][ks][2], ql_[m][ks][3], bh0, bh1);
                }
            }
        }

        if (kt * 64 + 64 > nvb) {
#pragma unroll
            for (int nt = 0; nt < 8; nt++) {
                int c0 = kt * 64 + nt * 8 + 2 * tg;
                if (c0 >= nvb) {
                    s[0][nt][0] = s[0][nt][2] = -1e30f;
                    s[1][nt][0] = s[1][nt][2] = -1e30f;
                }
                if (c0 + 1 >= nvb) {
                    s[0][nt][1] = s[0][nt][3] = -1e30f;
                    s[1][nt][1] = s[1][nt][3] = -1e30f;
                }
            }
        }

#pragma unroll
        for (int m = 0; m < 2; m++) {
#pragma unroll
            for (int r2 = 0; r2 < 2; r2++) {
                const int c0 = r2 * 2;
                float tmax = -1e30f;
#pragma unroll
                for (int nt = 0; nt < 8; nt++) {
                    tmax = fmaxf(tmax, s[m][nt][c0]);
                    tmax = fmaxf(tmax, s[m][nt][c0 + 1]);
                }
                tmax = fmaxf(tmax, __shfl_xor_sync(0xffffffffu, tmax, 1));
                tmax = fmaxf(tmax, __shfl_xor_sync(0xffffffffu, tmax, 2));
                float mn = fmaxf(mr[m][r2], tmax);
                float sc = __expf(mr[m][r2] - mn);
                mr[m][r2] = mn;
                float ts = 0.f;
#pragma unroll
                for (int nt = 0; nt < 8; nt++) {
                    float p0 = __expf(s[m][nt][c0]     - mn);
                    float p1 = __expf(s[m][nt][c0 + 1] - mn);
                    s[m][nt][c0]     = p0;
                    s[m][nt][c0 + 1] = p1;
                    ts += p0 + p1;
                }
                ts += __shfl_xor_sync(0xffffffffu, ts, 1);
                ts += __shfl_xor_sync(0xffffffffu, ts, 2);
                lr[m][r2] = lr[m][r2] * sc + ts;
#pragma unroll
                for (int nt = 0; nt < 8; nt++) {
                    o[m][nt][c0]     *= sc;
                    o[m][nt][c0 + 1] *= sc;
                }
            }
        }

#pragma unroll
        for (int ks = 0; ks < 4; ks++) {
            uint32_t ph[2][4], pl[2][4];
#pragma unroll
            for (int m = 0; m < 2; m++) {
                split2(make_float2(s[m][2*ks][0],   s[m][2*ks][1]),   ph[m][0], pl[m][0]);
                split2(make_float2(s[m][2*ks][2],   s[m][2*ks][3]),   ph[m][1], pl[m][1]);
                split2(make_float2(s[m][2*ks+1][0], s[m][2*ks+1][1]), ph[m][2], pl[m][2]);
                split2(make_float2(s[m][2*ks+1][2], s[m][2*ks+1][3]), ph[m][3], pl[m][3]);
            }
            const int kk = ks * 16 + 2 * tg;
#pragma unroll
            for (int nt = 0; nt < 8; nt++) {
                const int rr = (nt * 8 + g) * AST + kk;
                uint32_t vh0 = *(const uint32_t*)&vh[rr];
                uint32_t vh1 = *(const uint32_t*)&vh[rr + 8];
                uint32_t vl0 = *(const uint32_t*)&vl[rr];
                uint32_t vl1 = *(const uint32_t*)&vl[rr + 8];
#pragma unroll
                for (int m = 0; m < 2; m++) {
                    mma_bf16(o[m][nt], ph[m][0], ph[m][1], ph[m][2], ph[m][3], vh0, vh1);
                    mma_bf16(o[m][nt], ph[m][0], ph[m][1], ph[m][2], ph[m][3], vl0, vl1);
                    mma_bf16(o[m][nt], pl[m][0], pl[m][1], pl[m][2], pl[m][3], vh0, vh1);
                }
            }
        }
    }

#pragma unroll
    for (int m = 0; m < 2; m++) {
#pragma unroll
        for (int r2 = 0; r2 < 2; r2++) {
            float inv = 1.f / lr[m][r2];
            int row = q0 + w * 32 + m * 16 + g + r2 * 8;
            float* op = ys + (size_t)(b * TT + row) * KK + h * SS;
#pragma unroll
            for (int nt = 0; nt < 8; nt++) {
                float2 ov = { o[m][nt][r2*2] * inv, o[m][nt][r2*2 + 1] * inv };
                *(float2*)(op + nt * 8 + 2 * tg) = ov;
            }
        }
    }
}

// ============================================================================
// launch
// ============================================================================
extern "C" void kernel_launch(void* const* d_in, const int* in_sizes, int n_in,
                              void* d_out, int out_size)
{
    const float* x    = (const float*)d_in[0];
    const int*   mask = (const int*)  d_in[1];
    const float* Wk   = (const float*)d_in[2];
    const float* Wq   = (const float*)d_in[3];
    const float* Wv   = (const float*)d_in[4];
    const float* Wu   = (const float*)d_in[5];
    const float* bu   = (const float*)d_in[6];
    float* out = (float*)d_out;

    __nv_bfloat16 *xh, *xl, *Wqh, *Wql, *Wkh, *Wkl;
    __nv_bfloat16 *Qh, *Ql, *Kh, *Kl, *Vh, *Vl;
    float *ys, *sx, *swv, *swu, *sy;
    int8_t *x1, *x2, *Wv1, *Wv2, *Wu1, *Wu2, *y1, *y2;
    int *idx, *nv;
    cudaGetSymbolAddress((void**)&xh,  g_xh);  cudaGetSymbolAddress((void**)&xl,  g_xl);
    cudaGetSymbolAddress((void**)&Wqh, g_Wqh); cudaGetSymbolAddress((void**)&Wql, g_Wql);
    cudaGetSymbolAddress((void**)&Wkh, g_Wkh); cudaGetSymbolAddress((void**)&Wkl, g_Wkl);
    cudaGetSymbolAddress((void**)&Qh,  g_Qh);  cudaGetSymbolAddress((void**)&Ql,  g_Ql);
    cudaGetSymbolAddress((void**)&Kh,  g_Kh);  cudaGetSymbolAddress((void**)&Kl,  g_Kl);
    cudaGetSymbolAddress((void**)&Vh,  g_Vh);  cudaGetSymbolAddress((void**)&Vl,  g_Vl);
    cudaGetSymbolAddress((void**)&ys,  g_ys);
    cudaGetSymbolAddress((void**)&x1,  g_x1);  cudaGetSymbolAddress((void**)&x2,  g_x2);
    cudaGetSymbolAddress((void**)&Wv1, g_Wv1); cudaGetSymbolAddress((void**)&Wv2, g_Wv2);
    cudaGetSymbolAddress((void**)&Wu1, g_Wu1); cudaGetSymbolAddress((void**)&Wu2, g_Wu2);
    cudaGetSymbolAddress((void**)&y1,  g_y1);  cudaGetSymbolAddress((void**)&y2,  g_y2);
    cudaGetSymbolAddress((void**)&sx,  g_sx);  cudaGetSymbolAddress((void**)&swv, g_swv);
    cudaGetSymbolAddress((void**)&swu, g_swu); cudaGetSymbolAddress((void**)&sy,  g_sy);
    cudaGetSymbolAddress((void**)&idx, g_idx); cudaGetSymbolAddress((void**)&nv,  g_nv);

    cudaFuncSetAttribute(gemm_bf16_kernel,
                         cudaFuncAttributeMaxDynamicSharedMemorySize, GEMM_SMEM);
    cudaFuncSetAttribute(gemm_s8_kernel,
                         cudaFuncAttributeMaxDynamicSharedMemorySize, GEMM_SMEM);

    // preprocessing
    split_kernel<<<512, 256>>>(x,  xh,  xl,  MROWS * KK / 2);
    split_kernel<<<256, 256>>>(Wq, Wqh, Wql, KK * KK / 2);
    split_kernel<<<256, 256>>>(Wk, Wkh, Wkl, KK * KK / 2);
    quant_kernel<<<MROWS / 8, 256>>>(x,  x1,  x2,  sx,  MROWS);
    quant_kernel<<<KK / 8,    256>>>(Wv, Wv1, Wv2, swv, KK);
    quant_kernel<<<KK / 8,    256>>>(Wu, Wu1, Wu2, swu, KK);
    compact_kernel<<<BB, 1024>>>(mask, idx, nv);

    dim3 gg(KK / 128, MROWS / 128);   // (8, 32)
    gemm_bf16_kernel<<<gg, 256, GEMM_SMEM>>>(xh, xl, Wqh, Wql, Qh, Ql, MROWS, KK);
    gemm_bf16_kernel<<<gg, 256, GEMM_SMEM>>>(xh, xl, Wkh, Wkl, Kh, Kl, MROWS, KK);
    gemm_s8_kernel<<<gg, 256, GEMM_SMEM>>>(x1, x2, Wv1, Wv2, sx, swv, nullptr,
                                           nullptr, Vh, Vl, MROWS, KK);

    dim3 ga(TT / 128, HH, BB);        // (16, 16, 2)
    attn_tc_kernel<<<ga, 128>>>(Qh, Ql, Kh, Kl, Vh, Vl, idx, nv, ys);

    quant_kernel<<<MROWS / 8, 256>>>(ys, y1, y2, sy, MROWS);
    gemm_s8_kernel<<<gg, 256, GEMM_SMEM>>>(y1, y2, Wu1, Wu2, sy, swu, bu,
                                           out, nullptr, nullptr, MROWS, KK);
}

// round 8
// speedup vs baseline: 1.3410x; 1.3410x over previous
#include <cuda_runtime.h>
#include <cuda_bf16.h>
#include <cuda_fp16.h>
#include <cstdint>

#define BB   2
#define TT   2048
#define KK   1024
#define HH   16
#define SS   64
#define MROWS (BB*TT)   // 4096

// ---- scratch (static device globals; no allocation allowed) ----
__device__ __half g_xh[MROWS*KK], g_xl[MROWS*KK];
__device__ __half g_Wqh[KK*KK],  g_Wql[KK*KK];
__device__ __half g_Wkh[KK*KK],  g_Wkl[KK*KK];
__device__ __half g_Wvh[KK*KK],  g_Wvl[KK*KK];
__device__ __half g_Wuh[KK*KK],  g_Wul[KK*KK];
__device__ __nv_bfloat16 g_Qh[MROWS*KK], g_Ql[MROWS*KK];
__device__ __nv_bfloat16 g_Kh[MROWS*KK], g_Kl[MROWS*KK];
__device__ __nv_bfloat16 g_Vh[MROWS*KK], g_Vl[MROWS*KK];
__device__ __half g_ysh[MROWS*KK], g_ysl[MROWS*KK];
__device__ int g_idx[BB*TT];
__device__ int g_nv [BB];

#define INV2048 4.8828125e-4f

// ============================================================================
// helpers
// ============================================================================
__device__ __forceinline__ uint32_t smem_u32(const void* p) {
    uint32_t a;
    asm("{ .reg .u64 t; cvta.to.shared.u64 t, %1; cvt.u32.u64 %0, t; }"
        : "=r"(a) : "l"(p));
    return a;
}

// bf16 mma, fp32 accum (attention path, proven)
__device__ __forceinline__ void mma_bf16(float d[4],
                                         uint32_t a0, uint32_t a1, uint32_t a2, uint32_t a3,
                                         uint32_t b0, uint32_t b1) {
    asm volatile(
        "mma.sync.aligned.m16n8k16.row.col.f32.bf16.bf16.f32 "
        "{%0,%1,%2,%3}, {%4,%5,%6,%7}, {%8,%9}, {%0,%1,%2,%3};"
        : "+f"(d[0]), "+f"(d[1]), "+f"(d[2]), "+f"(d[3])
        : "r"(a0), "r"(a1), "r"(a2), "r"(a3), "r"(b0), "r"(b1));
}

// fp16 mma, fp32 accum (GEMM main term)
__device__ __forceinline__ void mma_f16f32(float d[4],
                                           uint32_t a0, uint32_t a1, uint32_t a2, uint32_t a3,
                                           uint32_t b0, uint32_t b1) {
    asm volatile(
        "mma.sync.aligned.m16n8k16.row.col.f32.f16.f16.f32 "
        "{%0,%1,%2,%3}, {%4,%5,%6,%7}, {%8,%9}, {%0,%1,%2,%3};"
        : "+f"(d[0]), "+f"(d[1]), "+f"(d[2]), "+f"(d[3])
        : "r"(a0), "r"(a1), "r"(a2), "r"(a3), "r"(b0), "r"(b1));
}

// fp16 mma, fp16 accum (GEMM correction terms — the 2x-rate experiment)
__device__ __forceinline__ void mma_f16f16(uint32_t d[2],
                                           uint32_t a0, uint32_t a1, uint32_t a2, uint32_t a3,
                                           uint32_t b0, uint32_t b1) {
    asm volatile(
        "mma.sync.aligned.m16n8k16.row.col.f16.f16.f16.f16 "
        "{%0,%1}, {%2,%3,%4,%5}, {%6,%7}, {%0,%1};"
        : "+r"(d[0]), "+r"(d[1])
        : "r"(a0), "r"(a1), "r"(a2), "r"(a3), "r"(b0), "r"(b1));
}

#define LDSM4(r0, r1, r2, r3, addr) \
    asm volatile("ldmatrix.sync.aligned.m8n8.x4.shared.b16 {%0,%1,%2,%3}, [%4];" \
                 : "=r"(r0), "=r"(r1), "=r"(r2), "=r"(r3) : "r"(addr))

__device__ __forceinline__ void split2(float2 f, uint32_t& h, uint32_t& l) {
    __nv_bfloat162 hh = __float22bfloat162_rn(f);
    float2 hf = __bfloat1622float2(hh);
    __nv_bfloat162 ll = __float22bfloat162_rn(make_float2(f.x - hf.x, f.y - hf.y));
    h = *(uint32_t*)&hh;
    l = *(uint32_t*)&ll;
}

// fp16 split with scaled lo digit: x = h + (l/2048)
__device__ __forceinline__ void split2h(float2 f, uint32_t& h, uint32_t& l) {
    __half h0 = __float2half_rn(f.x);
    __half h1 = __float2half_rn(f.y);
    __half l0 = __float2half_rn((f.x - __half2float(h0)) * 2048.f);
    __half l1 = __float2half_rn((f.y - __half2float(h1)) * 2048.f);
    __half2 hh = __halves2half2(h0, h1);
    __half2 ll = __halves2half2(l0, l1);
    h = *(uint32_t*)&hh;
    l = *(uint32_t*)&ll;
}

// ============================================================================
// preprocessing: fp32 -> fp16 (hi, scaled lo)
// ============================================================================
__global__ __launch_bounds__(256)
void splith_kernel(const float* __restrict__ in,
                   __half* __restrict__ hi,
                   __half* __restrict__ lo, int n2)
{
    for (int i = blockIdx.x * blockDim.x + threadIdx.x; i < n2;
         i += gridDim.x * blockDim.x) {
        float2 f = ((const float2*)in)[i];
        uint32_t h, l;
        split2h(f, h, l);
        ((uint32_t*)hi)[i] = h;
        ((uint32_t*)lo)[i] = l;
    }
}

// ============================================================================
// mask compaction (unchanged, proven)
// ============================================================================
__global__ __launch_bounds__(1024)
void compact_kernel(const int* __restrict__ mask, int* __restrict__ idx,
                    int* __restrict__ nv)
{
    __shared__ int s[1024];
    const int b = blockIdx.x;
    const int t = threadIdx.x;
    const int m0 = mask[b * TT + 2 * t];
    const int m1 = mask[b * TT + 2 * t + 1];
    const int c  = m0 + m1;
    s[t] = c;
    __syncthreads();
    for (int off = 1; off < 1024; off <<= 1) {
        int v = s[t];
        int u = (t >= off) ? s[t - off] : 0;
        __syncthreads();
        s[t] = v + u;
        __syncthreads();
    }
    const int incl = s[t];
    const int excl = incl - c;
    if (m0) idx[b * TT + excl] = 2 * t;
    if (m1) idx[b * TT + excl + m0] = 2 * t + 1;
    if (t == 1023) nv[b] = incl;
}

// ============================================================================
// fp16 two-digit GEMM: C = f32acc(AhBh) + f16acc(AhBl' + Al'Bh)/2048
// CTA 128x128, GBK=32 double-buffered cp.async, ldmatrix, 8 warps (2m x 4n).
// Output: fp32(+bias) or split-bf16 (for attention).
// ============================================================================
#define GBK 32
#define NIT (KK / GBK)          // 32
#define BKP 40                  // fp16 row stride (80 B)
#define ATILE (128 * BKP)
#define GEMM_SMEM (8 * ATILE * 2)   // 81920 B

__global__ void __launch_bounds__(256)
gemm_f16_kernel(const __half* __restrict__ Agh,
                const __half* __restrict__ Agl,
                const __half* __restrict__ Bgh,
                const __half* __restrict__ Bgl,
                const float* __restrict__ bias,
                float* __restrict__ Cf,
                __nv_bfloat16* __restrict__ Ch,
                __nv_bfloat16* __restrict__ Cl,
                int M, int N)
{
    extern __shared__ __half sm[];
    const uint32_t sbase = smem_u32(sm);

    const int tid  = threadIdx.x;
    const int lane = tid & 31;
    const int wid  = tid >> 5;
    const int g    = lane >> 2;
    const int tg   = lane & 3;
    const int wm   = wid & 1;
    const int wn   = wid >> 1;
    const int m0   = blockIdx.y * 128;
    const int n0   = blockIdx.x * 128;

    const __half* gsrc[4] = {
        Agh + (size_t)m0 * KK, Agl + (size_t)m0 * KK,
        Bgh + (size_t)n0 * KK, Bgl + (size_t)n0 * KK };

    const uint32_t aoff = (uint32_t)((wm * 64 + (lane & 15)) * BKP + ((lane & 16) ? 8 : 0));
    const uint32_t boff = (uint32_t)((wn * 32 + (lane & 7) + ((lane & 16) ? 8 : 0)) * BKP
                                     + ((lane & 8) ? 8 : 0));

#define GISSUE(k0, bsel) do { \
    _Pragma("unroll") \
    for (int a = 0; a < 4; a++) { \
        uint32_t sd = sbase + (uint32_t)(((bsel) * 4 + a) * ATILE) * 2; \
        _Pragma("unroll") \
        for (int j = 0; j < 2; j++) { \
            int row = j * 64 + (tid >> 2); int cc = tid & 3; \
            uint32_t s = sd + (uint32_t)(row * BKP + cc * 8) * 2; \
            const __half* gp = gsrc[a] + (size_t)row * KK + (k0) + cc * 8; \
            asm volatile("cp.async.cg.shared.global [%0], [%1], 16;" :: "r"(s), "l"(gp)); \
        } \
    } \
    asm volatile("cp.async.commit_group;"); \
} while (0)

    float accF[4][4][4];
    uint32_t cacc[4][4][2];
#pragma unroll
    for (int i = 0; i < 4; i++)
#pragma unroll
        for (int j = 0; j < 4; j++) {
#pragma unroll
            for (int r = 0; r < 4; r++) accF[i][j][r] = 0.f;
            cacc[i][j][0] = 0u; cacc[i][j][1] = 0u;
        }

    GISSUE(0, 0);

    for (int it = 0; it < NIT; it++) {
        const int buf = it & 1;
        asm volatile("cp.async.wait_group 0;");
        __syncthreads();
        if (it + 1 < NIT) GISSUE((it + 1) * GBK, buf ^ 1);

        const uint32_t bb = sbase + (uint32_t)(buf * 4 * ATILE) * 2;
#pragma unroll
        for (int ks = 0; ks < 2; ks++) {
            const uint32_t ko = ks * 32;
            uint32_t bh[4][2], bl[4][2];
            LDSM4(bh[0][0], bh[0][1], bh[1][0], bh[1][1],
                  bb + 2 * ATILE * 2 + boff * 2 + ko);
            LDSM4(bh[2][0], bh[2][1], bh[3][0], bh[3][1],
                  bb + 2 * ATILE * 2 + (boff + 16 * BKP) * 2 + ko);
            LDSM4(bl[0][0], bl[0][1], bl[1][0], bl[1][1],
                  bb + 3 * ATILE * 2 + boff * 2 + ko);
            LDSM4(bl[2][0], bl[2][1], bl[3][0], bl[3][1],
                  bb + 3 * ATILE * 2 + (boff + 16 * BKP) * 2 + ko);
#pragma unroll
            for (int mf = 0; mf < 4; mf++) {
                uint32_t ah0, ah1, ah2, ah3, al0, al1, al2, al3;
                LDSM4(ah0, ah1, ah2, ah3, bb + (aoff + mf * 16 * BKP) * 2 + ko);
                LDSM4(al0, al1, al2, al3, bb + ATILE * 2 + (aoff + mf * 16 * BKP) * 2 + ko);
#pragma unroll
                for (int nf = 0; nf < 4; nf++) {
                    mma_f16f32(accF[mf][nf], ah0, ah1, ah2, ah3, bh[nf][0], bh[nf][1]);
                    mma_f16f16(cacc[mf][nf], ah0, ah1, ah2, ah3, bl[nf][0], bl[nf][1]);
                    mma_f16f16(cacc[mf][nf], al0, al1, al2, al3, bh[nf][0], bh[nf][1]);
                }
            }
        }
    }
#undef GISSUE

    // ---- epilogue: combine main + correction/2048 ----
#pragma unroll
    for (int mf = 0; mf < 4; mf++) {
        int r0 = m0 + wm * 64 + mf * 16 + g;
#pragma unroll
        for (int nf = 0; nf < 4; nf++) {
            int col = n0 + wn * 32 + nf * 8 + tg * 2;
            __half2 c0 = *(__half2*)&cacc[mf][nf][0];
            __half2 c1 = *(__half2*)&cacc[mf][nf][1];
            float v00 = accF[mf][nf][0] + __low2float(c0)  * INV2048;
            float v01 = accF[mf][nf][1] + __high2float(c0) * INV2048;
            float v10 = accF[mf][nf][2] + __low2float(c1)  * INV2048;
            float v11 = accF[mf][nf][3] + __high2float(c1) * INV2048;
            if (Cf) {
                float b0 = 0.f, b1 = 0.f;
                if (bias) { b0 = __ldg(&bias[col]); b1 = __ldg(&bias[col + 1]); }
                float2 o0 = { v00 + b0, v01 + b1 };
                float2 o1 = { v10 + b0, v11 + b1 };
                *(float2*)&Cf[(size_t)r0 * N + col]       = o0;
                *(float2*)&Cf[(size_t)(r0 + 8) * N + col] = o1;
            } else {
                uint32_t h0, l0, h1, l1;
                split2(make_float2(v00, v01), h0, l0);
                split2(make_float2(v10, v11), h1, l1);
                *(uint32_t*)&Ch[(size_t)r0 * N + col]       = h0;
                *(uint32_t*)&Cl[(size_t)r0 * N + col]       = l0;
                *(uint32_t*)&Ch[(size_t)(r0 + 8) * N + col] = h1;
                *(uint32_t*)&Cl[(size_t)(r0 + 8) * N + col] = l1;
            }
        }
    }
}

// ============================================================================
// Tensor-core flash attention (split-bf16, proven round-6 body).
// Epilogue now emits fp16 (hi, scaled lo) for the fp16 U-GEMM.
// ============================================================================
#define AST 72

__global__ __launch_bounds__(128, 2)
void attn_tc_kernel(const __nv_bfloat16* __restrict__ Qh_,
                    const __nv_bfloat16* __restrict__ Ql_,
                    const __nv_bfloat16* __restrict__ Kh_,
                    const __nv_bfloat16* __restrict__ Kl_,
                    const __nv_bfloat16* __restrict__ Vh_,
                    const __nv_bfloat16* __restrict__ Vl_,
                    const int* __restrict__ idx,
                    const int* __restrict__ nvp,
                    __half* __restrict__ ysh,
                    __half* __restrict__ ysl)
{
    __shared__ __nv_bfloat16 kh[64 * AST], kl[64 * AST];
    __shared__ __nv_bfloat16 vh[64 * AST], vl[64 * AST];

    const int tid  = threadIdx.x;
    const int lane = tid & 31;
    const int w    = tid >> 5;
    const int g    = lane >> 2;
    const int tg   = lane & 3;
    const int b    = blockIdx.z;
    const int h    = blockIdx.y;
    const int q0   = blockIdx.x * 128;

    const int nvb    = nvp[b];
    const int ntiles = (nvb + 63) >> 6;

    const __nv_bfloat16* Qhb = Qh_ + (size_t)(b * TT + q0 + w * 32) * KK + h * SS;
    const __nv_bfloat16* Qlb = Ql_ + (size_t)(b * TT + q0 + w * 32) * KK + h * SS;
    uint32_t qh_[2][4][4], ql_[2][4][4];
#pragma unroll
    for (int m = 0; m < 2; m++) {
#pragma unroll
        for (int ks = 0; ks < 4; ks++) {
            int r0 = m * 16 + g, r1 = r0 + 8;
            int d0 = ks * 16 + 2 * tg;
            qh_[m][ks][0] = *(const uint32_t*)(Qhb + (size_t)r0 * KK + d0);
            qh_[m][ks][1] = *(const uint32_t*)(Qhb + (size_t)r1 * KK + d0);
            qh_[m][ks][2] = *(const uint32_t*)(Qhb + (size_t)r0 * KK + d0 + 8);
            qh_[m][ks][3] = *(const uint32_t*)(Qhb + (size_t)r1 * KK + d0 + 8);
            ql_[m][ks][0] = *(const uint32_t*)(Qlb + (size_t)r0 * KK + d0);
            ql_[m][ks][1] = *(const uint32_t*)(Qlb + (size_t)r1 * KK + d0);
            ql_[m][ks][2] = *(const uint32_t*)(Qlb + (size_t)r0 * KK + d0 + 8);
            ql_[m][ks][3] = *(const uint32_t*)(Qlb + (size_t)r1 * KK + d0 + 8);
        }
    }

    float o[2][8][4];
#pragma unroll
    for (int m = 0; m < 2; m++)
#pragma unroll
        for (int nt = 0; nt < 8; nt++)
#pragma unroll
            for (int c = 0; c < 4; c++) o[m][nt][c] = 0.f;
    float mr[2][2] = { {-1e30f, -1e30f}, {-1e30f, -1e30f} };
    float lr[2][2] = { {0.f, 0.f}, {0.f, 0.f} };

    const int* idxb = idx + b * TT;
    const __nv_bfloat16* Khb = Kh_ + (size_t)b * TT * KK + h * SS;
    const __nv_bfloat16* Klb = Kl_ + (size_t)b * TT * KK + h * SS;
    const __nv_bfloat16* Vhb = Vh_ + (size_t)b * TT * KK + h * SS;
    const __nv_bfloat16* Vlb = Vl_ + (size_t)b * TT * KK + h * SS;

    const int ikey = tid >> 1;
    const int half = tid & 1;

    for (int kt = 0; kt < ntiles; kt++) {
        __syncthreads();
        int slot = kt * 64 + ikey;
        int r = (slot < nvb) ? idxb[slot] : 0;
        {
            const uint4* kph = (const uint4*)(Khb + (size_t)r * KK + half * 32);
            const uint4* kpl = (const uint4*)(Klb + (size_t)r * KK + half * 32);
            int dst = ikey * AST + half * 32;
#pragma unroll
            for (int j = 0; j < 4; j++) {
                *(uint4*)&kh[dst + j * 8] = kph[j];
                *(uint4*)&kl[dst + j * 8] = kpl[j];
            }
        }
        {
            const __nv_bfloat162* vph = (const __nv_bfloat162*)(Vhb + (size_t)r * KK + half * 32);
            const __nv_bfloat162* vpl = (const __nv_bfloat162*)(Vlb + (size_t)r * KK + half * 32);
#pragma unroll
            for (int jj = 0; jj < 16; jj++) {
                int dd = half * 32 + 2 * jj;
                __nv_bfloat162 ph = vph[jj];
                __nv_bfloat162 pl = vpl[jj];
                vh[dd * AST + ikey]       = ph.x;
                vh[(dd + 1) * AST + ikey] = ph.y;
                vl[dd * AST + ikey]       = pl.x;
                vl[(dd + 1) * AST + ikey] = pl.y;
            }
        }
        __syncthreads();

        float s[2][8][4];
#pragma unroll
        for (int m = 0; m < 2; m++)
#pragma unroll
            for (int nt = 0; nt < 8; nt++)
#pragma unroll
                for (int c = 0; c < 4; c++) s[m][nt][c] = 0.f;

#pragma unroll
        for (int ks = 0; ks < 4; ks++) {
            const int kk = ks * 16 + 2 * tg;
#pragma unroll
            for (int nt = 0; nt < 8; nt++) {
                const int rr = (nt * 8 + g) * AST + kk;
                uint32_t bh0 = *(const uint32_t*)&kh[rr];
                uint32_t bh1 = *(const uint32_t*)&kh[rr + 8];
                uint32_t bl0 = *(const uint32_t*)&kl[rr];
                uint32_t bl1 = *(const uint32_t*)&kl[rr + 8];
#pragma unroll
                for (int m = 0; m < 2; m++) {
                    mma_bf16(s[m][nt], qh_[m][ks][0], qh_[m][ks][1], qh_[m][ks][2], qh_[m][ks][3], bh0, bh1);
                    mma_bf16(s[m][nt], qh_[m][ks][0], qh_[m][ks][1], qh_[m][ks][2], qh_[m][ks][3], bl0, bl1);
                    mma_bf16(s[m][nt], ql_[m][ks][0], ql_[m][ks][1], ql_[m][ks][2], ql_[m][ks][3], bh0, bh1);
                }
            }
        }

        if (kt * 64 + 64 > nvb) {
#pragma unroll
            for (int nt = 0; nt < 8; nt++) {
                int c0 = kt * 64 + nt * 8 + 2 * tg;
                if (c0 >= nvb) {
                    s[0][nt][0] = s[0][nt][2] = -1e30f;
                    s[1][nt][0] = s[1][nt][2] = -1e30f;
                }
                if (c0 + 1 >= nvb) {
                    s[0][nt][1] = s[0][nt][3] = -1e30f;
                    s[1][nt][1] = s[1][nt][3] = -1e30f;
                }
            }
        }

#pragma unroll
        for (int m = 0; m < 2; m++) {
#pragma unroll
            for (int r2 = 0; r2 < 2; r2++) {
                const int c0 = r2 * 2;
                float tmax = -1e30f;
#pragma unroll
                for (int nt = 0; nt < 8; nt++) {
                    tmax = fmaxf(tmax, s[m][nt][c0]);
                    tmax = fmaxf(tmax, s[m][nt][c0 + 1]);
                }
                tmax = fmaxf(tmax, __shfl_xor_sync(0xffffffffu, tmax, 1));
                tmax = fmaxf(tmax, __shfl_xor_sync(0xffffffffu, tmax, 2));
                float mn = fmaxf(mr[m][r2], tmax);
                float sc = __expf(mr[m][r2] - mn);
                mr[m][r2] = mn;
                float ts = 0.f;
#pragma unroll
                for (int nt = 0; nt < 8; nt++) {
                    float p0 = __expf(s[m][nt][c0]     - mn);
                    float p1 = __expf(s[m][nt][c0 + 1] - mn);
                    s[m][nt][c0]     = p0;
                    s[m][nt][c0 + 1] = p1;
                    ts += p0 + p1;
                }
                ts += __shfl_xor_sync(0xffffffffu, ts, 1);
                ts += __shfl_xor_sync(0xffffffffu, ts, 2);
                lr[m][r2] = lr[m][r2] * sc + ts;
#pragma unroll
                for (int nt = 0; nt < 8; nt++) {
                    o[m][nt][c0]     *= sc;
                    o[m][nt][c0 + 1] *= sc;
                }
            }
        }

#pragma unroll
        for (int ks = 0; ks < 4; ks++) {
            uint32_t ph[2][4], pl[2][4];
#pragma unroll
            for (int m = 0; m < 2; m++) {
                split2(make_float2(s[m][2*ks][0],   s[m][2*ks][1]),   ph[m][0], pl[m][0]);
                split2(make_float2(s[m][2*ks][2],   s[m][2*ks][3]),   ph[m][1], pl[m][1]);
                split2(make_float2(s[m][2*ks+1][0], s[m][2*ks+1][1]), ph[m][2], pl[m][2]);
                split2(make_float2(s[m][2*ks+1][2], s[m][2*ks+1][3]), ph[m][3], pl[m][3]);
            }
            const int kk = ks * 16 + 2 * tg;
#pragma unroll
            for (int nt = 0; nt < 8; nt++) {
                const int rr = (nt * 8 + g) * AST + kk;
                uint32_t vh0 = *(const uint32_t*)&vh[rr];
                uint32_t vh1 = *(const uint32_t*)&vh[rr + 8];
                uint32_t vl0 = *(const uint32_t*)&vl[rr];
                uint32_t vl1 = *(const uint32_t*)&vl[rr + 8];
#pragma unroll
                for (int m = 0; m < 2; m++) {
                    mma_bf16(o[m][nt], ph[m][0], ph[m][1], ph[m][2], ph[m][3], vh0, vh1);
                    mma_bf16(o[m][nt], ph[m][0], ph[m][1], ph[m][2], ph[m][3], vl0, vl1);
                    mma_bf16(o[m][nt], pl[m][0], pl[m][1], pl[m][2], pl[m][3], vh0, vh1);
                }
            }
        }
    }

    // ---- epilogue: normalize, emit fp16 (hi, scaled lo) ----
#pragma unroll
    for (int m = 0; m < 2; m++) {
#pragma unroll
        for (int r2 = 0; r2 < 2; r2++) {
            float inv = 1.f / lr[m][r2];
            int row = q0 + w * 32 + m * 16 + g + r2 * 8;
            size_t off = (size_t)(b * TT + row) * KK + h * SS;
#pragma unroll
            for (int nt = 0; nt < 8; nt++) {
                uint32_t hh, ll;
                split2h(make_float2(o[m][nt][r2*2] * inv, o[m][nt][r2*2+1] * inv), hh, ll);
                *(uint32_t*)&ysh[off + nt * 8 + 2 * tg] = hh;
                *(uint32_t*)&ysl[off + nt * 8 + 2 * tg] = ll;
            }
        }
    }
}

// ============================================================================
// launch
// ============================================================================
extern "C" void kernel_launch(void* const* d_in, const int* in_sizes, int n_in,
                              void* d_out, int out_size)
{
    const float* x    = (const float*)d_in[0];
    const int*   mask = (const int*)  d_in[1];
    const float* Wk   = (const float*)d_in[2];
    const float* Wq   = (const float*)d_in[3];
    const float* Wv   = (const float*)d_in[4];
    const float* Wu   = (const float*)d_in[5];
    const float* bu   = (const float*)d_in[6];
    float* out = (float*)d_out;

    __half *xh, *xl, *Wqh, *Wql, *Wkh, *Wkl, *Wvh, *Wvl, *Wuh, *Wul, *ysh, *ysl;
    __nv_bfloat16 *Qh, *Ql, *Kh, *Kl, *Vh, *Vl;
    int *idx, *nv;
    cudaGetSymbolAddress((void**)&xh,  g_xh);  cudaGetSymbolAddress((void**)&xl,  g_xl);
    cudaGetSymbolAddress((void**)&Wqh, g_Wqh); cudaGetSymbolAddress((void**)&Wql, g_Wql);
    cudaGetSymbolAddress((void**)&Wkh, g_Wkh); cudaGetSymbolAddress((void**)&Wkl, g_Wkl);
    cudaGetSymbolAddress((void**)&Wvh, g_Wvh); cudaGetSymbolAddress((void**)&Wvl, g_Wvl);
    cudaGetSymbolAddress((void**)&Wuh, g_Wuh); cudaGetSymbolAddress((void**)&Wul, g_Wul);
    cudaGetSymbolAddress((void**)&Qh,  g_Qh);  cudaGetSymbolAddress((void**)&Ql,  g_Ql);
    cudaGetSymbolAddress((void**)&Kh,  g_Kh);  cudaGetSymbolAddress((void**)&Kl,  g_Kl);
    cudaGetSymbolAddress((void**)&Vh,  g_Vh);  cudaGetSymbolAddress((void**)&Vl,  g_Vl);
    cudaGetSymbolAddress((void**)&ysh, g_ysh); cudaGetSymbolAddress((void**)&ysl, g_ysl);
    cudaGetSymbolAddress((void**)&idx, g_idx); cudaGetSymbolAddress((void**)&nv,  g_nv);

    cudaFuncSetAttribute(gemm_f16_kernel,
                         cudaFuncAttributeMaxDynamicSharedMemorySize, GEMM_SMEM);

    // preprocessing
    splith_kernel<<<512, 256>>>(x,  xh,  xl,  MROWS * KK / 2);
    splith_kernel<<<256, 256>>>(Wq, Wqh, Wql, KK * KK / 2);
    splith_kernel<<<256, 256>>>(Wk, Wkh, Wkl, KK * KK / 2);
    splith_kernel<<<256, 256>>>(Wv, Wvh, Wvl, KK * KK / 2);
    splith_kernel<<<256, 256>>>(Wu, Wuh, Wul, KK * KK / 2);
    compact_kernel<<<BB, 1024>>>(mask, idx, nv);

    dim3 gg(KK / 128, MROWS / 128);   // (8, 32)
    gemm_f16_kernel<<<gg, 256, GEMM_SMEM>>>(xh, xl, Wqh, Wql, nullptr,
                                            nullptr, Qh, Ql, MROWS, KK);
    gemm_f16_kernel<<<gg, 256, GEMM_SMEM>>>(xh, xl, Wkh, Wkl, nullptr,
                                            nullptr, Kh, Kl, MROWS, KK);
    gemm_f16_kernel<<<gg, 256, GEMM_SMEM>>>(xh, xl, Wvh, Wvl, nullptr,
                                            nullptr, Vh, Vl, MROWS, KK);

    dim3 ga(TT / 128, HH, BB);        // (16, 16, 2)
    attn_tc_kernel<<<ga, 128>>>(Qh, Ql, Kh, Kl, Vh, Vl, idx, nv, ysh, ysl);

    gemm_f16_kernel<<<gg, 256, GEMM_SMEM>>>(ysh, ysl, Wuh, Wul, bu,
                                            out, nullptr, nullptr, MROWS, KK);
}

// round 9
// speedup vs baseline: 1.9878x; 1.4823x over previous
#include <cuda_runtime.h>
#include <cuda_bf16.h>
#include <cuda_fp16.h>
#include <cstdint>

#define BB   2
#define TT   2048
#define KK   1024
#define HH   16
#define SS   64
#define MROWS (BB*TT)   // 4096

// ---- scratch (static device globals; no allocation allowed) ----
__device__ __nv_bfloat16 g_xh[MROWS*KK], g_xl[MROWS*KK];
__device__ __nv_bfloat16 g_Wqh[KK*KK],  g_Wql[KK*KK];
__device__ __nv_bfloat16 g_Wkh[KK*KK],  g_Wkl[KK*KK];
__device__ __nv_bfloat16 g_Qh[MROWS*KK], g_Ql[MROWS*KK];
__device__ __nv_bfloat16 g_Kh[MROWS*KK], g_Kl[MROWS*KK];
__device__ __half g_xf [MROWS*KK];
__device__ __half g_Wvf[KK*KK];
__device__ __half g_Wuf[KK*KK];
__device__ __half g_Vf [MROWS*KK];
__device__ __half g_ysf[MROWS*KK];
__device__ int g_idx[BB*TT];
__device__ int g_nv [BB];

// ============================================================================
// helpers
// ============================================================================
__device__ __forceinline__ uint32_t smem_u32(const void* p) {
    uint32_t a;
    asm("{ .reg .u64 t; cvta.to.shared.u64 t, %1; cvt.u32.u64 %0, t; }"
        : "=r"(a) : "l"(p));
    return a;
}

__device__ __forceinline__ void mma_bf16(float d[4],
                                         uint32_t a0, uint32_t a1, uint32_t a2, uint32_t a3,
                                         uint32_t b0, uint32_t b1) {
    asm volatile(
        "mma.sync.aligned.m16n8k16.row.col.f32.bf16.bf16.f32 "
        "{%0,%1,%2,%3}, {%4,%5,%6,%7}, {%8,%9}, {%0,%1,%2,%3};"
        : "+f"(d[0]), "+f"(d[1]), "+f"(d[2]), "+f"(d[3])
        : "r"(a0), "r"(a1), "r"(a2), "r"(a3), "r"(b0), "r"(b1));
}

__device__ __forceinline__ void mma_f16f32(float d[4],
                                           uint32_t a0, uint32_t a1, uint32_t a2, uint32_t a3,
                                           uint32_t b0, uint32_t b1) {
    asm volatile(
        "mma.sync.aligned.m16n8k16.row.col.f32.f16.f16.f32 "
        "{%0,%1,%2,%3}, {%4,%5,%6,%7}, {%8,%9}, {%0,%1,%2,%3};"
        : "+f"(d[0]), "+f"(d[1]), "+f"(d[2]), "+f"(d[3])
        : "r"(a0), "r"(a1), "r"(a2), "r"(a3), "r"(b0), "r"(b1));
}

#define LDSM4(r0, r1, r2, r3, addr) \
    asm volatile("ldmatrix.sync.aligned.m8n8.x4.shared.b16 {%0,%1,%2,%3}, [%4];" \
                 : "=r"(r0), "=r"(r1), "=r"(r2), "=r"(r3) : "r"(addr))

__device__ __forceinline__ void split2(float2 f, uint32_t& h, uint32_t& l) {
    __nv_bfloat162 hh = __float22bfloat162_rn(f);
    float2 hf = __bfloat1622float2(hh);
    __nv_bfloat162 ll = __float22bfloat162_rn(make_float2(f.x - hf.x, f.y - hf.y));
    h = *(uint32_t*)&hh;
    l = *(uint32_t*)&ll;
}

__device__ __forceinline__ uint32_t pack_h2(float2 f) {
    __half2 hh = __float22half2_rn(f);
    return *(uint32_t*)&hh;
}

// ============================================================================
// preprocessing
// ============================================================================
__global__ __launch_bounds__(256)
void split_kernel(const float* __restrict__ in,
                  __nv_bfloat16* __restrict__ hi,
                  __nv_bfloat16* __restrict__ lo, int n2)
{
    for (int i = blockIdx.x * blockDim.x + threadIdx.x; i < n2;
         i += gridDim.x * blockDim.x) {
        float2 f = ((const float2*)in)[i];
        uint32_t h, l;
        split2(f, h, l);
        ((uint32_t*)hi)[i] = h;
        ((uint32_t*)lo)[i] = l;
    }
}

__global__ __launch_bounds__(256)
void half_kernel(const float* __restrict__ in, __half* __restrict__ outp, int n2)
{
    for (int i = blockIdx.x * blockDim.x + threadIdx.x; i < n2;
         i += gridDim.x * blockDim.x) {
        float2 f = ((const float2*)in)[i];
        ((uint32_t*)outp)[i] = pack_h2(f);
    }
}

// ============================================================================
// mask compaction (unchanged, proven)
// ============================================================================
__global__ __launch_bounds__(1024)
void compact_kernel(const int* __restrict__ mask, int* __restrict__ idx,
                    int* __restrict__ nv)
{
    __shared__ int s[1024];
    const int b = blockIdx.x;
    const int t = threadIdx.x;
    const int m0 = mask[b * TT + 2 * t];
    const int m1 = mask[b * TT + 2 * t + 1];
    const int c  = m0 + m1;
    s[t] = c;
    __syncthreads();
    for (int off = 1; off < 1024; off <<= 1) {
        int v = s[t];
        int u = (t >= off) ? s[t - off] : 0;
        __syncthreads();
        s[t] = v + u;
        __syncthreads();
    }
    const int incl = s[t];
    const int excl = incl - c;
    if (m0) idx[b * TT + excl] = 2 * t;
    if (m1) idx[b * TT + excl + m0] = 2 * t + 1;
    if (t == 1023) nv[b] = incl;
}

// ============================================================================
// 3-term split-bf16 GEMM (round-6 proven, 1 CTA/SM): Q and K projections.
// C = A @ B^T, output split-bf16.
// ============================================================================
#define GBK 32
#define NIT (KK / GBK)          // 32
#define BKP 40
#define ATILE (128 * BKP)
#define G3SMEM (8 * ATILE * 2)   // 81920 B

__global__ void __launch_bounds__(256)
gemm3_kernel(const __nv_bfloat16* __restrict__ Agh,
             const __nv_bfloat16* __restrict__ Agl,
             const __nv_bfloat16* __restrict__ Bgh,
             const __nv_bfloat16* __restrict__ Bgl,
             __nv_bfloat16* __restrict__ Ch,
             __nv_bfloat16* __restrict__ Cl,
             int M, int N)
{
    extern __shared__ __nv_bfloat16 sm3[];
    const uint32_t sbase = smem_u32(sm3);

    const int tid  = threadIdx.x;
    const int lane = tid & 31;
    const int wid  = tid >> 5;
    const int g    = lane >> 2;
    const int tg   = lane & 3;
    const int wm   = wid & 1;
    const int wn   = wid >> 1;
    const int m0   = blockIdx.y * 128;
    const int n0   = blockIdx.x * 128;

    const __nv_bfloat16* gsrc[4] = {
        Agh + (size_t)m0 * KK, Agl + (size_t)m0 * KK,
        Bgh + (size_t)n0 * KK, Bgl + (size_t)n0 * KK };

    const uint32_t aoff = (uint32_t)((wm * 64 + (lane & 15)) * BKP + ((lane & 16) ? 8 : 0));
    const uint32_t boff = (uint32_t)((wn * 32 + (lane & 7) + ((lane & 16) ? 8 : 0)) * BKP
                                     + ((lane & 8) ? 8 : 0));

#define G3ISSUE(k0, bsel) do { \
    _Pragma("unroll") \
    for (int a = 0; a < 4; a++) { \
        uint32_t sd = sbase + (uint32_t)(((bsel) * 4 + a) * ATILE) * 2; \
        _Pragma("unroll") \
        for (int j = 0; j < 2; j++) { \
            int row = j * 64 + (tid >> 2); int cc = tid & 3; \
            uint32_t s = sd + (uint32_t)(row * BKP + cc * 8) * 2; \
            const __nv_bfloat16* gp = gsrc[a] + (size_t)row * KK + (k0) + cc * 8; \
            asm volatile("cp.async.cg.shared.global [%0], [%1], 16;" :: "r"(s), "l"(gp)); \
        } \
    } \
    asm volatile("cp.async.commit_group;"); \
} while (0)

    float acc[4][4][4];
#pragma unroll
    for (int i = 0; i < 4; i++)
#pragma unroll
        for (int j = 0; j < 4; j++)
#pragma unroll
            for (int r = 0; r < 4; r++) acc[i][j][r] = 0.f;

    G3ISSUE(0, 0);

    for (int it = 0; it < NIT; it++) {
        const int buf = it & 1;
        asm volatile("cp.async.wait_group 0;");
        __syncthreads();
        if (it + 1 < NIT) G3ISSUE((it + 1) * GBK, buf ^ 1);

        const uint32_t bb = sbase + (uint32_t)(buf * 4 * ATILE) * 2;
#pragma unroll
        for (int ks = 0; ks < 2; ks++) {
            const uint32_t ko = ks * 32;
            uint32_t bh[4][2], bl[4][2];
            LDSM4(bh[0][0], bh[0][1], bh[1][0], bh[1][1],
                  bb + 2 * ATILE * 2 + boff * 2 + ko);
            LDSM4(bh[2][0], bh[2][1], bh[3][0], bh[3][1],
                  bb + 2 * ATILE * 2 + (boff + 16 * BKP) * 2 + ko);
            LDSM4(bl[0][0], bl[0][1], bl[1][0], bl[1][1],
                  bb + 3 * ATILE * 2 + boff * 2 + ko);
            LDSM4(bl[2][0], bl[2][1], bl[3][0], bl[3][1],
                  bb + 3 * ATILE * 2 + (boff + 16 * BKP) * 2 + ko);
#pragma unroll
            for (int mf = 0; mf < 4; mf++) {
                uint32_t ah0, ah1, ah2, ah3, al0, al1, al2, al3;
                LDSM4(ah0, ah1, ah2, ah3, bb + (aoff + mf * 16 * BKP) * 2 + ko);
                LDSM4(al0, al1, al2, al3, bb + ATILE * 2 + (aoff + mf * 16 * BKP) * 2 + ko);
#pragma unroll
                for (int nf = 0; nf < 4; nf++) {
                    mma_bf16(acc[mf][nf], ah0, ah1, ah2, ah3, bh[nf][0], bh[nf][1]);
                    mma_bf16(acc[mf][nf], ah0, ah1, ah2, ah3, bl[nf][0], bl[nf][1]);
                    mma_bf16(acc[mf][nf], al0, al1, al2, al3, bh[nf][0], bh[nf][1]);
                }
            }
        }
    }
#undef G3ISSUE

#pragma unroll
    for (int mf = 0; mf < 4; mf++) {
        int r0 = m0 + wm * 64 + mf * 16 + g;
#pragma unroll
        for (int nf = 0; nf < 4; nf++) {
            int col = n0 + wn * 32 + nf * 8 + tg * 2;
            uint32_t h0, l0, h1, l1;
            split2(make_float2(acc[mf][nf][0], acc[mf][nf][1]), h0, l0);
            split2(make_float2(acc[mf][nf][2], acc[mf][nf][3]), h1, l1);
            *(uint32_t*)&Ch[(size_t)r0 * N + col]       = h0;
            *(uint32_t*)&Cl[(size_t)r0 * N + col]       = l0;
            *(uint32_t*)&Ch[(size_t)(r0 + 8) * N + col] = h1;
            *(uint32_t*)&Cl[(size_t)(r0 + 8) * N + col] = l1;
        }
    }
}

// ============================================================================
// 1-term fp16 GEMM: C = A @ B^T (fp16 operands, fp32 accum).
// Output: fp32 (+bias) or fp16. V projection and output projection.
// ============================================================================
#define G1SMEM (4 * ATILE * 2)   // 2 bufs x (A+B) = 40960 B

__global__ void __launch_bounds__(256)
gemm1_kernel(const __half* __restrict__ Ag,
             const __half* __restrict__ Bg,
             const float* __restrict__ bias,
             float* __restrict__ Cf,
             __half* __restrict__ Chf,
             int M, int N)
{
    extern __shared__ __half sm1[];
    const uint32_t sbase = smem_u32(sm1);

    const int tid  = threadIdx.x;
    const int lane = tid & 31;
    const int wid  = tid >> 5;
    const int g    = lane >> 2;
    const int tg   = lane & 3;
    const int wm   = wid & 1;
    const int wn   = wid >> 1;
    const int m0   = blockIdx.y * 128;
    const int n0   = blockIdx.x * 128;

    const __half* gsrc[2] = { Ag + (size_t)m0 * KK, Bg + (size_t)n0 * KK };

    const uint32_t aoff = (uint32_t)((wm * 64 + (lane & 15)) * BKP + ((lane & 16) ? 8 : 0));
    const uint32_t boff = (uint32_t)((wn * 32 + (lane & 7) + ((lane & 16) ? 8 : 0)) * BKP
                                     + ((lane & 8) ? 8 : 0));

#define G1ISSUE(k0, bsel) do { \
    _Pragma("unroll") \
    for (int a = 0; a < 2; a++) { \
        uint32_t sd = sbase + (uint32_t)(((bsel) * 2 + a) * ATILE) * 2; \
        _Pragma("unroll") \
        for (int j = 0; j < 2; j++) { \
            int row = j * 64 + (tid >> 2); int cc = tid & 3; \
            uint32_t s = sd + (uint32_t)(row * BKP + cc * 8) * 2; \
            const __half* gp = gsrc[a] + (size_t)row * KK + (k0) + cc * 8; \
            asm volatile("cp.async.cg.shared.global [%0], [%1], 16;" :: "r"(s), "l"(gp)); \
        } \
    } \
    asm volatile("cp.async.commit_group;"); \
} while (0)

    float acc[4][4][4];
#pragma unroll
    for (int i = 0; i < 4; i++)
#pragma unroll
        for (int j = 0; j < 4; j++)
#pragma unroll
            for (int r = 0; r < 4; r++) acc[i][j][r] = 0.f;

    G1ISSUE(0, 0);

    for (int it = 0; it < NIT; it++) {
        const int buf = it & 1;
        asm volatile("cp.async.wait_group 0;");
        __syncthreads();
        if (it + 1 < NIT) G1ISSUE((it + 1) * GBK, buf ^ 1);

        const uint32_t bb = sbase + (uint32_t)(buf * 2 * ATILE) * 2;
#pragma unroll
        for (int ks = 0; ks < 2; ks++) {
            const uint32_t ko = ks * 32;
            uint32_t bf[4][2];
            LDSM4(bf[0][0], bf[0][1], bf[1][0], bf[1][1],
                  bb + ATILE * 2 + boff * 2 + ko);
            LDSM4(bf[2][0], bf[2][1], bf[3][0], bf[3][1],
                  bb + ATILE * 2 + (boff + 16 * BKP) * 2 + ko);
#pragma unroll
            for (int mf = 0; mf < 4; mf++) {
                uint32_t a0, a1, a2, a3;
                LDSM4(a0, a1, a2, a3, bb + (aoff + mf * 16 * BKP) * 2 + ko);
#pragma unroll
                for (int nf = 0; nf < 4; nf++)
                    mma_f16f32(acc[mf][nf], a0, a1, a2, a3, bf[nf][0], bf[nf][1]);
            }
        }
    }
#undef G1ISSUE

#pragma unroll
    for (int mf = 0; mf < 4; mf++) {
        int r0 = m0 + wm * 64 + mf * 16 + g;
#pragma unroll
        for (int nf = 0; nf < 4; nf++) {
            int col = n0 + wn * 32 + nf * 8 + tg * 2;
            if (Cf) {
                float b0 = 0.f, b1 = 0.f;
                if (bias) { b0 = __ldg(&bias[col]); b1 = __ldg(&bias[col + 1]); }
                float2 o0 = { acc[mf][nf][0] + b0, acc[mf][nf][1] + b1 };
                float2 o1 = { acc[mf][nf][2] + b0, acc[mf][nf][3] + b1 };
                *(float2*)&Cf[(size_t)r0 * N + col]       = o0;
                *(float2*)&Cf[(size_t)(r0 + 8) * N + col] = o1;
            } else {
                *(uint32_t*)&Chf[(size_t)r0 * N + col] =
                    pack_h2(make_float2(acc[mf][nf][0], acc[mf][nf][1]));
                *(uint32_t*)&Chf[(size_t)(r0 + 8) * N + col] =
                    pack_h2(make_float2(acc[mf][nf][2], acc[mf][nf][3]));
            }
        }
    }
}

// ============================================================================
// Flash attention: QK^T split-bf16 3-term (score path), PV single fp16 MMA.
// CTA = 128 queries x one (b,h). Output ys as fp16.
// ============================================================================
#define AST 72

__global__ __launch_bounds__(128, 2)
void attn_tc_kernel(const __nv_bfloat16* __restrict__ Qh_,
                    const __nv_bfloat16* __restrict__ Ql_,
                    const __nv_bfloat16* __restrict__ Kh_,
                    const __nv_bfloat16* __restrict__ Kl_,
                    const __half* __restrict__ Vf_,
                    const int* __restrict__ idx,
                    const int* __restrict__ nvp,
                    __half* __restrict__ ysf)
{
    __shared__ __nv_bfloat16 kh[64 * AST], kl[64 * AST];
    __shared__ __half vs[64 * AST];

    const int tid  = threadIdx.x;
    const int lane = tid & 31;
    const int w    = tid >> 5;
    const int g    = lane >> 2;
    const int tg   = lane & 3;
    const int b    = blockIdx.z;
    const int h    = blockIdx.y;
    const int q0   = blockIdx.x * 128;

    const int nvb    = nvp[b];
    const int ntiles = (nvb + 63) >> 6;

    const __nv_bfloat16* Qhb = Qh_ + (size_t)(b * TT + q0 + w * 32) * KK + h * SS;
    const __nv_bfloat16* Qlb = Ql_ + (size_t)(b * TT + q0 + w * 32) * KK + h * SS;
    uint32_t qh_[2][4][4], ql_[2][4][4];
#pragma unroll
    for (int m = 0; m < 2; m++) {
#pragma unroll
        for (int ks = 0; ks < 4; ks++) {
            int r0 = m * 16 + g, r1 = r0 + 8;
            int d0 = ks * 16 + 2 * tg;
            qh_[m][ks][0] = *(const uint32_t*)(Qhb + (size_t)r0 * KK + d0);
            qh_[m][ks][1] = *(const uint32_t*)(Qhb + (size_t)r1 * KK + d0);
            qh_[m][ks][2] = *(const uint32_t*)(Qhb + (size_t)r0 * KK + d0 + 8);
            qh_[m][ks][3] = *(const uint32_t*)(Qhb + (size_t)r1 * KK + d0 + 8);
            ql_[m][ks][0] = *(const uint32_t*)(Qlb + (size_t)r0 * KK + d0);
            ql_[m][ks][1] = *(const uint32_t*)(Qlb + (size_t)r1 * KK + d0);
            ql_[m][ks][2] = *(const uint32_t*)(Qlb + (size_t)r0 * KK + d0 + 8);
            ql_[m][ks][3] = *(const uint32_t*)(Qlb + (size_t)r1 * KK + d0 + 8);
        }
    }

    float o[2][8][4];
#pragma unroll
    for (int m = 0; m < 2; m++)
#pragma unroll
        for (int nt = 0; nt < 8; nt++)
#pragma unroll
            for (int c = 0; c < 4; c++) o[m][nt][c] = 0.f;
    float mr[2][2] = { {-1e30f, -1e30f}, {-1e30f, -1e30f} };
    float lr[2][2] = { {0.f, 0.f}, {0.f, 0.f} };

    const int* idxb = idx + b * TT;
    const __nv_bfloat16* Khb = Kh_ + (size_t)b * TT * KK + h * SS;
    const __nv_bfloat16* Klb = Kl_ + (size_t)b * TT * KK + h * SS;
    const __half*        Vfb = Vf_ + (size_t)b * TT * KK + h * SS;

    const int ikey = tid >> 1;
    const int half = tid & 1;

    for (int kt = 0; kt < ntiles; kt++) {
        __syncthreads();
        int slot = kt * 64 + ikey;
        int r = (slot < nvb) ? idxb[slot] : 0;
        // K tile: row copy (split bf16)
        {
            const uint4* kph = (const uint4*)(Khb + (size_t)r * KK + half * 32);
            const uint4* kpl = (const uint4*)(Klb + (size_t)r * KK + half * 32);
            int dst = ikey * AST + half * 32;
#pragma unroll
            for (int j = 0; j < 4; j++) {
                *(uint4*)&kh[dst + j * 8] = kph[j];
                *(uint4*)&kl[dst + j * 8] = kpl[j];
            }
        }
        // V tile: transposed scatter (single fp16)
        {
            const __half2* vph = (const __half2*)(Vfb + (size_t)r * KK + half * 32);
#pragma unroll
            for (int jj = 0; jj < 16; jj++) {
                int dd = half * 32 + 2 * jj;
                __half2 pv = vph[jj];
                vs[dd * AST + ikey]       = __low2half(pv);
                vs[(dd + 1) * AST + ikey] = __high2half(pv);
            }
        }
        __syncthreads();

        // ---- S = Q K^T (bf16 3-term) ----
        float s[2][8][4];
#pragma unroll
        for (int m = 0; m < 2; m++)
#pragma unroll
            for (int nt = 0; nt < 8; nt++)
#pragma unroll
                for (int c = 0; c < 4; c++) s[m][nt][c] = 0.f;

#pragma unroll
        for (int ks = 0; ks < 4; ks++) {
            const int kk = ks * 16 + 2 * tg;
#pragma unroll
            for (int nt = 0; nt < 8; nt++) {
                const int rr = (nt * 8 + g) * AST + kk;
                uint32_t bh0 = *(const uint32_t*)&kh[rr];
                uint32_t bh1 = *(const uint32_t*)&kh[rr + 8];
                uint32_t bl0 = *(const uint32_t*)&kl[rr];
                uint32_t bl1 = *(const uint32_t*)&kl[rr + 8];
#pragma unroll
                for (int m = 0; m < 2; m++) {
                    mma_bf16(s[m][nt], qh_[m][ks][0], qh_[m][ks][1], qh_[m][ks][2], qh_[m][ks][3], bh0, bh1);
                    mma_bf16(s[m][nt], qh_[m][ks][0], qh_[m][ks][1], qh_[m][ks][2], qh_[m][ks][3], bl0, bl1);
                    mma_bf16(s[m][nt], ql_[m][ks][0], ql_[m][ks][1], ql_[m][ks][2], ql_[m][ks][3], bh0, bh1);
                }
            }
        }

        // ---- tail masking ----
        if (kt * 64 + 64 > nvb) {
#pragma unroll
            for (int nt = 0; nt < 8; nt++) {
                int c0 = kt * 64 + nt * 8 + 2 * tg;
                if (c0 >= nvb) {
                    s[0][nt][0] = s[0][nt][2] = -1e30f;
                    s[1][nt][0] = s[1][nt][2] = -1e30f;
                }
                if (c0 + 1 >= nvb) {
                    s[0][nt][1] = s[0][nt][3] = -1e30f;
                    s[1][nt][1] = s[1][nt][3] = -1e30f;
                }
            }
        }

        // ---- online softmax ----
#pragma unroll
        for (int m = 0; m < 2; m++) {
#pragma unroll
            for (int r2 = 0; r2 < 2; r2++) {
                const int c0 = r2 * 2;
                float tmax = -1e30f;
#pragma unroll
                for (int nt = 0; nt < 8; nt++) {
                    tmax = fmaxf(tmax, s[m][nt][c0]);
                    tmax = fmaxf(tmax, s[m][nt][c0 + 1]);
                }
                tmax = fmaxf(tmax, __shfl_xor_sync(0xffffffffu, tmax, 1));
                tmax = fmaxf(tmax, __shfl_xor_sync(0xffffffffu, tmax, 2));
                float mn = fmaxf(mr[m][r2], tmax);
                float sc = __expf(mr[m][r2] - mn);
                mr[m][r2] = mn;
                float ts = 0.f;
#pragma unroll
                for (int nt = 0; nt < 8; nt++) {
                    float p0 = __expf(s[m][nt][c0]     - mn);
                    float p1 = __expf(s[m][nt][c0 + 1] - mn);
                    s[m][nt][c0]     = p0;
                    s[m][nt][c0 + 1] = p1;
                    ts += p0 + p1;
                }
                ts += __shfl_xor_sync(0xffffffffu, ts, 1);
                ts += __shfl_xor_sync(0xffffffffu, ts, 2);
                lr[m][r2] = lr[m][r2] * sc + ts;
#pragma unroll
                for (int nt = 0; nt < 8; nt++) {
                    o[m][nt][c0]     *= sc;
                    o[m][nt][c0 + 1] *= sc;
                }
            }
        }

        // ---- O += P V (single fp16 MMA) ----
#pragma unroll
        for (int ks = 0; ks < 4; ks++) {
            uint32_t ph[2][4];
#pragma unroll
            for (int m = 0; m < 2; m++) {
                ph[m][0] = pack_h2(make_float2(s[m][2*ks][0],   s[m][2*ks][1]));
                ph[m][1] = pack_h2(make_float2(s[m][2*ks][2],   s[m][2*ks][3]));
                ph[m][2] = pack_h2(make_float2(s[m][2*ks+1][0], s[m][2*ks+1][1]));
                ph[m][3] = pack_h2(make_float2(s[m][2*ks+1][2], s[m][2*ks+1][3]));
            }
            const int kk = ks * 16 + 2 * tg;
#pragma unroll
            for (int nt = 0; nt < 8; nt++) {
                const int rr = (nt * 8 + g) * AST + kk;
                uint32_t v0 = *(const uint32_t*)&vs[rr];
                uint32_t v1 = *(const uint32_t*)&vs[rr + 8];
#pragma unroll
                for (int m = 0; m < 2; m++)
                    mma_f16f32(o[m][nt], ph[m][0], ph[m][1], ph[m][2], ph[m][3], v0, v1);
            }
        }
    }

    // ---- epilogue: normalize, emit fp16 ----
#pragma unroll
    for (int m = 0; m < 2; m++) {
#pragma unroll
        for (int r2 = 0; r2 < 2; r2++) {
            float inv = 1.f / lr[m][r2];
            int row = q0 + w * 32 + m * 16 + g + r2 * 8;
            size_t off = (size_t)(b * TT + row) * KK + h * SS;
#pragma unroll
            for (int nt = 0; nt < 8; nt++) {
                *(uint32_t*)&ysf[off + nt * 8 + 2 * tg] =
                    pack_h2(make_float2(o[m][nt][r2*2] * inv, o[m][nt][r2*2+1] * inv));
            }
        }
    }
}

// ============================================================================
// launch
// ============================================================================
extern "C" void kernel_launch(void* const* d_in, const int* in_sizes, int n_in,
                              void* d_out, int out_size)
{
    const float* x    = (const float*)d_in[0];
    const int*   mask = (const int*)  d_in[1];
    const float* Wk   = (const float*)d_in[2];
    const float* Wq   = (const float*)d_in[3];
    const float* Wv   = (const float*)d_in[4];
    const float* Wu   = (const float*)d_in[5];
    const float* bu   = (const float*)d_in[6];
    float* out = (float*)d_out;

    __nv_bfloat16 *xh, *xl, *Wqh, *Wql, *Wkh, *Wkl, *Qh, *Ql, *Kh, *Kl;
    __half *xf, *Wvf, *Wuf, *Vf, *ysf;
    int *idx, *nv;
    cudaGetSymbolAddress((void**)&xh,  g_xh);  cudaGetSymbolAddress((void**)&xl,  g_xl);
    cudaGetSymbolAddress((void**)&Wqh, g_Wqh); cudaGetSymbolAddress((void**)&Wql, g_Wql);
    cudaGetSymbolAddress((void**)&Wkh, g_Wkh); cudaGetSymbolAddress((void**)&Wkl, g_Wkl);
    cudaGetSymbolAddress((void**)&Qh,  g_Qh);  cudaGetSymbolAddress((void**)&Ql,  g_Ql);
    cudaGetSymbolAddress((void**)&Kh,  g_Kh);  cudaGetSymbolAddress((void**)&Kl,  g_Kl);
    cudaGetSymbolAddress((void**)&xf,  g_xf);
    cudaGetSymbolAddress((void**)&Wvf, g_Wvf); cudaGetSymbolAddress((void**)&Wuf, g_Wuf);
    cudaGetSymbolAddress((void**)&Vf,  g_Vf);  cudaGetSymbolAddress((void**)&ysf, g_ysf);
    cudaGetSymbolAddress((void**)&idx, g_idx); cudaGetSymbolAddress((void**)&nv,  g_nv);

    cudaFuncSetAttribute(gemm3_kernel,
                         cudaFuncAttributeMaxDynamicSharedMemorySize, G3SMEM);
    cudaFuncSetAttribute(gemm1_kernel,
                         cudaFuncAttributeMaxDynamicSharedMemorySize, G1SMEM);

    // preprocessing
    split_kernel<<<512, 256>>>(x,  xh,  xl,  MROWS * KK / 2);
    split_kernel<<<256, 256>>>(Wq, Wqh, Wql, KK * KK / 2);
    split_kernel<<<256, 256>>>(Wk, Wkh, Wkl, KK * KK / 2);
    half_kernel <<<512, 256>>>(x,  xf,  MROWS * KK / 2);
    half_kernel <<<256, 256>>>(Wv, Wvf, KK * KK / 2);
    half_kernel <<<256, 256>>>(Wu, Wuf, KK * KK / 2);
    compact_kernel<<<BB, 1024>>>(mask, idx, nv);

    dim3 gg(KK / 128, MROWS / 128);   // (8, 32)
    gemm3_kernel<<<gg, 256, G3SMEM>>>(xh, xl, Wqh, Wql, Qh, Ql, MROWS, KK);
    gemm3_kernel<<<gg, 256, G3SMEM>>>(xh, xl, Wkh, Wkl, Kh, Kl, MROWS, KK);
    gemm1_kernel<<<gg, 256, G1SMEM>>>(xf, Wvf, nullptr, nullptr, Vf, MROWS, KK);

    dim3 ga(TT / 128, HH, BB);        // (16, 16, 2)
    attn_tc_kernel<<<ga, 128>>>(Qh, Ql, Kh, Kl, Vf, idx, nv, ysf);

    gemm1_kernel<<<gg, 256, G1SMEM>>>(ysf, Wuf, bu, out, nullptr, MROWS, KK);
}

// round 10
// speedup vs baseline: 2.0770x; 1.0449x over previous
#include <cuda_runtime.h>
#include <cuda_bf16.h>
#include <cuda_fp16.h>
#include <cstdint>

#define BB   2
#define TT   2048
#define KK   1024
#define HH   16
#define SS   64
#define MROWS (BB*TT)   // 4096

// ---- scratch (static device globals; no allocation allowed) ----
__device__ __nv_bfloat16 g_xh[MROWS*KK], g_xl[MROWS*KK];      // x split (Q GEMM)
__device__ __nv_bfloat16 g_xgh[MROWS*KK], g_xgl[MROWS*KK];    // gathered x split (K GEMM)
__device__ __half        g_xgf[MROWS*KK];                      // gathered x fp16 (V GEMM)
__device__ __nv_bfloat16 g_Wqh[KK*KK],  g_Wql[KK*KK];
__device__ __nv_bfloat16 g_Wkh[KK*KK],  g_Wkl[KK*KK];
__device__ __nv_bfloat16 g_Qh[MROWS*KK], g_Ql[MROWS*KK];
__device__ __nv_bfloat16 g_Kh[MROWS*KK], g_Kl[MROWS*KK];      // compacted K
__device__ __half g_Wvf[KK*KK];
__device__ __half g_Wuf[KK*KK];
__device__ __half g_Vf [MROWS*KK];                             // compacted V
__device__ __half g_ysf[MROWS*KK];
__device__ int g_idx[BB*TT];
__device__ int g_nv [BB];

// ============================================================================
// helpers
// ============================================================================
__device__ __forceinline__ uint32_t smem_u32(const void* p) {
    uint32_t a;
    asm("{ .reg .u64 t; cvta.to.shared.u64 t, %1; cvt.u32.u64 %0, t; }"
        : "=r"(a) : "l"(p));
    return a;
}

__device__ __forceinline__ void mma_bf16(float d[4],
                                         uint32_t a0, uint32_t a1, uint32_t a2, uint32_t a3,
                                         uint32_t b0, uint32_t b1) {
    asm volatile(
        "mma.sync.aligned.m16n8k16.row.col.f32.bf16.bf16.f32 "
        "{%0,%1,%2,%3}, {%4,%5,%6,%7}, {%8,%9}, {%0,%1,%2,%3};"
        : "+f"(d[0]), "+f"(d[1]), "+f"(d[2]), "+f"(d[3])
        : "r"(a0), "r"(a1), "r"(a2), "r"(a3), "r"(b0), "r"(b1));
}

__device__ __forceinline__ void mma_f16f32(float d[4],
                                           uint32_t a0, uint32_t a1, uint32_t a2, uint32_t a3,
                                           uint32_t b0, uint32_t b1) {
    asm volatile(
        "mma.sync.aligned.m16n8k16.row.col.f32.f16.f16.f32 "
        "{%0,%1,%2,%3}, {%4,%5,%6,%7}, {%8,%9}, {%0,%1,%2,%3};"
        : "+f"(d[0]), "+f"(d[1]), "+f"(d[2]), "+f"(d[3])
        : "r"(a0), "r"(a1), "r"(a2), "r"(a3), "r"(b0), "r"(b1));
}

#define LDSM4(r0, r1, r2, r3, addr) \
    asm volatile("ldmatrix.sync.aligned.m8n8.x4.shared.b16 {%0,%1,%2,%3}, [%4];" \
                 : "=r"(r0), "=r"(r1), "=r"(r2), "=r"(r3) : "r"(addr))

__device__ __forceinline__ void split2(float2 f, uint32_t& h, uint32_t& l) {
    __nv_bfloat162 hh = __float22bfloat162_rn(f);
    float2 hf = __bfloat1622float2(hh);
    __nv_bfloat162 ll = __float22bfloat162_rn(make_float2(f.x - hf.x, f.y - hf.y));
    h = *(uint32_t*)&hh;
    l = *(uint32_t*)&ll;
}

__device__ __forceinline__ uint32_t pack_h2(float2 f) {
    __half2 hh = __float22half2_rn(f);
    return *(uint32_t*)&hh;
}

// ============================================================================
// preprocessing (fused)
// ============================================================================
// x -> split bf16 (Q GEMM input)  [gathered variants made separately]
__global__ __launch_bounds__(256)
void prep_x_kernel(const float* __restrict__ x,
                   __nv_bfloat16* __restrict__ xh,
                   __nv_bfloat16* __restrict__ xl)
{
    int i = blockIdx.x * 256 + threadIdx.x;           // over MROWS*KK/2 float2
    float2 f = ((const float2*)x)[i];
    uint32_t h, l;
    split2(f, h, l);
    ((uint32_t*)xh)[i] = h;
    ((uint32_t*)xl)[i] = l;
}

// all 4 weights in one launch: z=0 Wq split, z=1 Wk split, z=2 Wv half, z=3 Wu half
__global__ __launch_bounds__(256)
void prep_w_kernel(const float* __restrict__ Wq, const float* __restrict__ Wk,
                   const float* __restrict__ Wv, const float* __restrict__ Wu,
                   __nv_bfloat16* __restrict__ Wqh, __nv_bfloat16* __restrict__ Wql,
                   __nv_bfloat16* __restrict__ Wkh, __nv_bfloat16* __restrict__ Wkl,
                   __half* __restrict__ Wvf, __half* __restrict__ Wuf)
{
    int i = blockIdx.x * 256 + threadIdx.x;           // over KK*KK/2 float2
    int z = blockIdx.y;
    if (z == 0) {
        float2 f = ((const float2*)Wq)[i];
        uint32_t h, l; split2(f, h, l);
        ((uint32_t*)Wqh)[i] = h; ((uint32_t*)Wql)[i] = l;
    } else if (z == 1) {
        float2 f = ((const float2*)Wk)[i];
        uint32_t h, l; split2(f, h, l);
        ((uint32_t*)Wkh)[i] = h; ((uint32_t*)Wkl)[i] = l;
    } else if (z == 2) {
        ((uint32_t*)Wvf)[i] = pack_h2(((const float2*)Wv)[i]);
    } else {
        ((uint32_t*)Wuf)[i] = pack_h2(((const float2*)Wu)[i]);
    }
}

// gather valid x rows (compacted): writes bf16 split (K GEMM) + fp16 (V GEMM)
__global__ __launch_bounds__(256)
void gather_kernel(const float* __restrict__ x,
                   const int* __restrict__ idx,
                   const int* __restrict__ nv,
                   __nv_bfloat16* __restrict__ xgh,
                   __nv_bfloat16* __restrict__ xgl,
                   __half* __restrict__ xgf)
{
    int i = blockIdx.x * 256 + threadIdx.x;           // over MROWS*KK/2 float2
    int slot = i >> 9;                                // 512 float2 per row
    int c2   = i & 511;
    int b    = slot / TT;
    int s    = slot - b * TT;
    int r    = (s < nv[b]) ? idx[b * TT + s] : idx[b * TT];
    float2 f = ((const float2*)(x + (size_t)(b * TT + r) * KK))[c2];
    uint32_t h, l;
    split2(f, h, l);
    ((uint32_t*)(xgh + (size_t)slot * KK))[c2] = h;
    ((uint32_t*)(xgl + (size_t)slot * KK))[c2] = l;
    ((uint32_t*)(xgf + (size_t)slot * KK))[c2] = pack_h2(f);
}

// ============================================================================
// mask compaction (unchanged, proven)
// ============================================================================
__global__ __launch_bounds__(1024)
void compact_kernel(const int* __restrict__ mask, int* __restrict__ idx,
                    int* __restrict__ nv)
{
    __shared__ int s[1024];
    const int b = blockIdx.x;
    const int t = threadIdx.x;
    const int m0 = mask[b * TT + 2 * t];
    const int m1 = mask[b * TT + 2 * t + 1];
    const int c  = m0 + m1;
    s[t] = c;
    __syncthreads();
    for (int off = 1; off < 1024; off <<= 1) {
        int v = s[t];
        int u = (t >= off) ? s[t - off] : 0;
        __syncthreads();
        s[t] = v + u;
        __syncthreads();
    }
    const int incl = s[t];
    const int excl = incl - c;
    if (m0) idx[b * TT + excl] = 2 * t;
    if (m1) idx[b * TT + excl + m0] = 2 * t + 1;
    if (t == 1023) nv[b] = incl;
}

// ============================================================================
// 3-term split-bf16 GEMM (proven). Optional per-batch early exit via nvp.
// ============================================================================
#define GBK 32
#define NIT (KK / GBK)          // 32
#define BKP 40
#define ATILE (128 * BKP)
#define G3SMEM (8 * ATILE * 2)   // 81920 B

__global__ void __launch_bounds__(256)
gemm3_kernel(const __nv_bfloat16* __restrict__ Agh,
             const __nv_bfloat16* __restrict__ Agl,
             const __nv_bfloat16* __restrict__ Bgh,
             const __nv_bfloat16* __restrict__ Bgl,
             __nv_bfloat16* __restrict__ Ch,
             __nv_bfloat16* __restrict__ Cl,
             const int* __restrict__ nvp,
             int M, int N)
{
    const int m0 = blockIdx.y * 128;
    if (nvp) {
        int bb2 = m0 / TT;
        int sl  = m0 - bb2 * TT;
        if (sl >= nvp[bb2]) return;   // whole tile beyond valid keys
    }

    extern __shared__ __nv_bfloat16 sm3[];
    const uint32_t sbase = smem_u32(sm3);

    const int tid  = threadIdx.x;
    const int lane = tid & 31;
    const int wid  = tid >> 5;
    const int g    = lane >> 2;
    const int tg   = lane & 3;
    const int wm   = wid & 1;
    const int wn   = wid >> 1;
    const int n0   = blockIdx.x * 128;

    const __nv_bfloat16* gsrc[4] = {
        Agh + (size_t)m0 * KK, Agl + (size_t)m0 * KK,
        Bgh + (size_t)n0 * KK, Bgl + (size_t)n0 * KK };

    const uint32_t aoff = (uint32_t)((wm * 64 + (lane & 15)) * BKP + ((lane & 16) ? 8 : 0));
    const uint32_t boff = (uint32_t)((wn * 32 + (lane & 7) + ((lane & 16) ? 8 : 0)) * BKP
                                     + ((lane & 8) ? 8 : 0));

#define G3ISSUE(k0, bsel) do { \
    _Pragma("unroll") \
    for (int a = 0; a < 4; a++) { \
        uint32_t sd = sbase + (uint32_t)(((bsel) * 4 + a) * ATILE) * 2; \
        _Pragma("unroll") \
        for (int j = 0; j < 2; j++) { \
            int row = j * 64 + (tid >> 2); int cc = tid & 3; \
            uint32_t s = sd + (uint32_t)(row * BKP + cc * 8) * 2; \
            const __nv_bfloat16* gp = gsrc[a] + (size_t)row * KK + (k0) + cc * 8; \
            asm volatile("cp.async.cg.shared.global [%0], [%1], 16;" :: "r"(s), "l"(gp)); \
        } \
    } \
    asm volatile("cp.async.commit_group;"); \
} while (0)

    float acc[4][4][4];
#pragma unroll
    for (int i = 0; i < 4; i++)
#pragma unroll
        for (int j = 0; j < 4; j++)
#pragma unroll
            for (int r = 0; r < 4; r++) acc[i][j][r] = 0.f;

    G3ISSUE(0, 0);

    for (int it = 0; it < NIT; it++) {
        const int buf = it & 1;
        asm volatile("cp.async.wait_group 0;");
        __syncthreads();
        if (it + 1 < NIT) G3ISSUE((it + 1) * GBK, buf ^ 1);

        const uint32_t bb = sbase + (uint32_t)(buf * 4 * ATILE) * 2;
#pragma unroll
        for (int ks = 0; ks < 2; ks++) {
            const uint32_t ko = ks * 32;
            uint32_t bh[4][2], bl[4][2];
            LDSM4(bh[0][0], bh[0][1], bh[1][0], bh[1][1],
                  bb + 2 * ATILE * 2 + boff * 2 + ko);
            LDSM4(bh[2][0], bh[2][1], bh[3][0], bh[3][1],
                  bb + 2 * ATILE * 2 + (boff + 16 * BKP) * 2 + ko);
            LDSM4(bl[0][0], bl[0][1], bl[1][0], bl[1][1],
                  bb + 3 * ATILE * 2 + boff * 2 + ko);
            LDSM4(bl[2][0], bl[2][1], bl[3][0], bl[3][1],
                  bb + 3 * ATILE * 2 + (boff + 16 * BKP) * 2 + ko);
#pragma unroll
            for (int mf = 0; mf < 4; mf++) {
                uint32_t ah0, ah1, ah2, ah3, al0, al1, al2, al3;
                LDSM4(ah0, ah1, ah2, ah3, bb + (aoff + mf * 16 * BKP) * 2 + ko);
                LDSM4(al0, al1, al2, al3, bb + ATILE * 2 + (aoff + mf * 16 * BKP) * 2 + ko);
#pragma unroll
                for (int nf = 0; nf < 4; nf++) {
                    mma_bf16(acc[mf][nf], ah0, ah1, ah2, ah3, bh[nf][0], bh[nf][1]);
                    mma_bf16(acc[mf][nf], ah0, ah1, ah2, ah3, bl[nf][0], bl[nf][1]);
                    mma_bf16(acc[mf][nf], al0, al1, al2, al3, bh[nf][0], bh[nf][1]);
                }
            }
        }
    }
#undef G3ISSUE

#pragma unroll
    for (int mf = 0; mf < 4; mf++) {
        int r0 = m0 + wm * 64 + mf * 16 + g;
#pragma unroll
        for (int nf = 0; nf < 4; nf++) {
            int col = n0 + wn * 32 + nf * 8 + tg * 2;
            uint32_t h0, l0, h1, l1;
            split2(make_float2(acc[mf][nf][0], acc[mf][nf][1]), h0, l0);
            split2(make_float2(acc[mf][nf][2], acc[mf][nf][3]), h1, l1);
            *(uint32_t*)&Ch[(size_t)r0 * N + col]       = h0;
            *(uint32_t*)&Cl[(size_t)r0 * N + col]       = l0;
            *(uint32_t*)&Ch[(size_t)(r0 + 8) * N + col] = h1;
            *(uint32_t*)&Cl[(size_t)(r0 + 8) * N + col] = l1;
        }
    }
}

// ============================================================================
// 1-term fp16 GEMM. Optional per-batch early exit via nvp.
// ============================================================================
#define G1SMEM (4 * ATILE * 2)   // 40960 B

__global__ void __launch_bounds__(256)
gemm1_kernel(const __half* __restrict__ Ag,
             const __half* __restrict__ Bg,
             const float* __restrict__ bias,
             float* __restrict__ Cf,
             __half* __restrict__ Chf,
             const int* __restrict__ nvp,
             int M, int N)
{
    const int m0 = blockIdx.y * 128;
    if (nvp) {
        int bb2 = m0 / TT;
        int sl  = m0 - bb2 * TT;
        if (sl >= nvp[bb2]) return;
    }

    extern __shared__ __half sm1[];
    const uint32_t sbase = smem_u32(sm1);

    const int tid  = threadIdx.x;
    const int lane = tid & 31;
    const int wid  = tid >> 5;
    const int g    = lane >> 2;
    const int tg   = lane & 3;
    const int wm   = wid & 1;
    const int wn   = wid >> 1;
    const int n0   = blockIdx.x * 128;

    const __half* gsrc[2] = { Ag + (size_t)m0 * KK, Bg + (size_t)n0 * KK };

    const uint32_t aoff = (uint32_t)((wm * 64 + (lane & 15)) * BKP + ((lane & 16) ? 8 : 0));
    const uint32_t boff = (uint32_t)((wn * 32 + (lane & 7) + ((lane & 16) ? 8 : 0)) * BKP
                                     + ((lane & 8) ? 8 : 0));

#define G1ISSUE(k0, bsel) do { \
    _Pragma("unroll") \
    for (int a = 0; a < 2; a++) { \
        uint32_t sd = sbase + (uint32_t)(((bsel) * 2 + a) * ATILE) * 2; \
        _Pragma("unroll") \
        for (int j = 0; j < 2; j++) { \
            int row = j * 64 + (tid >> 2); int cc = tid & 3; \
            uint32_t s = sd + (uint32_t)(row * BKP + cc * 8) * 2; \
            const __half* gp = gsrc[a] + (size_t)row * KK + (k0) + cc * 8; \
            asm volatile("cp.async.cg.shared.global [%0], [%1], 16;" :: "r"(s), "l"(gp)); \
        } \
    } \
    asm volatile("cp.async.commit_group;"); \
} while (0)

    float acc[4][4][4];
#pragma unroll
    for (int i = 0; i < 4; i++)
#pragma unroll
        for (int j = 0; j < 4; j++)
#pragma unroll
            for (int r = 0; r < 4; r++) acc[i][j][r] = 0.f;

    G1ISSUE(0, 0);

    for (int it = 0; it < NIT; it++) {
        const int buf = it & 1;
        asm volatile("cp.async.wait_group 0;");
        __syncthreads();
        if (it + 1 < NIT) G1ISSUE((it + 1) * GBK, buf ^ 1);

        const uint32_t bb = sbase + (uint32_t)(buf * 2 * ATILE) * 2;
#pragma unroll
        for (int ks = 0; ks < 2; ks++) {
            const uint32_t ko = ks * 32;
            uint32_t bf[4][2];
            LDSM4(bf[0][0], bf[0][1], bf[1][0], bf[1][1],
                  bb + ATILE * 2 + boff * 2 + ko);
            LDSM4(bf[2][0], bf[2][1], bf[3][0], bf[3][1],
                  bb + ATILE * 2 + (boff + 16 * BKP) * 2 + ko);
#pragma unroll
            for (int mf = 0; mf < 4; mf++) {
                uint32_t a0, a1, a2, a3;
                LDSM4(a0, a1, a2, a3, bb + (aoff + mf * 16 * BKP) * 2 + ko);
#pragma unroll
                for (int nf = 0; nf < 4; nf++)
                    mma_f16f32(acc[mf][nf], a0, a1, a2, a3, bf[nf][0], bf[nf][1]);
            }
        }
    }
#undef G1ISSUE

#pragma unroll
    for (int mf = 0; mf < 4; mf++) {
        int r0 = m0 + wm * 64 + mf * 16 + g;
#pragma unroll
        for (int nf = 0; nf < 4; nf++) {
            int col = n0 + wn * 32 + nf * 8 + tg * 2;
            if (Cf) {
                float b0 = 0.f, b1 = 0.f;
                if (bias) { b0 = __ldg(&bias[col]); b1 = __ldg(&bias[col + 1]); }
                float2 o0 = { acc[mf][nf][0] + b0, acc[mf][nf][1] + b1 };
                float2 o1 = { acc[mf][nf][2] + b0, acc[mf][nf][3] + b1 };
                *(float2*)&Cf[(size_t)r0 * N + col]       = o0;
                *(float2*)&Cf[(size_t)(r0 + 8) * N + col] = o1;
            } else {
                *(uint32_t*)&Chf[(size_t)r0 * N + col] =
                    pack_h2(make_float2(acc[mf][nf][0], acc[mf][nf][1]));
                *(uint32_t*)&Chf[(size_t)(r0 + 8) * N + col] =
                    pack_h2(make_float2(acc[mf][nf][2], acc[mf][nf][3]));
            }
        }
    }
}

// ============================================================================
// Flash attention over COMPACTED K/V: QK^T bf16 3-term, PV fp16 1-term.
// ============================================================================
#define AST 72

__global__ __launch_bounds__(128, 2)
void attn_tc_kernel(const __nv_bfloat16* __restrict__ Qh_,
                    const __nv_bfloat16* __restrict__ Ql_,
                    const __nv_bfloat16* __restrict__ Kh_,
                    const __nv_bfloat16* __restrict__ Kl_,
                    const __half* __restrict__ Vf_,
                    const int* __restrict__ nvp,
                    __half* __restrict__ ysf)
{
    __shared__ __nv_bfloat16 kh[64 * AST], kl[64 * AST];
    __shared__ __half vs[64 * AST];

    const int tid  = threadIdx.x;
    const int lane = tid & 31;
    const int w    = tid >> 5;
    const int g    = lane >> 2;
    const int tg   = lane & 3;
    const int b    = blockIdx.z;
    const int h    = blockIdx.y;
    const int q0   = blockIdx.x * 128;

    const int nvb    = nvp[b];
    const int ntiles = (nvb + 63) >> 6;

    const __nv_bfloat16* Qhb = Qh_ + (size_t)(b * TT + q0 + w * 32) * KK + h * SS;
    const __nv_bfloat16* Qlb = Ql_ + (size_t)(b * TT + q0 + w * 32) * KK + h * SS;
    uint32_t qh_[2][4][4], ql_[2][4][4];
#pragma unroll
    for (int m = 0; m < 2; m++) {
#pragma unroll
        for (int ks = 0; ks < 4; ks++) {
            int r0 = m * 16 + g, r1 = r0 + 8;
            int d0 = ks * 16 + 2 * tg;
            qh_[m][ks][0] = *(const uint32_t*)(Qhb + (size_t)r0 * KK + d0);
            qh_[m][ks][1] = *(const uint32_t*)(Qhb + (size_t)r1 * KK + d0);
            qh_[m][ks][2] = *(const uint32_t*)(Qhb + (size_t)r0 * KK + d0 + 8);
            qh_[m][ks][3] = *(const uint32_t*)(Qhb + (size_t)r1 * KK + d0 + 8);
            ql_[m][ks][0] = *(const uint32_t*)(Qlb + (size_t)r0 * KK + d0);
            ql_[m][ks][1] = *(const uint32_t*)(Qlb + (size_t)r1 * KK + d0);
            ql_[m][ks][2] = *(const uint32_t*)(Qlb + (size_t)r0 * KK + d0 + 8);
            ql_[m][ks][3] = *(const uint32_t*)(Qlb + (size_t)r1 * KK + d0 + 8);
        }
    }

    float o[2][8][4];
#pragma unroll
    for (int m = 0; m < 2; m++)
#pragma unroll
        for (int nt = 0; nt < 8; nt++)
#pragma unroll
            for (int c = 0; c < 4; c++) o[m][nt][c] = 0.f;
    float mr[2][2] = { {-1e30f, -1e30f}, {-1e30f, -1e30f} };
    float lr[2][2] = { {0.f, 0.f}, {0.f, 0.f} };

    const __nv_bfloat16* Khb = Kh_ + (size_t)b * TT * KK + h * SS;
    const __nv_bfloat16* Klb = Kl_ + (size_t)b * TT * KK + h * SS;
    const __half*        Vfb = Vf_ + (size_t)b * TT * KK + h * SS;

    const int ikey = tid >> 1;
    const int half = tid & 1;

    for (int kt = 0; kt < ntiles; kt++) {
        __syncthreads();
        int slot = kt * 64 + ikey;      // compacted: direct row, no gather
        // K tile: row copy (split bf16)
        {
            const uint4* kph = (const uint4*)(Khb + (size_t)slot * KK + half * 32);
            const uint4* kpl = (const uint4*)(Klb + (size_t)slot * KK + half * 32);
            int dst = ikey * AST + half * 32;
#pragma unroll
            for (int j = 0; j < 4; j++) {
                *(uint4*)&kh[dst + j * 8] = kph[j];
                *(uint4*)&kl[dst + j * 8] = kpl[j];
            }
        }
        // V tile: transposed scatter (fp16)
        {
            const __half2* vph = (const __half2*)(Vfb + (size_t)slot * KK + half * 32);
#pragma unroll
            for (int jj = 0; jj < 16; jj++) {
                int dd = half * 32 + 2 * jj;
                __half2 pv = vph[jj];
                vs[dd * AST + ikey]       = __low2half(pv);
                vs[(dd + 1) * AST + ikey] = __high2half(pv);
            }
        }
        __syncthreads();

        // ---- S = Q K^T (bf16 3-term) ----
        float s[2][8][4];
#pragma unroll
        for (int m = 0; m < 2; m++)
#pragma unroll
            for (int nt = 0; nt < 8; nt++)
#pragma unroll
                for (int c = 0; c < 4; c++) s[m][nt][c] = 0.f;

#pragma unroll
        for (int ks = 0; ks < 4; ks++) {
            const int kk = ks * 16 + 2 * tg;
#pragma unroll
            for (int nt = 0; nt < 8; nt++) {
                const int rr = (nt * 8 + g) * AST + kk;
                uint32_t bh0 = *(const uint32_t*)&kh[rr];
                uint32_t bh1 = *(const uint32_t*)&kh[rr + 8];
                uint32_t bl0 = *(const uint32_t*)&kl[rr];
                uint32_t bl1 = *(const uint32_t*)&kl[rr + 8];
#pragma unroll
                for (int m = 0; m < 2; m++) {
                    mma_bf16(s[m][nt], qh_[m][ks][0], qh_[m][ks][1], qh_[m][ks][2], qh_[m][ks][3], bh0, bh1);
                    mma_bf16(s[m][nt], qh_[m][ks][0], qh_[m][ks][1], qh_[m][ks][2], qh_[m][ks][3], bl0, bl1);
                    mma_bf16(s[m][nt], ql_[m][ks][0], ql_[m][ks][1], ql_[m][ks][2], ql_[m][ks][3], bh0, bh1);
                }
            }
        }

        // ---- tail masking ----
        if (kt * 64 + 64 > nvb) {
#pragma unroll
            for (int nt = 0; nt < 8; nt++) {
                int c0 = kt * 64 + nt * 8 + 2 * tg;
                if (c0 >= nvb) {
                    s[0][nt][0] = s[0][nt][2] = -1e30f;
                    s[1][nt][0] = s[1][nt][2] = -1e30f;
                }
                if (c0 + 1 >= nvb) {
                    s[0][nt][1] = s[0][nt][3] = -1e30f;
                    s[1][nt][1] = s[1][nt][3] = -1e30f;
                }
            }
        }

        // ---- online softmax ----
#pragma unroll
        for (int m = 0; m < 2; m++) {
#pragma unroll
            for (int r2 = 0; r2 < 2; r2++) {
                const int c0 = r2 * 2;
                float tmax = -1e30f;
#pragma unroll
                for (int nt = 0; nt < 8; nt++) {
                    tmax = fmaxf(tmax, s[m][nt][c0]);
                    tmax = fmaxf(tmax, s[m][nt][c0 + 1]);
                }
                tmax = fmaxf(tmax, __shfl_xor_sync(0xffffffffu, tmax, 1));
                tmax = fmaxf(tmax, __shfl_xor_sync(0xffffffffu, tmax, 2));
                float mn = fmaxf(mr[m][r2], tmax);
                float sc = __expf(mr[m][r2] - mn);
                mr[m][r2] = mn;
                float ts = 0.f;
#pragma unroll
                for (int nt = 0; nt < 8; nt++) {
                    float p0 = __expf(s[m][nt][c0]     - mn);
                    float p1 = __expf(s[m][nt][c0 + 1] - mn);
                    s[m][nt][c0]     = p0;
                    s[m][nt][c0 + 1] = p1;
                    ts += p0 + p1;
                }
                ts += __shfl_xor_sync(0xffffffffu, ts, 1);
                ts += __shfl_xor_sync(0xffffffffu, ts, 2);
                lr[m][r2] = lr[m][r2] * sc + ts;
#pragma unroll
                for (int nt = 0; nt < 8; nt++) {
                    o[m][nt][c0]     *= sc;
                    o[m][nt][c0 + 1] *= sc;
                }
            }
        }

        // ---- O += P V (single fp16 MMA) ----
#pragma unroll
        for (int ks = 0; ks < 4; ks++) {
            uint32_t ph[2][4];
#pragma unroll
            for (int m = 0; m < 2; m++) {
                ph[m][0] = pack_h2(make_float2(s[m][2*ks][0],   s[m][2*ks][1]));
                ph[m][1] = pack_h2(make_float2(s[m][2*ks][2],   s[m][2*ks][3]));
                ph[m][2] = pack_h2(make_float2(s[m][2*ks+1][0], s[m][2*ks+1][1]));
                ph[m][3] = pack_h2(make_float2(s[m][2*ks+1][2], s[m][2*ks+1][3]));
            }
            const int kk = ks * 16 + 2 * tg;
#pragma unroll
            for (int nt = 0; nt < 8; nt++) {
                const int rr = (nt * 8 + g) * AST + kk;
                uint32_t v0 = *(const uint32_t*)&vs[rr];
                uint32_t v1 = *(const uint32_t*)&vs[rr + 8];
#pragma unroll
                for (int m = 0; m < 2; m++)
                    mma_f16f32(o[m][nt], ph[m][0], ph[m][1], ph[m][2], ph[m][3], v0, v1);
            }
        }
    }

    // ---- epilogue: normalize, emit fp16 ----
#pragma unroll
    for (int m = 0; m < 2; m++) {
#pragma unroll
        for (int r2 = 0; r2 < 2; r2++) {
            float inv = 1.f / lr[m][r2];
            int row = q0 + w * 32 + m * 16 + g + r2 * 8;
            size_t off = (size_t)(b * TT + row) * KK + h * SS;
#pragma unroll
            for (int nt = 0; nt < 8; nt++) {
                *(uint32_t*)&ysf[off + nt * 8 + 2 * tg] =
                    pack_h2(make_float2(o[m][nt][r2*2] * inv, o[m][nt][r2*2+1] * inv));
            }
        }
    }
}

// ============================================================================
// launch
// ============================================================================
extern "C" void kernel_launch(void* const* d_in, const int* in_sizes, int n_in,
                              void* d_out, int out_size)
{
    const float* x    = (const float*)d_in[0];
    const int*   mask = (const int*)  d_in[1];
    const float* Wk   = (const float*)d_in[2];
    const float* Wq   = (const float*)d_in[3];
    const float* Wv   = (const float*)d_in[4];
    const float* Wu   = (const float*)d_in[5];
    const float* bu   = (const float*)d_in[6];
    float* out = (float*)d_out;

    __nv_bfloat16 *xh, *xl, *xgh, *xgl, *Wqh, *Wql, *Wkh, *Wkl, *Qh, *Ql, *Kh, *Kl;
    __half *xgf, *Wvf, *Wuf, *Vf, *ysf;
    int *idx, *nv;
    cudaGetSymbolAddress((void**)&xh,  g_xh);  cudaGetSymbolAddress((void**)&xl,  g_xl);
    cudaGetSymbolAddress((void**)&xgh, g_xgh); cudaGetSymbolAddress((void**)&xgl, g_xgl);
    cudaGetSymbolAddress((void**)&xgf, g_xgf);
    cudaGetSymbolAddress((void**)&Wqh, g_Wqh); cudaGetSymbolAddress((void**)&Wql, g_Wql);
    cudaGetSymbolAddress((void**)&Wkh, g_Wkh); cudaGetSymbolAddress((void**)&Wkl, g_Wkl);
    cudaGetSymbolAddress((void**)&Qh,  g_Qh);  cudaGetSymbolAddress((void**)&Ql,  g_Ql);
    cudaGetSymbolAddress((void**)&Kh,  g_Kh);  cudaGetSymbolAddress((void**)&Kl,  g_Kl);
    cudaGetSymbolAddress((void**)&Wvf, g_Wvf); cudaGetSymbolAddress((void**)&Wuf, g_Wuf);
    cudaGetSymbolAddress((void**)&Vf,  g_Vf);  cudaGetSymbolAddress((void**)&ysf, g_ysf);
    cudaGetSymbolAddress((void**)&idx, g_idx); cudaGetSymbolAddress((void**)&nv,  g_nv);

    cudaFuncSetAttribute(gemm3_kernel,
                         cudaFuncAttributeMaxDynamicSharedMemorySize, G3SMEM);
    cudaFuncSetAttribute(gemm1_kernel,
                         cudaFuncAttributeMaxDynamicSharedMemorySize, G1SMEM);

    // preprocessing (compact must precede gather)
    compact_kernel<<<BB, 1024>>>(mask, idx, nv);
    prep_x_kernel<<<MROWS * KK / 2 / 256, 256>>>(x, xh, xl);
    prep_w_kernel<<<dim3(KK * KK / 2 / 256, 4), 256>>>(Wq, Wk, Wv, Wu,
                                                       Wqh, Wql, Wkh, Wkl, Wvf, Wuf);
    gather_kernel<<<MROWS * KK / 2 / 256, 256>>>(x, idx, nv, xgh, xgl, xgf);

    dim3 gg(KK / 128, MROWS / 128);   // (8, 32)
    gemm3_kernel<<<gg, 256, G3SMEM>>>(xh,  xl,  Wqh, Wql, Qh, Ql, nullptr, MROWS, KK);
    gemm3_kernel<<<gg, 256, G3SMEM>>>(xgh, xgl, Wkh, Wkl, Kh, Kl, nv,      MROWS, KK);
    gemm1_kernel<<<gg, 256, G1SMEM>>>(xgf, Wvf, nullptr, nullptr, Vf, nv,  MROWS, KK);

    dim3 ga(TT / 128, HH, BB);        // (16, 16, 2)
    attn_tc_kernel<<<ga, 128>>>(Qh, Ql, Kh, Kl, Vf, nv, ysf);

    gemm1_kernel<<<gg, 256, G1SMEM>>>(ysf, Wuf, bu, out, nullptr, nullptr, MROWS, KK);
}

// round 11
// speedup vs baseline: 2.4186x; 1.1645x over previous
#include <cuda_runtime.h>
#include <cuda_bf16.h>
#include <cuda_fp16.h>
#include <cstdint>

#define BB   2
#define TT   2048
#define KK   1024
#define HH   16
#define SS   64
#define MROWS (BB*TT)   // 4096
#define INV2048 4.8828125e-4f

// ---- scratch (static device globals; no allocation allowed) ----
__device__ float         g_xg [MROWS*KK];                      // gathered x fp32 (K GEMM)
__device__ __half        g_xgf[MROWS*KK];                      // gathered x fp16 (V GEMM)
__device__ __nv_bfloat16 g_Qh[MROWS*KK], g_Ql[MROWS*KK];
__device__ __nv_bfloat16 g_Kh[MROWS*KK], g_Kl[MROWS*KK];      // compacted K
__device__ __half g_Wvf[KK*KK];
__device__ __half g_Wuf[KK*KK];
__device__ __half g_Vf [MROWS*KK];                             // compacted V
__device__ __half g_ysf[MROWS*KK];
__device__ int g_idx[BB*TT];
__device__ int g_nv [BB];

// ============================================================================
// helpers
// ============================================================================
__device__ __forceinline__ uint32_t smem_u32(const void* p) {
    uint32_t a;
    asm("{ .reg .u64 t; cvta.to.shared.u64 t, %1; cvt.u32.u64 %0, t; }"
        : "=r"(a) : "l"(p));
    return a;
}

__device__ __forceinline__ void mma_bf16(float d[4],
                                         uint32_t a0, uint32_t a1, uint32_t a2, uint32_t a3,
                                         uint32_t b0, uint32_t b1) {
    asm volatile(
        "mma.sync.aligned.m16n8k16.row.col.f32.bf16.bf16.f32 "
        "{%0,%1,%2,%3}, {%4,%5,%6,%7}, {%8,%9}, {%0,%1,%2,%3};"
        : "+f"(d[0]), "+f"(d[1]), "+f"(d[2]), "+f"(d[3])
        : "r"(a0), "r"(a1), "r"(a2), "r"(a3), "r"(b0), "r"(b1));
}

__device__ __forceinline__ void mma_f16f32(float d[4],
                                           uint32_t a0, uint32_t a1, uint32_t a2, uint32_t a3,
                                           uint32_t b0, uint32_t b1) {
    asm volatile(
        "mma.sync.aligned.m16n8k16.row.col.f32.f16.f16.f32 "
        "{%0,%1,%2,%3}, {%4,%5,%6,%7}, {%8,%9}, {%0,%1,%2,%3};"
        : "+f"(d[0]), "+f"(d[1]), "+f"(d[2]), "+f"(d[3])
        : "r"(a0), "r"(a1), "r"(a2), "r"(a3), "r"(b0), "r"(b1));
}

#define LDSM4(r0, r1, r2, r3, addr) \
    asm volatile("ldmatrix.sync.aligned.m8n8.x4.shared.b16 {%0,%1,%2,%3}, [%4];" \
                 : "=r"(r0), "=r"(r1), "=r"(r2), "=r"(r3) : "r"(addr))

__device__ __forceinline__ void split2(float2 f, uint32_t& h, uint32_t& l) {
    __nv_bfloat162 hh = __float22bfloat162_rn(f);
    float2 hf = __bfloat1622float2(hh);
    __nv_bfloat162 ll = __float22bfloat162_rn(make_float2(f.x - hf.x, f.y - hf.y));
    h = *(uint32_t*)&hh;
    l = *(uint32_t*)&ll;
}

// fp16 split, lo digit pre-scaled by 2048
__device__ __forceinline__ void split2h(float2 f, uint32_t& h, uint32_t& l) {
    __half2 hh = __float22half2_rn(f);
    float2 hf = __half22float2(hh);
    __half2 ll = __float22half2_rn(make_float2((f.x - hf.x) * 2048.f,
                                               (f.y - hf.y) * 2048.f));
    h = *(uint32_t*)&hh;
    l = *(uint32_t*)&ll;
}

__device__ __forceinline__ uint32_t pack_h2(float2 f) {
    __half2 hh = __float22half2_rn(f);
    return *(uint32_t*)&hh;
}

// ============================================================================
// mask compaction (proven)
// ============================================================================
__global__ __launch_bounds__(1024)
void compact_kernel(const int* __restrict__ mask, int* __restrict__ idx,
                    int* __restrict__ nv)
{
    __shared__ int s[1024];
    const int b = blockIdx.x;
    const int t = threadIdx.x;
    const int m0 = mask[b * TT + 2 * t];
    const int m1 = mask[b * TT + 2 * t + 1];
    const int c  = m0 + m1;
    s[t] = c;
    __syncthreads();
    for (int off = 1; off < 1024; off <<= 1) {
        int v = s[t];
        int u = (t >= off) ? s[t - off] : 0;
        __syncthreads();
        s[t] = v + u;
        __syncthreads();
    }
    const int incl = s[t];
    const int excl = incl - c;
    if (m0) idx[b * TT + excl] = 2 * t;
    if (m1) idx[b * TT + excl + m0] = 2 * t + 1;
    if (t == 1023) nv[b] = incl;
}

// gather valid x rows: fp32 copy (K GEMM) + fp16 (V GEMM)
__global__ __launch_bounds__(256)
void gather_kernel(const float* __restrict__ x,
                   const int* __restrict__ idx,
                   const int* __restrict__ nv,
                   float* __restrict__ xg,
                   __half* __restrict__ xgf)
{
    int i = blockIdx.x * 256 + threadIdx.x;           // over MROWS*KK/2 float2
    int slot = i >> 9;
    int c2   = i & 511;
    int b    = slot / TT;
    int s    = slot - b * TT;
    int r    = (s < nv[b]) ? idx[b * TT + s] : idx[b * TT];
    float2 f = ((const float2*)(x + (size_t)(b * TT + r) * KK))[c2];
    ((float2*)(xg + (size_t)slot * KK))[c2] = f;
    ((uint32_t*)(xgf + (size_t)slot * KK))[c2] = pack_h2(f);
}

// Wv, Wu -> fp16
__global__ __launch_bounds__(256)
void prep_w_kernel(const float* __restrict__ Wv, const float* __restrict__ Wu,
                   __half* __restrict__ Wvf, __half* __restrict__ Wuf)
{
    int i = blockIdx.x * 256 + threadIdx.x;
    if (blockIdx.y == 0) ((uint32_t*)Wvf)[i] = pack_h2(((const float2*)Wv)[i]);
    else                 ((uint32_t*)Wuf)[i] = pack_h2(((const float2*)Wu)[i]);
}

// ============================================================================
// common GEMM geometry
// ============================================================================
#define GBK 32
#define NIT (KK / GBK)          // 32
#define BKP 40
#define ATILE (128 * BKP)

// ============================================================================
// gemm2: Q projection. fp32 inputs inline-converted.
// A = x as fp16 2-digit (hi + lo*2048), B = Wq single fp16.
// C = f32acc(Ah B) + f32acc(Al B)/2048, output split-bf16.
// ============================================================================
#define G2SMEM (6 * ATILE * 2)   // 61440 B

__global__ void __launch_bounds__(256)
gemm2_kernel(const float* __restrict__ Ag,
             const float* __restrict__ Bg,
             __nv_bfloat16* __restrict__ Ch,
             __nv_bfloat16* __restrict__ Cl,
             int M, int N)
{
    extern __shared__ __half sm2[];
    const uint32_t sbase = smem_u32(sm2);

    const int tid  = threadIdx.x;
    const int lane = tid & 31;
    const int wid  = tid >> 5;
    const int g    = lane >> 2;
    const int tg   = lane & 3;
    const int wm   = wid & 1;
    const int wn   = wid >> 1;
    const int m0   = blockIdx.y * 128;
    const int n0   = blockIdx.x * 128;

    const float* Agp = Ag + (size_t)m0 * KK;
    const float* Bgp = Bg + (size_t)n0 * KK;

    const uint32_t aoff = (uint32_t)((wm * 64 + (lane & 15)) * BKP + ((lane & 16) ? 8 : 0));
    const uint32_t boff = (uint32_t)((wn * 32 + (lane & 7) + ((lane & 16) ? 8 : 0)) * BKP
                                     + ((lane & 8) ? 8 : 0));

    // loader: idx = j*256+tid over 1024 float4; row = idx>>3, c4 = idx&7
    float4 ra[4], rb[4];
#define G2LOAD(k0) do { \
    _Pragma("unroll") \
    for (int j = 0; j < 4; j++) { \
        int idx = j * 256 + tid; int row = idx >> 3; int c4 = idx & 7; \
        ra[j] = *(const float4*)(Agp + (size_t)row * KK + (k0) + c4 * 4); \
        rb[j] = *(const float4*)(Bgp + (size_t)row * KK + (k0) + c4 * 4); \
    } } while (0)

#define G2STORE(bsel) do { \
    _Pragma("unroll") \
    for (int j = 0; j < 4; j++) { \
        int idx = j * 256 + tid; int row = idx >> 3; int c4 = idx & 7; \
        uint32_t off = (uint32_t)((bsel) * 3 * ATILE + row * BKP + c4 * 4) * 2; \
        uint32_t h0, l0, h1, l1; \
        split2h(make_float2(ra[j].x, ra[j].y), h0, l0); \
        split2h(make_float2(ra[j].z, ra[j].w), h1, l1); \
        *(uint32_t*)((char*)sm2 + off)                  = h0; \
        *(uint32_t*)((char*)sm2 + off + 4)              = h1; \
        *(uint32_t*)((char*)sm2 + off + ATILE * 2)      = l0; \
        *(uint32_t*)((char*)sm2 + off + ATILE * 2 + 4)  = l1; \
        *(uint32_t*)((char*)sm2 + off + 2 * ATILE * 2)     = pack_h2(make_float2(rb[j].x, rb[j].y)); \
        *(uint32_t*)((char*)sm2 + off + 2 * ATILE * 2 + 4) = pack_h2(make_float2(rb[j].z, rb[j].w)); \
    } } while (0)

    float acc [4][4][4];
    float acc2[4][4][4];
#pragma unroll
    for (int i = 0; i < 4; i++)
#pragma unroll
        for (int j = 0; j < 4; j++)
#pragma unroll
            for (int r = 0; r < 4; r++) { acc[i][j][r] = 0.f; acc2[i][j][r] = 0.f; }

    G2LOAD(0);
    G2STORE(0);
    __syncthreads();

    for (int it = 0; it < NIT; it++) {
        const int buf = it & 1;
        if (it + 1 < NIT) G2LOAD((it + 1) * GBK);

        const uint32_t bb = sbase + (uint32_t)(buf * 3 * ATILE) * 2;
#pragma unroll
        for (int ks = 0; ks < 2; ks++) {
            const uint32_t ko = ks * 32;
            uint32_t bf[4][2];
            LDSM4(bf[0][0], bf[0][1], bf[1][0], bf[1][1],
                  bb + 2 * ATILE * 2 + boff * 2 + ko);
            LDSM4(bf[2][0], bf[2][1], bf[3][0], bf[3][1],
                  bb + 2 * ATILE * 2 + (boff + 16 * BKP) * 2 + ko);
#pragma unroll
            for (int mf = 0; mf < 4; mf++) {
                uint32_t ah0, ah1, ah2, ah3, al0, al1, al2, al3;
                LDSM4(ah0, ah1, ah2, ah3, bb + (aoff + mf * 16 * BKP) * 2 + ko);
                LDSM4(al0, al1, al2, al3, bb + ATILE * 2 + (aoff + mf * 16 * BKP) * 2 + ko);
#pragma unroll
                for (int nf = 0; nf < 4; nf++) {
                    mma_f16f32(acc [mf][nf], ah0, ah1, ah2, ah3, bf[nf][0], bf[nf][1]);
                    mma_f16f32(acc2[mf][nf], al0, al1, al2, al3, bf[nf][0], bf[nf][1]);
                }
            }
        }

        if (it + 1 < NIT) {
            __syncthreads();
            G2STORE(buf ^ 1);
            __syncthreads();
        }
    }
#undef G2LOAD
#undef G2STORE

#pragma unroll
    for (int mf = 0; mf < 4; mf++) {
        int r0 = m0 + wm * 64 + mf * 16 + g;
#pragma unroll
        for (int nf = 0; nf < 4; nf++) {
            int col = n0 + wn * 32 + nf * 8 + tg * 2;
            float v00 = acc[mf][nf][0] + acc2[mf][nf][0] * INV2048;
            float v01 = acc[mf][nf][1] + acc2[mf][nf][1] * INV2048;
            float v10 = acc[mf][nf][2] + acc2[mf][nf][2] * INV2048;
            float v11 = acc[mf][nf][3] + acc2[mf][nf][3] * INV2048;
            uint32_t h0, l0, h1, l1;
            split2(make_float2(v00, v01), h0, l0);
            split2(make_float2(v10, v11), h1, l1);
            *(uint32_t*)&Ch[(size_t)r0 * N + col]       = h0;
            *(uint32_t*)&Cl[(size_t)r0 * N + col]       = l0;
            *(uint32_t*)&Ch[(size_t)(r0 + 8) * N + col] = h1;
            *(uint32_t*)&Cl[(size_t)(r0 + 8) * N + col] = l1;
        }
    }
}

// ============================================================================
// gemm3: K projection. fp32 inputs, inline 3-term split-bf16, early exit.
// ============================================================================
#define G3SMEM (8 * ATILE * 2)   // 81920 B

__global__ void __launch_bounds__(256)
gemm3_kernel(const float* __restrict__ Ag,
             const float* __restrict__ Bg,
             __nv_bfloat16* __restrict__ Ch,
             __nv_bfloat16* __restrict__ Cl,
             const int* __restrict__ nvp,
             int M, int N)
{
    const int m0 = blockIdx.y * 128;
    if (nvp) {
        int bb2 = m0 / TT;
        if ((m0 - bb2 * TT) >= nvp[bb2]) return;
    }

    extern __shared__ __nv_bfloat16 sm3[];
    const uint32_t sbase = smem_u32(sm3);

    const int tid  = threadIdx.x;
    const int lane = tid & 31;
    const int wid  = tid >> 5;
    const int g    = lane >> 2;
    const int tg   = lane & 3;
    const int wm   = wid & 1;
    const int wn   = wid >> 1;
    const int n0   = blockIdx.x * 128;

    const float* Agp = Ag + (size_t)m0 * KK;
    const float* Bgp = Bg + (size_t)n0 * KK;

    const uint32_t aoff = (uint32_t)((wm * 64 + (lane & 15)) * BKP + ((lane & 16) ? 8 : 0));
    const uint32_t boff = (uint32_t)((wn * 32 + (lane & 7) + ((lane & 16) ? 8 : 0)) * BKP
                                     + ((lane & 8) ? 8 : 0));

    float4 ra[4], rb[4];
#define G3LOAD(k0) do { \
    _Pragma("unroll") \
    for (int j = 0; j < 4; j++) { \
        int idx = j * 256 + tid; int row = idx >> 3; int c4 = idx & 7; \
        ra[j] = *(const float4*)(Agp + (size_t)row * KK + (k0) + c4 * 4); \
        rb[j] = *(const float4*)(Bgp + (size_t)row * KK + (k0) + c4 * 4); \
    } } while (0)

#define G3STORE(bsel) do { \
    _Pragma("unroll") \
    for (int j = 0; j < 4; j++) { \
        int idx = j * 256 + tid; int row = idx >> 3; int c4 = idx & 7; \
        uint32_t off = (uint32_t)((bsel) * 4 * ATILE + row * BKP + c4 * 4) * 2; \
        uint32_t h0, l0, h1, l1; \
        split2(make_float2(ra[j].x, ra[j].y), h0, l0); \
        split2(make_float2(ra[j].z, ra[j].w), h1, l1); \
        *(uint32_t*)((char*)sm3 + off)                 = h0; \
        *(uint32_t*)((char*)sm3 + off + 4)             = h1; \
        *(uint32_t*)((char*)sm3 + off + ATILE * 2)     = l0; \
        *(uint32_t*)((char*)sm3 + off + ATILE * 2 + 4) = l1; \
        split2(make_float2(rb[j].x, rb[j].y), h0, l0); \
        split2(make_float2(rb[j].z, rb[j].w), h1, l1); \
        *(uint32_t*)((char*)sm3 + off + 2 * ATILE * 2)     = h0; \
        *(uint32_t*)((char*)sm3 + off + 2 * ATILE * 2 + 4) = h1; \
        *(uint32_t*)((char*)sm3 + off + 3 * ATILE * 2)     = l0; \
        *(uint32_t*)((char*)sm3 + off + 3 * ATILE * 2 + 4) = l1; \
    } } while (0)

    float acc[4][4][4];
#pragma unroll
    for (int i = 0; i < 4; i++)
#pragma unroll
        for (int j = 0; j < 4; j++)
#pragma unroll
            for (int r = 0; r < 4; r++) acc[i][j][r] = 0.f;

    G3LOAD(0);
    G3STORE(0);
    __syncthreads();

    for (int it = 0; it < NIT; it++) {
        const int buf = it & 1;
        if (it + 1 < NIT) G3LOAD((it + 1) * GBK);

        const uint32_t bb = sbase + (uint32_t)(buf * 4 * ATILE) * 2;
#pragma unroll
        for (int ks = 0; ks < 2; ks++) {
            const uint32_t ko = ks * 32;
            uint32_t bh[4][2], bl[4][2];
            LDSM4(bh[0][0], bh[0][1], bh[1][0], bh[1][1],
                  bb + 2 * ATILE * 2 + boff * 2 + ko);
            LDSM4(bh[2][0], bh[2][1], bh[3][0], bh[3][1],
                  bb + 2 * ATILE * 2 + (boff + 16 * BKP) * 2 + ko);
            LDSM4(bl[0][0], bl[0][1], bl[1][0], bl[1][1],
                  bb + 3 * ATILE * 2 + boff * 2 + ko);
            LDSM4(bl[2][0], bl[2][1], bl[3][0], bl[3][1],
                  bb + 3 * ATILE * 2 + (boff + 16 * BKP) * 2 + ko);
#pragma unroll
            for (int mf = 0; mf < 4; mf++) {
                uint32_t ah0, ah1, ah2, ah3, al0, al1, al2, al3;
                LDSM4(ah0, ah1, ah2, ah3, bb + (aoff + mf * 16 * BKP) * 2 + ko);
                LDSM4(al0, al1, al2, al3, bb + ATILE * 2 + (aoff + mf * 16 * BKP) * 2 + ko);
#pragma unroll
                for (int nf = 0; nf < 4; nf++) {
                    mma_bf16(acc[mf][nf], ah0, ah1, ah2, ah3, bh[nf][0], bh[nf][1]);
                    mma_bf16(acc[mf][nf], ah0, ah1, ah2, ah3, bl[nf][0], bl[nf][1]);
                    mma_bf16(acc[mf][nf], al0, al1, al2, al3, bh[nf][0], bh[nf][1]);
                }
            }
        }

        if (it + 1 < NIT) {
            __syncthreads();
            G3STORE(buf ^ 1);
            __syncthreads();
        }
    }
#undef G3LOAD
#undef G3STORE

#pragma unroll
    for (int mf = 0; mf < 4; mf++) {
        int r0 = m0 + wm * 64 + mf * 16 + g;
#pragma unroll
        for (int nf = 0; nf < 4; nf++) {
            int col = n0 + wn * 32 + nf * 8 + tg * 2;
            uint32_t h0, l0, h1, l1;
            split2(make_float2(acc[mf][nf][0], acc[mf][nf][1]), h0, l0);
            split2(make_float2(acc[mf][nf][2], acc[mf][nf][3]), h1, l1);
            *(uint32_t*)&Ch[(size_t)r0 * N + col]       = h0;
            *(uint32_t*)&Cl[(size_t)r0 * N + col]       = l0;
            *(uint32_t*)&Ch[(size_t)(r0 + 8) * N + col] = h1;
            *(uint32_t*)&Cl[(size_t)(r0 + 8) * N + col] = l1;
        }
    }
}

// ============================================================================
// gemm1: 1-term fp16 (V projection, output projection). cp.async path.
// ============================================================================
#define G1SMEM (4 * ATILE * 2)   // 40960 B

__global__ void __launch_bounds__(256)
gemm1_kernel(const __half* __restrict__ Ag,
             const __half* __restrict__ Bg,
             const float* __restrict__ bias,
             float* __restrict__ Cf,
             __half* __restrict__ Chf,
             const int* __restrict__ nvp,
             int M, int N)
{
    const int m0 = blockIdx.y * 128;
    if (nvp) {
        int bb2 = m0 / TT;
        if ((m0 - bb2 * TT) >= nvp[bb2]) return;
    }

    extern __shared__ __half sm1[];
    const uint32_t sbase = smem_u32(sm1);

    const int tid  = threadIdx.x;
    const int lane = tid & 31;
    const int wid  = tid >> 5;
    const int g    = lane >> 2;
    const int tg   = lane & 3;
    const int wm   = wid & 1;
    const int wn   = wid >> 1;
    const int n0   = blockIdx.x * 128;

    const __half* gsrc[2] = { Ag + (size_t)m0 * KK, Bg + (size_t)n0 * KK };

    const uint32_t aoff = (uint32_t)((wm * 64 + (lane & 15)) * BKP + ((lane & 16) ? 8 : 0));
    const uint32_t boff = (uint32_t)((wn * 32 + (lane & 7) + ((lane & 16) ? 8 : 0)) * BKP
                                     + ((lane & 8) ? 8 : 0));

#define G1ISSUE(k0, bsel) do { \
    _Pragma("unroll") \
    for (int a = 0; a < 2; a++) { \
        uint32_t sd = sbase + (uint32_t)(((bsel) * 2 + a) * ATILE) * 2; \
        _Pragma("unroll") \
        for (int j = 0; j < 2; j++) { \
            int row = j * 64 + (tid >> 2); int cc = tid & 3; \
            uint32_t s = sd + (uint32_t)(row * BKP + cc * 8) * 2; \
            const __half* gp = gsrc[a] + (size_t)row * KK + (k0) + cc * 8; \
            asm volatile("cp.async.cg.shared.global [%0], [%1], 16;" :: "r"(s), "l"(gp)); \
        } \
    } \
    asm volatile("cp.async.commit_group;"); \
} while (0)

    float acc[4][4][4];
#pragma unroll
    for (int i = 0; i < 4; i++)
#pragma unroll
        for (int j = 0; j < 4; j++)
#pragma unroll
            for (int r = 0; r < 4; r++) acc[i][j][r] = 0.f;

    G1ISSUE(0, 0);

    for (int it = 0; it < NIT; it++) {
        const int buf = it & 1;
        asm volatile("cp.async.wait_group 0;");
        __syncthreads();
        if (it + 1 < NIT) G1ISSUE((it + 1) * GBK, buf ^ 1);

        const uint32_t bb = sbase + (uint32_t)(buf * 2 * ATILE) * 2;
#pragma unroll
        for (int ks = 0; ks < 2; ks++) {
            const uint32_t ko = ks * 32;
            uint32_t bf[4][2];
            LDSM4(bf[0][0], bf[0][1], bf[1][0], bf[1][1],
                  bb + ATILE * 2 + boff * 2 + ko);
            LDSM4(bf[2][0], bf[2][1], bf[3][0], bf[3][1],
                  bb + ATILE * 2 + (boff + 16 * BKP) * 2 + ko);
#pragma unroll
            for (int mf = 0; mf < 4; mf++) {
                uint32_t a0, a1, a2, a3;
                LDSM4(a0, a1, a2, a3, bb + (aoff + mf * 16 * BKP) * 2 + ko);
#pragma unroll
                for (int nf = 0; nf < 4; nf++)
                    mma_f16f32(acc[mf][nf], a0, a1, a2, a3, bf[nf][0], bf[nf][1]);
            }
        }
    }
#undef G1ISSUE

#pragma unroll
    for (int mf = 0; mf < 4; mf++) {
        int r0 = m0 + wm * 64 + mf * 16 + g;
#pragma unroll
        for (int nf = 0; nf < 4; nf++) {
            int col = n0 + wn * 32 + nf * 8 + tg * 2;
            if (Cf) {
                float b0 = 0.f, b1 = 0.f;
                if (bias) { b0 = __ldg(&bias[col]); b1 = __ldg(&bias[col + 1]); }
                float2 o0 = { acc[mf][nf][0] + b0, acc[mf][nf][1] + b1 };
                float2 o1 = { acc[mf][nf][2] + b0, acc[mf][nf][3] + b1 };
                *(float2*)&Cf[(size_t)r0 * N + col]       = o0;
                *(float2*)&Cf[(size_t)(r0 + 8) * N + col] = o1;
            } else {
                *(uint32_t*)&Chf[(size_t)r0 * N + col] =
                    pack_h2(make_float2(acc[mf][nf][0], acc[mf][nf][1]));
                *(uint32_t*)&Chf[(size_t)(r0 + 8) * N + col] =
                    pack_h2(make_float2(acc[mf][nf][2], acc[mf][nf][3]));
            }
        }
    }
}

// ============================================================================
// Flash attention over compacted K/V (proven round-10 body).
// ============================================================================
#define AST 72

__global__ __launch_bounds__(128, 2)
void attn_tc_kernel(const __nv_bfloat16* __restrict__ Qh_,
                    const __nv_bfloat16* __restrict__ Ql_,
                    const __nv_bfloat16* __restrict__ Kh_,
                    const __nv_bfloat16* __restrict__ Kl_,
                    const __half* __restrict__ Vf_,
                    const int* __restrict__ nvp,
                    __half* __restrict__ ysf)
{
    __shared__ __nv_bfloat16 kh[64 * AST], kl[64 * AST];
    __shared__ __half vs[64 * AST];

    const int tid  = threadIdx.x;
    const int lane = tid & 31;
    const int w    = tid >> 5;
    const int g    = lane >> 2;
    const int tg   = lane & 3;
    const int b    = blockIdx.z;
    const int h    = blockIdx.y;
    const int q0   = blockIdx.x * 128;

    const int nvb    = nvp[b];
    const int ntiles = (nvb + 63) >> 6;

    const __nv_bfloat16* Qhb = Qh_ + (size_t)(b * TT + q0 + w * 32) * KK + h * SS;
    const __nv_bfloat16* Qlb = Ql_ + (size_t)(b * TT + q0 + w * 32) * KK + h * SS;
    uint32_t qh_[2][4][4], ql_[2][4][4];
#pragma unroll
    for (int m = 0; m < 2; m++) {
#pragma unroll
        for (int ks = 0; ks < 4; ks++) {
            int r0 = m * 16 + g, r1 = r0 + 8;
            int d0 = ks * 16 + 2 * tg;
            qh_[m][ks][0] = *(const uint32_t*)(Qhb + (size_t)r0 * KK + d0);
            qh_[m][ks][1] = *(const uint32_t*)(Qhb + (size_t)r1 * KK + d0);
            qh_[m][ks][2] = *(const uint32_t*)(Qhb + (size_t)r0 * KK + d0 + 8);
            qh_[m][ks][3] = *(const uint32_t*)(Qhb + (size_t)r1 * KK + d0 + 8);
            ql_[m][ks][0] = *(const uint32_t*)(Qlb + (size_t)r0 * KK + d0);
            ql_[m][ks][1] = *(const uint32_t*)(Qlb + (size_t)r1 * KK + d0);
            ql_[m][ks][2] = *(const uint32_t*)(Qlb + (size_t)r0 * KK + d0 + 8);
            ql_[m][ks][3] = *(const uint32_t*)(Qlb + (size_t)r1 * KK + d0 + 8);
        }
    }

    float o[2][8][4];
#pragma unroll
    for (int m = 0; m < 2; m++)
#pragma unroll
        for (int nt = 0; nt < 8; nt++)
#pragma unroll
            for (int c = 0; c < 4; c++) o[m][nt][c] = 0.f;
    float mr[2][2] = { {-1e30f, -1e30f}, {-1e30f, -1e30f} };
    float lr[2][2] = { {0.f, 0.f}, {0.f, 0.f} };

    const __nv_bfloat16* Khb = Kh_ + (size_t)b * TT * KK + h * SS;
    const __nv_bfloat16* Klb = Kl_ + (size_t)b * TT * KK + h * SS;
    const __half*        Vfb = Vf_ + (size_t)b * TT * KK + h * SS;

    const int ikey = tid >> 1;
    const int half = tid & 1;

    for (int kt = 0; kt < ntiles; kt++) {
        __syncthreads();
        int slot = kt * 64 + ikey;
        {
            const uint4* kph = (const uint4*)(Khb + (size_t)slot * KK + half * 32);
            const uint4* kpl = (const uint4*)(Klb + (size_t)slot * KK + half * 32);
            int dst = ikey * AST + half * 32;
#pragma unroll
            for (int j = 0; j < 4; j++) {
                *(uint4*)&kh[dst + j * 8] = kph[j];
                *(uint4*)&kl[dst + j * 8] = kpl[j];
            }
        }
        {
            const __half2* vph = (const __half2*)(Vfb + (size_t)slot * KK + half * 32);
#pragma unroll
            for (int jj = 0; jj < 16; jj++) {
                int dd = half * 32 + 2 * jj;
                __half2 pv = vph[jj];
                vs[dd * AST + ikey]       = __low2half(pv);
                vs[(dd + 1) * AST + ikey] = __high2half(pv);
            }
        }
        __syncthreads();

        float s[2][8][4];
#pragma unroll
        for (int m = 0; m < 2; m++)
#pragma unroll
            for (int nt = 0; nt < 8; nt++)
#pragma unroll
                for (int c = 0; c < 4; c++) s[m][nt][c] = 0.f;

#pragma unroll
        for (int ks = 0; ks < 4; ks++) {
            const int kk = ks * 16 + 2 * tg;
#pragma unroll
            for (int nt = 0; nt < 8; nt++) {
                const int rr = (nt * 8 + g) * AST + kk;
                uint32_t bh0 = *(const uint32_t*)&kh[rr];
                uint32_t bh1 = *(const uint32_t*)&kh[rr + 8];
                uint32_t bl0 = *(const uint32_t*)&kl[rr];
                uint32_t bl1 = *(const uint32_t*)&kl[rr + 8];
#pragma unroll
                for (int m = 0; m < 2; m++) {
                    mma_bf16(s[m][nt], qh_[m][ks][0], qh_[m][ks][1], qh_[m][ks][2], qh_[m][ks][3], bh0, bh1);
                    mma_bf16(s[m][nt], qh_[m][ks][0], qh_[m][ks][1], qh_[m][ks][2], qh_[m][ks][3], bl0, bl1);
                    mma_bf16(s[m][nt], ql_[m][ks][0], ql_[m][ks][1], ql_[m][ks][2], ql_[m][ks][3], bh0, bh1);
                }
            }
        }

        if (kt * 64 + 64 > nvb) {
#pragma unroll
            for (int nt = 0; nt < 8; nt++) {
                int c0 = kt * 64 + nt * 8 + 2 * tg;
                if (c0 >= nvb) {
                    s[0][nt][0] = s[0][nt][2] = -1e30f;
                    s[1][nt][0] = s[1][nt][2] = -1e30f;
                }
                if (c0 + 1 >= nvb) {
                    s[0][nt][1] = s[0][nt][3] = -1e30f;
                    s[1][nt][1] = s[1][nt][3] = -1e30f;
                }
            }
        }

#pragma unroll
        for (int m = 0; m < 2; m++) {
#pragma unroll
            for (int r2 = 0; r2 < 2; r2++) {
                const int c0 = r2 * 2;
                float tmax = -1e30f;
#pragma unroll
                for (int nt = 0; nt < 8; nt++) {
                    tmax = fmaxf(tmax, s[m][nt][c0]);
                    tmax = fmaxf(tmax, s[m][nt][c0 + 1]);
                }
                tmax = fmaxf(tmax, __shfl_xor_sync(0xffffffffu, tmax, 1));
                tmax = fmaxf(tmax, __shfl_xor_sync(0xffffffffu, tmax, 2));
                float mn = fmaxf(mr[m][r2], tmax);
                float sc = __expf(mr[m][r2] - mn);
                mr[m][r2] = mn;
                float ts = 0.f;
#pragma unroll
                for (int nt = 0; nt < 8; nt++) {
                    float p0 = __expf(s[m][nt][c0]     - mn);
                    float p1 = __expf(s[m][nt][c0 + 1] - mn);
                    s[m][nt][c0]     = p0;
                    s[m][nt][c0 + 1] = p1;
                    ts += p0 + p1;
                }
                ts += __shfl_xor_sync(0xffffffffu, ts, 1);
                ts += __shfl_xor_sync(0xffffffffu, ts, 2);
                lr[m][r2] = lr[m][r2] * sc + ts;
#pragma unroll
                for (int nt = 0; nt < 8; nt++) {
                    o[m][nt][c0]     *= sc;
                    o[m][nt][c0 + 1] *= sc;
                }
            }
        }

#pragma unroll
        for (int ks = 0; ks < 4; ks++) {
            uint32_t ph[2][4];
#pragma unroll
            for (int m = 0; m < 2; m++) {
                ph[m][0] = pack_h2(make_float2(s[m][2*ks][0],   s[m][2*ks][1]));
                ph[m][1] = pack_h2(make_float2(s[m][2*ks][2],   s[m][2*ks][3]));
                ph[m][2] = pack_h2(make_float2(s[m][2*ks+1][0], s[m][2*ks+1][1]));
                ph[m][3] = pack_h2(make_float2(s[m][2*ks+1][2], s[m][2*ks+1][3]));
            }
            const int kk = ks * 16 + 2 * tg;
#pragma unroll
            for (int nt = 0; nt < 8; nt++) {
                const int rr = (nt * 8 + g) * AST + kk;
                uint32_t v0 = *(const uint32_t*)&vs[rr];
                uint32_t v1 = *(const uint32_t*)&vs[rr + 8];
#pragma unroll
                for (int m = 0; m < 2; m++)
                    mma_f16f32(o[m][nt], ph[m][0], ph[m][1], ph[m][2], ph[m][3], v0, v1);
            }
        }
    }

#pragma unroll
    for (int m = 0; m < 2; m++) {
#pragma unroll
        for (int r2 = 0; r2 < 2; r2++) {
            float inv = 1.f / lr[m][r2];
            int row = q0 + w * 32 + m * 16 + g + r2 * 8;
            size_t off = (size_t)(b * TT + row) * KK + h * SS;
#pragma unroll
            for (int nt = 0; nt < 8; nt++) {
                *(uint32_t*)&ysf[off + nt * 8 + 2 * tg] =
                    pack_h2(make_float2(o[m][nt][r2*2] * inv, o[m][nt][r2*2+1] * inv));
            }
        }
    }
}

// ============================================================================
// launch
// ============================================================================
extern "C" void kernel_launch(void* const* d_in, const int* in_sizes, int n_in,
                              void* d_out, int out_size)
{
    const float* x    = (const float*)d_in[0];
    const int*   mask = (const int*)  d_in[1];
    const float* Wk   = (const float*)d_in[2];
    const float* Wq   = (const float*)d_in[3];
    const float* Wv   = (const float*)d_in[4];
    const float* Wu   = (const float*)d_in[5];
    const float* bu   = (const float*)d_in[6];
    float* out = (float*)d_out;

    __nv_bfloat16 *Qh, *Ql, *Kh, *Kl;
    float *xg;
    __half *xgf, *Wvf, *Wuf, *Vf, *ysf;
    int *idx, *nv;
    cudaGetSymbolAddress((void**)&xg,  g_xg);
    cudaGetSymbolAddress((void**)&xgf, g_xgf);
    cudaGetSymbolAddress((void**)&Qh,  g_Qh);  cudaGetSymbolAddress((void**)&Ql,  g_Ql);
    cudaGetSymbolAddress((void**)&Kh,  g_Kh);  cudaGetSymbolAddress((void**)&Kl,  g_Kl);
    cudaGetSymbolAddress((void**)&Wvf, g_Wvf); cudaGetSymbolAddress((void**)&Wuf, g_Wuf);
    cudaGetSymbolAddress((void**)&Vf,  g_Vf);  cudaGetSymbolAddress((void**)&ysf, g_ysf);
    cudaGetSymbolAddress((void**)&idx, g_idx); cudaGetSymbolAddress((void**)&nv,  g_nv);

    cudaFuncSetAttribute(gemm2_kernel,
                         cudaFuncAttributeMaxDynamicSharedMemorySize, G2SMEM);
    cudaFuncSetAttribute(gemm3_kernel,
                         cudaFuncAttributeMaxDynamicSharedMemorySize, G3SMEM);
    cudaFuncSetAttribute(gemm1_kernel,
                         cudaFuncAttributeMaxDynamicSharedMemorySize, G1SMEM);

    compact_kernel<<<BB, 1024>>>(mask, idx, nv);
    gather_kernel<<<MROWS * KK / 2 / 256, 256>>>(x, idx, nv, xg, xgf);
    prep_w_kernel<<<dim3(KK * KK / 2 / 256, 2), 256>>>(Wv, Wu, Wvf, Wuf);

    dim3 gg(KK / 128, MROWS / 128);   // (8, 32)
    gemm2_kernel<<<gg, 256, G2SMEM>>>(x,  Wq, Qh, Ql, MROWS, KK);
    gemm3_kernel<<<gg, 256, G3SMEM>>>(xg, Wk, Kh, Kl, nv, MROWS, KK);
    gemm1_kernel<<<gg, 256, G1SMEM>>>(xgf, Wvf, nullptr, nullptr, Vf, nv, MROWS, KK);

    dim3 ga(TT / 128, HH, BB);        // (16, 16, 2)
    attn_tc_kernel<<<ga, 128>>>(Qh, Ql, Kh, Kl, Vf, nv, ysf);

    gemm1_kernel<<<gg, 256, G1SMEM>>>(ysf, Wuf, bu, out, nullptr, nullptr, MROWS, KK);
}

// round 12
// speedup vs baseline: 2.5702x; 1.0627x over previous
#include <cuda_runtime.h>
#include <cuda_bf16.h>
#include <cuda_fp16.h>
#include <cstdint>

#define BB   2
#define TT   2048
#define KK   1024
#define HH   16
#define SS   64
#define MROWS (BB*TT)   // 4096
#define INV2048 4.8828125e-4f

// ---- scratch (static device globals; no allocation allowed) ----
__device__ __nv_bfloat16 g_Qh[MROWS*KK], g_Ql[MROWS*KK];
__device__ __nv_bfloat16 g_Kh[MROWS*KK], g_Kl[MROWS*KK];      // compacted K
__device__ __half g_Wuf[KK*KK];
__device__ __half g_Vf [MROWS*KK];                             // compacted V
__device__ __half g_ysf[MROWS*KK];
__device__ int g_idx[BB*TT];
__device__ int g_nv [BB];

// ============================================================================
// helpers
// ============================================================================
__device__ __forceinline__ uint32_t smem_u32(const void* p) {
    uint32_t a;
    asm("{ .reg .u64 t; cvta.to.shared.u64 t, %1; cvt.u32.u64 %0, t; }"
        : "=r"(a) : "l"(p));
    return a;
}

__device__ __forceinline__ void mma_bf16(float d[4],
                                         uint32_t a0, uint32_t a1, uint32_t a2, uint32_t a3,
                                         uint32_t b0, uint32_t b1) {
    asm volatile(
        "mma.sync.aligned.m16n8k16.row.col.f32.bf16.bf16.f32 "
        "{%0,%1,%2,%3}, {%4,%5,%6,%7}, {%8,%9}, {%0,%1,%2,%3};"
        : "+f"(d[0]), "+f"(d[1]), "+f"(d[2]), "+f"(d[3])
        : "r"(a0), "r"(a1), "r"(a2), "r"(a3), "r"(b0), "r"(b1));
}

__device__ __forceinline__ void mma_f16f32(float d[4],
                                           uint32_t a0, uint32_t a1, uint32_t a2, uint32_t a3,
                                           uint32_t b0, uint32_t b1) {
    asm volatile(
        "mma.sync.aligned.m16n8k16.row.col.f32.f16.f16.f32 "
        "{%0,%1,%2,%3}, {%4,%5,%6,%7}, {%8,%9}, {%0,%1,%2,%3};"
        : "+f"(d[0]), "+f"(d[1]), "+f"(d[2]), "+f"(d[3])
        : "r"(a0), "r"(a1), "r"(a2), "r"(a3), "r"(b0), "r"(b1));
}

#define LDSM4(r0, r1, r2, r3, addr) \
    asm volatile("ldmatrix.sync.aligned.m8n8.x4.shared.b16 {%0,%1,%2,%3}, [%4];" \
                 : "=r"(r0), "=r"(r1), "=r"(r2), "=r"(r3) : "r"(addr))

__device__ __forceinline__ void split2(float2 f, uint32_t& h, uint32_t& l) {
    __nv_bfloat162 hh = __float22bfloat162_rn(f);
    float2 hf = __bfloat1622float2(hh);
    __nv_bfloat162 ll = __float22bfloat162_rn(make_float2(f.x - hf.x, f.y - hf.y));
    h = *(uint32_t*)&hh;
    l = *(uint32_t*)&ll;
}

__device__ __forceinline__ void split2h(float2 f, uint32_t& h, uint32_t& l) {
    __half2 hh = __float22half2_rn(f);
    float2 hf = __half22float2(hh);
    __half2 ll = __float22half2_rn(make_float2((f.x - hf.x) * 2048.f,
                                               (f.y - hf.y) * 2048.f));
    h = *(uint32_t*)&hh;
    l = *(uint32_t*)&ll;
}

__device__ __forceinline__ uint32_t pack_h2(float2 f) {
    __half2 hh = __float22half2_rn(f);
    return *(uint32_t*)&hh;
}

// ============================================================================
// mask compaction (proven)
// ============================================================================
__global__ __launch_bounds__(1024)
void compact_kernel(const int* __restrict__ mask, int* __restrict__ idx,
                    int* __restrict__ nv)
{
    __shared__ int s[1024];
    const int b = blockIdx.x;
    const int t = threadIdx.x;
    const int m0 = mask[b * TT + 2 * t];
    const int m1 = mask[b * TT + 2 * t + 1];
    const int c  = m0 + m1;
    s[t] = c;
    __syncthreads();
    for (int off = 1; off < 1024; off <<= 1) {
        int v = s[t];
        int u = (t >= off) ? s[t - off] : 0;
        __syncthreads();
        s[t] = v + u;
        __syncthreads();
    }
    const int incl = s[t];
    const int excl = incl - c;
    if (m0) idx[b * TT + excl] = 2 * t;
    if (m1) idx[b * TT + excl + m0] = 2 * t + 1;
    if (t == 1023) nv[b] = incl;
}

// Wu -> fp16
__global__ __launch_bounds__(256)
void prep_wu_kernel(const float* __restrict__ Wu, __half* __restrict__ Wuf)
{
    int i = blockIdx.x * 256 + threadIdx.x;
    ((uint32_t*)Wuf)[i] = pack_h2(((const float2*)Wu)[i]);
}

// ============================================================================
// common GEMM geometry
// ============================================================================
#define GBK 32
#define NIT (KK / GBK)          // 32
#define BKP 40
#define ATILE (128 * BKP)
#define PROJ_SMEM (8 * ATILE * 2)   // 81920 B (max of the 3 branches)

// ============================================================================
// Fused Q/K/V projection kernel. blockIdx.z selects branch:
//   z=0: Q = x @ Wq^T, fp16 2-digit A x single-fp16 B, split-bf16 out
//   z=1: K = gather(x) @ Wk^T, 3-term split-bf16, compacted out, early exit
//   z=2: V = gather(x) @ Wv^T, 1-term fp16, compacted fp16 out, early exit
// Gather is inline via smem row-index table.
// ============================================================================
__global__ void __launch_bounds__(256)
proj_kernel(const float* __restrict__ x,
            const float* __restrict__ Wq,
            const float* __restrict__ Wk,
            const float* __restrict__ Wv,
            const int* __restrict__ idx,
            const int* __restrict__ nvp,
            __nv_bfloat16* __restrict__ Qh, __nv_bfloat16* __restrict__ Ql,
            __nv_bfloat16* __restrict__ Kh, __nv_bfloat16* __restrict__ Kl,
            __half* __restrict__ Vf)
{
    extern __shared__ char smraw[];
    __shared__ int sidx[128];
    const uint32_t sbase = smem_u32(smraw);

    const int z    = blockIdx.z;
    const int tid  = threadIdx.x;
    const int lane = tid & 31;
    const int wid  = tid >> 5;
    const int g    = lane >> 2;
    const int tg   = lane & 3;
    const int wm   = wid & 1;
    const int wn   = wid >> 1;
    const int m0   = blockIdx.y * 128;
    const int n0   = blockIdx.x * 128;

    if (z >= 1) {
        const int b = m0 / TT;
        const int s = m0 - b * TT;
        const int nvb = nvp[b];
        if (s >= nvb) return;
        if (tid < 128) {
            int ss = s + tid;
            sidx[tid] = b * TT + idx[b * TT + (ss < nvb ? ss : 0)];
        }
        __syncthreads();
    }

    const uint32_t aoff = (uint32_t)((wm * 64 + (lane & 15)) * BKP + ((lane & 16) ? 8 : 0));
    const uint32_t boff = (uint32_t)((wn * 32 + (lane & 7) + ((lane & 16) ? 8 : 0)) * BKP
                                     + ((lane & 8) ? 8 : 0));

    float4 ra[4], rb[4];

    if (z == 0) {
        // ==================== Q: fp16 2-digit x single fp16 ====================
        const float* Agp = x  + (size_t)m0 * KK;
        const float* Bgp = Wq + (size_t)n0 * KK;

#define QLOAD(k0) do { \
    _Pragma("unroll") \
    for (int j = 0; j < 4; j++) { \
        int ix = j * 256 + tid; int row = ix >> 3; int c4 = ix & 7; \
        ra[j] = *(const float4*)(Agp + (size_t)row * KK + (k0) + c4 * 4); \
        rb[j] = *(const float4*)(Bgp + (size_t)row * KK + (k0) + c4 * 4); \
    } } while (0)

#define QSTORE(bsel) do { \
    _Pragma("unroll") \
    for (int j = 0; j < 4; j++) { \
        int ix = j * 256 + tid; int row = ix >> 3; int c4 = ix & 7; \
        uint32_t off = (uint32_t)((bsel) * 3 * ATILE + row * BKP + c4 * 4) * 2; \
        uint32_t h0, l0, h1, l1; \
        split2h(make_float2(ra[j].x, ra[j].y), h0, l0); \
        split2h(make_float2(ra[j].z, ra[j].w), h1, l1); \
        *(uint32_t*)(smraw + off)                 = h0; \
        *(uint32_t*)(smraw + off + 4)             = h1; \
        *(uint32_t*)(smraw + off + ATILE * 2)     = l0; \
        *(uint32_t*)(smraw + off + ATILE * 2 + 4) = l1; \
        *(uint32_t*)(smraw + off + 2 * ATILE * 2)     = pack_h2(make_float2(rb[j].x, rb[j].y)); \
        *(uint32_t*)(smraw + off + 2 * ATILE * 2 + 4) = pack_h2(make_float2(rb[j].z, rb[j].w)); \
    } } while (0)

        float acc [4][4][4];
        float acc2[4][4][4];
#pragma unroll
        for (int i = 0; i < 4; i++)
#pragma unroll
            for (int j = 0; j < 4; j++)
#pragma unroll
                for (int r = 0; r < 4; r++) { acc[i][j][r] = 0.f; acc2[i][j][r] = 0.f; }

        QLOAD(0);
        QSTORE(0);
        __syncthreads();

        for (int it = 0; it < NIT; it++) {
            const int buf = it & 1;
            if (it + 1 < NIT) QLOAD((it + 1) * GBK);

            const uint32_t bb = sbase + (uint32_t)(buf * 3 * ATILE) * 2;
#pragma unroll
            for (int ks = 0; ks < 2; ks++) {
                const uint32_t ko = ks * 32;
                uint32_t bf[4][2];
                LDSM4(bf[0][0], bf[0][1], bf[1][0], bf[1][1],
                      bb + 2 * ATILE * 2 + boff * 2 + ko);
                LDSM4(bf[2][0], bf[2][1], bf[3][0], bf[3][1],
                      bb + 2 * ATILE * 2 + (boff + 16 * BKP) * 2 + ko);
#pragma unroll
                for (int mf = 0; mf < 4; mf++) {
                    uint32_t ah0, ah1, ah2, ah3, al0, al1, al2, al3;
                    LDSM4(ah0, ah1, ah2, ah3, bb + (aoff + mf * 16 * BKP) * 2 + ko);
                    LDSM4(al0, al1, al2, al3, bb + ATILE * 2 + (aoff + mf * 16 * BKP) * 2 + ko);
#pragma unroll
                    for (int nf = 0; nf < 4; nf++) {
                        mma_f16f32(acc [mf][nf], ah0, ah1, ah2, ah3, bf[nf][0], bf[nf][1]);
                        mma_f16f32(acc2[mf][nf], al0, al1, al2, al3, bf[nf][0], bf[nf][1]);
                    }
                }
            }

            if (it + 1 < NIT) {
                __syncthreads();
                QSTORE(buf ^ 1);
                __syncthreads();
            }
        }
#undef QLOAD
#undef QSTORE

#pragma unroll
        for (int mf = 0; mf < 4; mf++) {
            int r0 = m0 + wm * 64 + mf * 16 + g;
#pragma unroll
            for (int nf = 0; nf < 4; nf++) {
                int col = n0 + wn * 32 + nf * 8 + tg * 2;
                float v00 = acc[mf][nf][0] + acc2[mf][nf][0] * INV2048;
                float v01 = acc[mf][nf][1] + acc2[mf][nf][1] * INV2048;
                float v10 = acc[mf][nf][2] + acc2[mf][nf][2] * INV2048;
                float v11 = acc[mf][nf][3] + acc2[mf][nf][3] * INV2048;
                uint32_t h0, l0, h1, l1;
                split2(make_float2(v00, v01), h0, l0);
                split2(make_float2(v10, v11), h1, l1);
                *(uint32_t*)&Qh[(size_t)r0 * KK + col]       = h0;
                *(uint32_t*)&Ql[(size_t)r0 * KK + col]       = l0;
                *(uint32_t*)&Qh[(size_t)(r0 + 8) * KK + col] = h1;
                *(uint32_t*)&Ql[(size_t)(r0 + 8) * KK + col] = l1;
            }
        }

    } else if (z == 1) {
        // ==================== K: 3-term split-bf16, inline gather ====================
        const float* Bgp = Wk + (size_t)n0 * KK;

#define KLOAD(k0) do { \
    _Pragma("unroll") \
    for (int j = 0; j < 4; j++) { \
        int ix = j * 256 + tid; int row = ix >> 3; int c4 = ix & 7; \
        ra[j] = *(const float4*)(x + (size_t)sidx[row] * KK + (k0) + c4 * 4); \
        rb[j] = *(const float4*)(Bgp + (size_t)row * KK + (k0) + c4 * 4); \
    } } while (0)

#define KSTORE(bsel) do { \
    _Pragma("unroll") \
    for (int j = 0; j < 4; j++) { \
        int ix = j * 256 + tid; int row = ix >> 3; int c4 = ix & 7; \
        uint32_t off = (uint32_t)((bsel) * 4 * ATILE + row * BKP + c4 * 4) * 2; \
        uint32_t h0, l0, h1, l1; \
        split2(make_float2(ra[j].x, ra[j].y), h0, l0); \
        split2(make_float2(ra[j].z, ra[j].w), h1, l1); \
        *(uint32_t*)(smraw + off)                 = h0; \
        *(uint32_t*)(smraw + off + 4)             = h1; \
        *(uint32_t*)(smraw + off + ATILE * 2)     = l0; \
        *(uint32_t*)(smraw + off + ATILE * 2 + 4) = l1; \
        split2(make_float2(rb[j].x, rb[j].y), h0, l0); \
        split2(make_float2(rb[j].z, rb[j].w), h1, l1); \
        *(uint32_t*)(smraw + off + 2 * ATILE * 2)     = h0; \
        *(uint32_t*)(smraw + off + 2 * ATILE * 2 + 4) = h1; \
        *(uint32_t*)(smraw + off + 3 * ATILE * 2)     = l0; \
        *(uint32_t*)(smraw + off + 3 * ATILE * 2 + 4) = l1; \
    } } while (0)

        float acc[4][4][4];
#pragma unroll
        for (int i = 0; i < 4; i++)
#pragma unroll
            for (int j = 0; j < 4; j++)
#pragma unroll
                for (int r = 0; r < 4; r++) acc[i][j][r] = 0.f;

        KLOAD(0);
        KSTORE(0);
        __syncthreads();

        for (int it = 0; it < NIT; it++) {
            const int buf = it & 1;
            if (it + 1 < NIT) KLOAD((it + 1) * GBK);

            const uint32_t bb = sbase + (uint32_t)(buf * 4 * ATILE) * 2;
#pragma unroll
            for (int ks = 0; ks < 2; ks++) {
                const uint32_t ko = ks * 32;
                uint32_t bh[4][2], bl[4][2];
                LDSM4(bh[0][0], bh[0][1], bh[1][0], bh[1][1],
                      bb + 2 * ATILE * 2 + boff * 2 + ko);
                LDSM4(bh[2][0], bh[2][1], bh[3][0], bh[3][1],
                      bb + 2 * ATILE * 2 + (boff + 16 * BKP) * 2 + ko);
                LDSM4(bl[0][0], bl[0][1], bl[1][0], bl[1][1],
                      bb + 3 * ATILE * 2 + boff * 2 + ko);
                LDSM4(bl[2][0], bl[2][1], bl[3][0], bl[3][1],
                      bb + 3 * ATILE * 2 + (boff + 16 * BKP) * 2 + ko);
#pragma unroll
                for (int mf = 0; mf < 4; mf++) {
                    uint32_t ah0, ah1, ah2, ah3, al0, al1, al2, al3;
                    LDSM4(ah0, ah1, ah2, ah3, bb + (aoff + mf * 16 * BKP) * 2 + ko);
                    LDSM4(al0, al1, al2, al3, bb + ATILE * 2 + (aoff + mf * 16 * BKP) * 2 + ko);
#pragma unroll
                    for (int nf = 0; nf < 4; nf++) {
                        mma_bf16(acc[mf][nf], ah0, ah1, ah2, ah3, bh[nf][0], bh[nf][1]);
                        mma_bf16(acc[mf][nf], ah0, ah1, ah2, ah3, bl[nf][0], bl[nf][1]);
                        mma_bf16(acc[mf][nf], al0, al1, al2, al3, bh[nf][0], bh[nf][1]);
                    }
                }
            }

            if (it + 1 < NIT) {
                __syncthreads();
                KSTORE(buf ^ 1);
                __syncthreads();
            }
        }
#undef KLOAD
#undef KSTORE

#pragma unroll
        for (int mf = 0; mf < 4; mf++) {
            int r0 = m0 + wm * 64 + mf * 16 + g;
#pragma unroll
            for (int nf = 0; nf < 4; nf++) {
                int col = n0 + wn * 32 + nf * 8 + tg * 2;
                uint32_t h0, l0, h1, l1;
                split2(make_float2(acc[mf][nf][0], acc[mf][nf][1]), h0, l0);
                split2(make_float2(acc[mf][nf][2], acc[mf][nf][3]), h1, l1);
                *(uint32_t*)&Kh[(size_t)r0 * KK + col]       = h0;
                *(uint32_t*)&Kl[(size_t)r0 * KK + col]       = l0;
                *(uint32_t*)&Kh[(size_t)(r0 + 8) * KK + col] = h1;
                *(uint32_t*)&Kl[(size_t)(r0 + 8) * KK + col] = l1;
            }
        }

    } else {
        // ==================== V: 1-term fp16, inline gather + convert ====================
        const float* Bgp = Wv + (size_t)n0 * KK;

#define VLOAD(k0) do { \
    _Pragma("unroll") \
    for (int j = 0; j < 4; j++) { \
        int ix = j * 256 + tid; int row = ix >> 3; int c4 = ix & 7; \
        ra[j] = *(const float4*)(x + (size_t)sidx[row] * KK + (k0) + c4 * 4); \
        rb[j] = *(const float4*)(Bgp + (size_t)row * KK + (k0) + c4 * 4); \
    } } while (0)

#define VSTORE(bsel) do { \
    _Pragma("unroll") \
    for (int j = 0; j < 4; j++) { \
        int ix = j * 256 + tid; int row = ix >> 3; int c4 = ix & 7; \
        uint32_t off = (uint32_t)((bsel) * 2 * ATILE + row * BKP + c4 * 4) * 2; \
        *(uint32_t*)(smraw + off)     = pack_h2(make_float2(ra[j].x, ra[j].y)); \
        *(uint32_t*)(smraw + off + 4) = pack_h2(make_float2(ra[j].z, ra[j].w)); \
        *(uint32_t*)(smraw + off + ATILE * 2)     = pack_h2(make_float2(rb[j].x, rb[j].y)); \
        *(uint32_t*)(smraw + off + ATILE * 2 + 4) = pack_h2(make_float2(rb[j].z, rb[j].w)); \
    } } while (0)

        float acc[4][4][4];
#pragma unroll
        for (int i = 0; i < 4; i++)
#pragma unroll
            for (int j = 0; j < 4; j++)
#pragma unroll
                for (int r = 0; r < 4; r++) acc[i][j][r] = 0.f;

        VLOAD(0);
        VSTORE(0);
        __syncthreads();

        for (int it = 0; it < NIT; it++) {
            const int buf = it & 1;
            if (it + 1 < NIT) VLOAD((it + 1) * GBK);

            const uint32_t bb = sbase + (uint32_t)(buf * 2 * ATILE) * 2;
#pragma unroll
            for (int ks = 0; ks < 2; ks++) {
                const uint32_t ko = ks * 32;
                uint32_t bf[4][2];
                LDSM4(bf[0][0], bf[0][1], bf[1][0], bf[1][1],
                      bb + ATILE * 2 + boff * 2 + ko);
                LDSM4(bf[2][0], bf[2][1], bf[3][0], bf[3][1],
                      bb + ATILE * 2 + (boff + 16 * BKP) * 2 + ko);
#pragma unroll
                for (int mf = 0; mf < 4; mf++) {
                    uint32_t a0, a1, a2, a3;
                    LDSM4(a0, a1, a2, a3, bb + (aoff + mf * 16 * BKP) * 2 + ko);
#pragma unroll
                    for (int nf = 0; nf < 4; nf++)
                        mma_f16f32(acc[mf][nf], a0, a1, a2, a3, bf[nf][0], bf[nf][1]);
                }
            }

            if (it + 1 < NIT) {
                __syncthreads();
                VSTORE(buf ^ 1);
                __syncthreads();
            }
        }
#undef VLOAD
#undef VSTORE

#pragma unroll
        for (int mf = 0; mf < 4; mf++) {
            int r0 = m0 + wm * 64 + mf * 16 + g;
#pragma unroll
            for (int nf = 0; nf < 4; nf++) {
                int col = n0 + wn * 32 + nf * 8 + tg * 2;
                *(uint32_t*)&Vf[(size_t)r0 * KK + col] =
                    pack_h2(make_float2(acc[mf][nf][0], acc[mf][nf][1]));
                *(uint32_t*)&Vf[(size_t)(r0 + 8) * KK + col] =
                    pack_h2(make_float2(acc[mf][nf][2], acc[mf][nf][3]));
            }
        }
    }
}

// ============================================================================
// gemm1: 1-term fp16 via cp.async (U projection only).
// ============================================================================
#define G1SMEM (4 * ATILE * 2)   // 40960 B

__global__ void __launch_bounds__(256)
gemm1_kernel(const __half* __restrict__ Ag,
             const __half* __restrict__ Bg,
             const float* __restrict__ bias,
             float* __restrict__ Cf,
             int M, int N)
{
    extern __shared__ __half sm1[];
    const uint32_t sbase = smem_u32(sm1);

    const int tid  = threadIdx.x;
    const int lane = tid & 31;
    const int wid  = tid >> 5;
    const int g    = lane >> 2;
    const int tg   = lane & 3;
    const int wm   = wid & 1;
    const int wn   = wid >> 1;
    const int m0   = blockIdx.y * 128;
    const int n0   = blockIdx.x * 128;

    const __half* gsrc[2] = { Ag + (size_t)m0 * KK, Bg + (size_t)n0 * KK };

    const uint32_t aoff = (uint32_t)((wm * 64 + (lane & 15)) * BKP + ((lane & 16) ? 8 : 0));
    const uint32_t boff = (uint32_t)((wn * 32 + (lane & 7) + ((lane & 16) ? 8 : 0)) * BKP
                                     + ((lane & 8) ? 8 : 0));

#define G1ISSUE(k0, bsel) do { \
    _Pragma("unroll") \
    for (int a = 0; a < 2; a++) { \
        uint32_t sd = sbase + (uint32_t)(((bsel) * 2 + a) * ATILE) * 2; \
        _Pragma("unroll") \
        for (int j = 0; j < 2; j++) { \
            int row = j * 64 + (tid >> 2); int cc = tid & 3; \
            uint32_t s = sd + (uint32_t)(row * BKP + cc * 8) * 2; \
            const __half* gp = gsrc[a] + (size_t)row * KK + (k0) + cc * 8; \
            asm volatile("cp.async.cg.shared.global [%0], [%1], 16;" :: "r"(s), "l"(gp)); \
        } \
    } \
    asm volatile("cp.async.commit_group;"); \
} while (0)

    float acc[4][4][4];
#pragma unroll
    for (int i = 0; i < 4; i++)
#pragma unroll
        for (int j = 0; j < 4; j++)
#pragma unroll
            for (int r = 0; r < 4; r++) acc[i][j][r] = 0.f;

    G1ISSUE(0, 0);

    for (int it = 0; it < NIT; it++) {
        const int buf = it & 1;
        asm volatile("cp.async.wait_group 0;");
        __syncthreads();
        if (it + 1 < NIT) G1ISSUE((it + 1) * GBK, buf ^ 1);

        const uint32_t bb = sbase + (uint32_t)(buf * 2 * ATILE) * 2;
#pragma unroll
        for (int ks = 0; ks < 2; ks++) {
            const uint32_t ko = ks * 32;
            uint32_t bf[4][2];
            LDSM4(bf[0][0], bf[0][1], bf[1][0], bf[1][1],
                  bb + ATILE * 2 + boff * 2 + ko);
            LDSM4(bf[2][0], bf[2][1], bf[3][0], bf[3][1],
                  bb + ATILE * 2 + (boff + 16 * BKP) * 2 + ko);
#pragma unroll
            for (int mf = 0; mf < 4; mf++) {
                uint32_t a0, a1, a2, a3;
                LDSM4(a0, a1, a2, a3, bb + (aoff + mf * 16 * BKP) * 2 + ko);
#pragma unroll
                for (int nf = 0; nf < 4; nf++)
                    mma_f16f32(acc[mf][nf], a0, a1, a2, a3, bf[nf][0], bf[nf][1]);
            }
        }
    }
#undef G1ISSUE

#pragma unroll
    for (int mf = 0; mf < 4; mf++) {
        int r0 = m0 + wm * 64 + mf * 16 + g;
#pragma unroll
        for (int nf = 0; nf < 4; nf++) {
            int col = n0 + wn * 32 + nf * 8 + tg * 2;
            float b0 = __ldg(&bias[col]), b1 = __ldg(&bias[col + 1]);
            float2 o0 = { acc[mf][nf][0] + b0, acc[mf][nf][1] + b1 };
            float2 o1 = { acc[mf][nf][2] + b0, acc[mf][nf][3] + b1 };
            *(float2*)&Cf[(size_t)r0 * N + col]       = o0;
            *(float2*)&Cf[(size_t)(r0 + 8) * N + col] = o1;
        }
    }
}

// ============================================================================
// Flash attention over compacted K/V (proven round-10/11 body).
// ============================================================================
#define AST 72

__global__ __launch_bounds__(128, 2)
void attn_tc_kernel(const __nv_bfloat16* __restrict__ Qh_,
                    const __nv_bfloat16* __restrict__ Ql_,
                    const __nv_bfloat16* __restrict__ Kh_,
                    const __nv_bfloat16* __restrict__ Kl_,
                    const __half* __restrict__ Vf_,
                    const int* __restrict__ nvp,
                    __half* __restrict__ ysf)
{
    __shared__ __nv_bfloat16 kh[64 * AST], kl[64 * AST];
    __shared__ __half vs[64 * AST];

    const int tid  = threadIdx.x;
    const int lane = tid & 31;
    const int w    = tid >> 5;
    const int g    = lane >> 2;
    const int tg   = lane & 3;
    const int b    = blockIdx.z;
    const int h    = blockIdx.y;
    const int q0   = blockIdx.x * 128;

    const int nvb    = nvp[b];
    const int ntiles = (nvb + 63) >> 6;

    const __nv_bfloat16* Qhb = Qh_ + (size_t)(b * TT + q0 + w * 32) * KK + h * SS;
    const __nv_bfloat16* Qlb = Ql_ + (size_t)(b * TT + q0 + w * 32) * KK + h * SS;
    uint32_t qh_[2][4][4], ql_[2][4][4];
#pragma unroll
    for (int m = 0; m < 2; m++) {
#pragma unroll
        for (int ks = 0; ks < 4; ks++) {
            int r0 = m * 16 + g, r1 = r0 + 8;
            int d0 = ks * 16 + 2 * tg;
            qh_[m][ks][0] = *(const uint32_t*)(Qhb + (size_t)r0 * KK + d0);
            qh_[m][ks][1] = *(const uint32_t*)(Qhb + (size_t)r1 * KK + d0);
            qh_[m][ks][2] = *(const uint32_t*)(Qhb + (size_t)r0 * KK + d0 + 8);
            qh_[m][ks][3] = *(const uint32_t*)(Qhb + (size_t)r1 * KK + d0 + 8);
            ql_[m][ks][0] = *(const uint32_t*)(Qlb + (size_t)r0 * KK + d0);
            ql_[m][ks][1] = *(const uint32_t*)(Qlb + (size_t)r1 * KK + d0);
            ql_[m][ks][2] = *(const uint32_t*)(Qlb + (size_t)r0 * KK + d0 + 8);
            ql_[m][ks][3] = *(const uint32_t*)(Qlb + (size_t)r1 * KK + d0 + 8);
        }
    }

    float o[2][8][4];
#pragma unroll
    for (int m = 0; m < 2; m++)
#pragma unroll
        for (int nt = 0; nt < 8; nt++)
#pragma unroll
            for (int c = 0; c < 4; c++) o[m][nt][c] = 0.f;
    float mr[2][2] = { {-1e30f, -1e30f}, {-1e30f, -1e30f} };
    float lr[2][2] = { {0.f, 0.f}, {0.f, 0.f} };

    const __nv_bfloat16* Khb = Kh_ + (size_t)b * TT * KK + h * SS;
    const __nv_bfloat16* Klb = Kl_ + (size_t)b * TT * KK + h * SS;
    const __half*        Vfb = Vf_ + (size_t)b * TT * KK + h * SS;

    const int ikey = tid >> 1;
    const int half = tid & 1;

    for (int kt = 0; kt < ntiles; kt++) {
        __syncthreads();
        int slot = kt * 64 + ikey;
        {
            const uint4* kph = (const uint4*)(Khb + (size_t)slot * KK + half * 32);
            const uint4* kpl = (const uint4*)(Klb + (size_t)slot * KK + half * 32);
            int dst = ikey * AST + half * 32;
#pragma unroll
            for (int j = 0; j < 4; j++) {
                *(uint4*)&kh[dst + j * 8] = kph[j];
                *(uint4*)&kl[dst + j * 8] = kpl[j];
            }
        }
        {
            const __half2* vph = (const __half2*)(Vfb + (size_t)slot * KK + half * 32);
#pragma unroll
            for (int jj = 0; jj < 16; jj++) {
                int dd = half * 32 + 2 * jj;
                __half2 pv = vph[jj];
                vs[dd * AST + ikey]       = __low2half(pv);
                vs[(dd + 1) * AST + ikey] = __high2half(pv);
            }
        }
        __syncthreads();

        float s[2][8][4];
#pragma unroll
        for (int m = 0; m < 2; m++)
#pragma unroll
            for (int nt = 0; nt < 8; nt++)
#pragma unroll
                for (int c = 0; c < 4; c++) s[m][nt][c] = 0.f;

#pragma unroll
        for (int ks = 0; ks < 4; ks++) {
            const int kk = ks * 16 + 2 * tg;
#pragma unroll
            for (int nt = 0; nt < 8; nt++) {
                const int rr = (nt * 8 + g) * AST + kk;
                uint32_t bh0 = *(const uint32_t*)&kh[rr];
                uint32_t bh1 = *(const uint32_t*)&kh[rr + 8];
                uint32_t bl0 = *(const uint32_t*)&kl[rr];
                uint32_t bl1 = *(const uint32_t*)&kl[rr + 8];
#pragma unroll
                for (int m = 0; m < 2; m++) {
                    mma_bf16(s[m][nt], qh_[m][ks][0], qh_[m][ks][1], qh_[m][ks][2], qh_[m][ks][3], bh0, bh1);
                    mma_bf16(s[m][nt], qh_[m][ks][0], qh_[m][ks][1], qh_[m][ks][2], qh_[m][ks][3], bl0, bl1);
                    mma_bf16(s[m][nt], ql_[m][ks][0], ql_[m][ks][1], ql_[m][ks][2], ql_[m][ks][3], bh0, bh1);
                }
            }
        }

        if (kt * 64 + 64 > nvb) {
#pragma unroll
            for (int nt = 0; nt < 8; nt++) {
                int c0 = kt * 64 + nt * 8 + 2 * tg;
                if (c0 >= nvb) {
                    s[0][nt][0] = s[0][nt][2] = -1e30f;
                    s[1][nt][0] = s[1][nt][2] = -1e30f;
                }
                if (c0 + 1 >= nvb) {
                    s[0][nt][1] = s[0][nt][3] = -1e30f;
                    s[1][nt][1] = s[1][nt][3] = -1e30f;
                }
            }
        }

#pragma unroll
        for (int m = 0; m < 2; m++) {
#pragma unroll
            for (int r2 = 0; r2 < 2; r2++) {
                const int c0 = r2 * 2;
                float tmax = -1e30f;
#pragma unroll
                for (int nt = 0; nt < 8; nt++) {
                    tmax = fmaxf(tmax, s[m][nt][c0]);
                    tmax = fmaxf(tmax, s[m][nt][c0 + 1]);
                }
                tmax = fmaxf(tmax, __shfl_xor_sync(0xffffffffu, tmax, 1));
                tmax = fmaxf(tmax, __shfl_xor_sync(0xffffffffu, tmax, 2));
                float mn = fmaxf(mr[m][r2], tmax);
                float sc = __expf(mr[m][r2] - mn);
                mr[m][r2] = mn;
                float ts = 0.f;
#pragma unroll
                for (int nt = 0; nt < 8; nt++) {
                    float p0 = __expf(s[m][nt][c0]     - mn);
                    float p1 = __expf(s[m][nt][c0 + 1] - mn);
                    s[m][nt][c0]     = p0;
                    s[m][nt][c0 + 1] = p1;
                    ts += p0 + p1;
                }
                ts += __shfl_xor_sync(0xffffffffu, ts, 1);
                ts += __shfl_xor_sync(0xffffffffu, ts, 2);
                lr[m][r2] = lr[m][r2] * sc + ts;
#pragma unroll
                for (int nt = 0; nt < 8; nt++) {
                    o[m][nt][c0]     *= sc;
                    o[m][nt][c0 + 1] *= sc;
                }
            }
        }

#pragma unroll
        for (int ks = 0; ks < 4; ks++) {
            uint32_t ph[2][4];
#pragma unroll
            for (int m = 0; m < 2; m++) {
                ph[m][0] = pack_h2(make_float2(s[m][2*ks][0],   s[m][2*ks][1]));
                ph[m][1] = pack_h2(make_float2(s[m][2*ks][2],   s[m][2*ks][3]));
                ph[m][2] = pack_h2(make_float2(s[m][2*ks+1][0], s[m][2*ks+1][1]));
                ph[m][3] = pack_h2(make_float2(s[m][2*ks+1][2], s[m][2*ks+1][3]));
            }
            const int kk = ks * 16 + 2 * tg;
#pragma unroll
            for (int nt = 0; nt < 8; nt++) {
                const int rr = (nt * 8 + g) * AST + kk;
                uint32_t v0 = *(const uint32_t*)&vs[rr];
                uint32_t v1 = *(const uint32_t*)&vs[rr + 8];
#pragma unroll
                for (int m = 0; m < 2; m++)
                    mma_f16f32(o[m][nt], ph[m][0], ph[m][1], ph[m][2], ph[m][3], v0, v1);
            }
        }
    }

#pragma unroll
    for (int m = 0; m < 2; m++) {
#pragma unroll
        for (int r2 = 0; r2 < 2; r2++) {
            float inv = 1.f / lr[m][r2];
            int row = q0 + w * 32 + m * 16 + g + r2 * 8;
            size_t off = (size_t)(b * TT + row) * KK + h * SS;
#pragma unroll
            for (int nt = 0; nt < 8; nt++) {
                *(uint32_t*)&ysf[off + nt * 8 + 2 * tg] =
                    pack_h2(make_float2(o[m][nt][r2*2] * inv, o[m][nt][r2*2+1] * inv));
            }
        }
    }
}

// ============================================================================
// launch
// ============================================================================
extern "C" void kernel_launch(void* const* d_in, const int* in_sizes, int n_in,
                              void* d_out, int out_size)
{
    const float* x    = (const float*)d_in[0];
    const int*   mask = (const int*)  d_in[1];
    const float* Wk   = (const float*)d_in[2];
    const float* Wq   = (const float*)d_in[3];
    const float* Wv   = (const float*)d_in[4];
    const float* Wu   = (const float*)d_in[5];
    const float* bu   = (const float*)d_in[6];
    float* out = (float*)d_out;

    __nv_bfloat16 *Qh, *Ql, *Kh, *Kl;
    __half *Wuf, *Vf, *ysf;
    int *idx, *nv;
    cudaGetSymbolAddress((void**)&Qh,  g_Qh);  cudaGetSymbolAddress((void**)&Ql,  g_Ql);
    cudaGetSymbolAddress((void**)&Kh,  g_Kh);  cudaGetSymbolAddress((void**)&Kl,  g_Kl);
    cudaGetSymbolAddress((void**)&Wuf, g_Wuf);
    cudaGetSymbolAddress((void**)&Vf,  g_Vf);  cudaGetSymbolAddress((void**)&ysf, g_ysf);
    cudaGetSymbolAddress((void**)&idx, g_idx); cudaGetSymbolAddress((void**)&nv,  g_nv);

    cudaFuncSetAttribute(proj_kernel,
                         cudaFuncAttributeMaxDynamicSharedMemorySize, PROJ_SMEM);
    cudaFuncSetAttribute(gemm1_kernel,
                         cudaFuncAttributeMaxDynamicSharedMemorySize, G1SMEM);

    compact_kernel<<<BB, 1024>>>(mask, idx, nv);
    prep_wu_kernel<<<KK * KK / 2 / 256, 256>>>(Wu, Wuf);

    dim3 gp(KK / 128, MROWS / 128, 3);   // (8, 32, 3): z = Q/K/V
    proj_kernel<<<gp, 256, PROJ_SMEM>>>(x, Wq, Wk, Wv, idx, nv,
                                        Qh, Ql, Kh, Kl, Vf);

    dim3 ga(TT / 128, HH, BB);           // (16, 16, 2)
    attn_tc_kernel<<<ga, 128>>>(Qh, Ql, Kh, Kl, Vf, nv, ysf);

    dim3 gu(KK / 128, MROWS / 128);      // (8, 32)
    gemm1_kernel<<<gu, 256, G1SMEM>>>(ysf, Wuf, bu, out, MROWS, KK);
}

// round 13
// speedup vs baseline: 2.9974x; 1.1662x over previous
#include <cuda_runtime.h>
#include <cuda_bf16.h>
#include <cuda_fp16.h>
#include <cstdint>

#define BB   2
#define TT   2048
#define KK   1024
#define HH   16
#define SS   64
#define MROWS (BB*TT)   // 4096
#define INV2048 4.8828125e-4f

// ---- scratch (static device globals; no allocation allowed) ----
__device__ __nv_bfloat16 g_Qh[MROWS*KK], g_Ql[MROWS*KK];
__device__ __nv_bfloat16 g_Kh[MROWS*KK], g_Kl[MROWS*KK];      // compacted K
__device__ __half g_Wuf[KK*KK];
__device__ __half g_Vf [MROWS*KK];                             // compacted V
__device__ __half g_ysf[MROWS*KK];
__device__ int g_idx[BB*TT];
__device__ int g_nv [BB];

// ============================================================================
// helpers
// ============================================================================
__device__ __forceinline__ uint32_t smem_u32(const void* p) {
    uint32_t a;
    asm("{ .reg .u64 t; cvta.to.shared.u64 t, %1; cvt.u32.u64 %0, t; }"
        : "=r"(a) : "l"(p));
    return a;
}

__device__ __forceinline__ void mma_bf16(float d[4],
                                         uint32_t a0, uint32_t a1, uint32_t a2, uint32_t a3,
                                         uint32_t b0, uint32_t b1) {
    asm volatile(
        "mma.sync.aligned.m16n8k16.row.col.f32.bf16.bf16.f32 "
        "{%0,%1,%2,%3}, {%4,%5,%6,%7}, {%8,%9}, {%0,%1,%2,%3};"
        : "+f"(d[0]), "+f"(d[1]), "+f"(d[2]), "+f"(d[3])
        : "r"(a0), "r"(a1), "r"(a2), "r"(a3), "r"(b0), "r"(b1));
}

__device__ __forceinline__ void mma_f16f32(float d[4],
                                           uint32_t a0, uint32_t a1, uint32_t a2, uint32_t a3,
                                           uint32_t b0, uint32_t b1) {
    asm volatile(
        "mma.sync.aligned.m16n8k16.row.col.f32.f16.f16.f32 "
        "{%0,%1,%2,%3}, {%4,%5,%6,%7}, {%8,%9}, {%0,%1,%2,%3};"
        : "+f"(d[0]), "+f"(d[1]), "+f"(d[2]), "+f"(d[3])
        : "r"(a0), "r"(a1), "r"(a2), "r"(a3), "r"(b0), "r"(b1));
}

#define LDSM4(r0, r1, r2, r3, addr) \
    asm volatile("ldmatrix.sync.aligned.m8n8.x4.shared.b16 {%0,%1,%2,%3}, [%4];" \
                 : "=r"(r0), "=r"(r1), "=r"(r2), "=r"(r3) : "r"(addr))

#define LDSM4T(r0, r1, r2, r3, addr) \
    asm volatile("ldmatrix.sync.aligned.m8n8.x4.trans.shared.b16 {%0,%1,%2,%3}, [%4];" \
                 : "=r"(r0), "=r"(r1), "=r"(r2), "=r"(r3) : "r"(addr))

__device__ __forceinline__ void split2(float2 f, uint32_t& h, uint32_t& l) {
    __nv_bfloat162 hh = __float22bfloat162_rn(f);
    float2 hf = __bfloat1622float2(hh);
    __nv_bfloat162 ll = __float22bfloat162_rn(make_float2(f.x - hf.x, f.y - hf.y));
    h = *(uint32_t*)&hh;
    l = *(uint32_t*)&ll;
}

__device__ __forceinline__ void split2h(float2 f, uint32_t& h, uint32_t& l) {
    __half2 hh = __float22half2_rn(f);
    float2 hf = __half22float2(hh);
    __half2 ll = __float22half2_rn(make_float2((f.x - hf.x) * 2048.f,
                                               (f.y - hf.y) * 2048.f));
    h = *(uint32_t*)&hh;
    l = *(uint32_t*)&ll;
}

__device__ __forceinline__ uint32_t pack_h2(float2 f) {
    __half2 hh = __float22half2_rn(f);
    return *(uint32_t*)&hh;
}

// ============================================================================
// mask compaction (proven)
// ============================================================================
__global__ __launch_bounds__(1024)
void compact_kernel(const int* __restrict__ mask, int* __restrict__ idx,
                    int* __restrict__ nv)
{
    __shared__ int s[1024];
    const int b = blockIdx.x;
    const int t = threadIdx.x;
    const int m0 = mask[b * TT + 2 * t];
    const int m1 = mask[b * TT + 2 * t + 1];
    const int c  = m0 + m1;
    s[t] = c;
    __syncthreads();
    for (int off = 1; off < 1024; off <<= 1) {
        int v = s[t];
        int u = (t >= off) ? s[t - off] : 0;
        __syncthreads();
        s[t] = v + u;
        __syncthreads();
    }
    const int incl = s[t];
    const int excl = incl - c;
    if (m0) idx[b * TT + excl] = 2 * t;
    if (m1) idx[b * TT + excl + m0] = 2 * t + 1;
    if (t == 1023) nv[b] = incl;
}

// Wu -> fp16
__global__ __launch_bounds__(256)
void prep_wu_kernel(const float* __restrict__ Wu, __half* __restrict__ Wuf)
{
    int i = blockIdx.x * 256 + threadIdx.x;
    ((uint32_t*)Wuf)[i] = pack_h2(((const float2*)Wu)[i]);
}

// ============================================================================
// common GEMM geometry
// ============================================================================
#define GBK 32
#define NIT (KK / GBK)          // 32
#define BKP 40
#define ATILE (128 * BKP)
#define PROJ_SMEM (8 * ATILE * 2)   // 81920 B

// ============================================================================
// Fused Q/K/V projection kernel (proven round-12 body).
// ============================================================================
__global__ void __launch_bounds__(256)
proj_kernel(const float* __restrict__ x,
            const float* __restrict__ Wq,
            const float* __restrict__ Wk,
            const float* __restrict__ Wv,
            const int* __restrict__ idx,
            const int* __restrict__ nvp,
            __nv_bfloat16* __restrict__ Qh, __nv_bfloat16* __restrict__ Ql,
            __nv_bfloat16* __restrict__ Kh, __nv_bfloat16* __restrict__ Kl,
            __half* __restrict__ Vf)
{
    extern __shared__ char smraw[];
    __shared__ int sidx[128];
    const uint32_t sbase = smem_u32(smraw);

    const int z    = blockIdx.z;
    const int tid  = threadIdx.x;
    const int lane = tid & 31;
    const int wid  = tid >> 5;
    const int g    = lane >> 2;
    const int tg   = lane & 3;
    const int wm   = wid & 1;
    const int wn   = wid >> 1;
    const int m0   = blockIdx.y * 128;
    const int n0   = blockIdx.x * 128;

    if (z >= 1) {
        const int b = m0 / TT;
        const int s = m0 - b * TT;
        const int nvb = nvp[b];
        if (s >= nvb) return;
        if (tid < 128) {
            int ss = s + tid;
            sidx[tid] = b * TT + idx[b * TT + (ss < nvb ? ss : 0)];
        }
        __syncthreads();
    }

    const uint32_t aoff = (uint32_t)((wm * 64 + (lane & 15)) * BKP + ((lane & 16) ? 8 : 0));
    const uint32_t boff = (uint32_t)((wn * 32 + (lane & 7) + ((lane & 16) ? 8 : 0)) * BKP
                                     + ((lane & 8) ? 8 : 0));

    float4 ra[4], rb[4];

    if (z == 0) {
        const float* Agp = x  + (size_t)m0 * KK;
        const float* Bgp = Wq + (size_t)n0 * KK;

#define QLOAD(k0) do { \
    _Pragma("unroll") \
    for (int j = 0; j < 4; j++) { \
        int ix = j * 256 + tid; int row = ix >> 3; int c4 = ix & 7; \
        ra[j] = *(const float4*)(Agp + (size_t)row * KK + (k0) + c4 * 4); \
        rb[j] = *(const float4*)(Bgp + (size_t)row * KK + (k0) + c4 * 4); \
    } } while (0)

#define QSTORE(bsel) do { \
    _Pragma("unroll") \
    for (int j = 0; j < 4; j++) { \
        int ix = j * 256 + tid; int row = ix >> 3; int c4 = ix & 7; \
        uint32_t off = (uint32_t)((bsel) * 3 * ATILE + row * BKP + c4 * 4) * 2; \
        uint32_t h0, l0, h1, l1; \
        split2h(make_float2(ra[j].x, ra[j].y), h0, l0); \
        split2h(make_float2(ra[j].z, ra[j].w), h1, l1); \
        *(uint32_t*)(smraw + off)                 = h0; \
        *(uint32_t*)(smraw + off + 4)             = h1; \
        *(uint32_t*)(smraw + off + ATILE * 2)     = l0; \
        *(uint32_t*)(smraw + off + ATILE * 2 + 4) = l1; \
        *(uint32_t*)(smraw + off + 2 * ATILE * 2)     = pack_h2(make_float2(rb[j].x, rb[j].y)); \
        *(uint32_t*)(smraw + off + 2 * ATILE * 2 + 4) = pack_h2(make_float2(rb[j].z, rb[j].w)); \
    } } while (0)

        float acc [4][4][4];
        float acc2[4][4][4];
#pragma unroll
        for (int i = 0; i < 4; i++)
#pragma unroll
            for (int j = 0; j < 4; j++)
#pragma unroll
                for (int r = 0; r < 4; r++) { acc[i][j][r] = 0.f; acc2[i][j][r] = 0.f; }

        QLOAD(0);
        QSTORE(0);
        __syncthreads();

        for (int it = 0; it < NIT; it++) {
            const int buf = it & 1;
            if (it + 1 < NIT) QLOAD((it + 1) * GBK);

            const uint32_t bb = sbase + (uint32_t)(buf * 3 * ATILE) * 2;
#pragma unroll
            for (int ks = 0; ks < 2; ks++) {
                const uint32_t ko = ks * 32;
                uint32_t bf[4][2];
                LDSM4(bf[0][0], bf[0][1], bf[1][0], bf[1][1],
                      bb + 2 * ATILE * 2 + boff * 2 + ko);
                LDSM4(bf[2][0], bf[2][1], bf[3][0], bf[3][1],
                      bb + 2 * ATILE * 2 + (boff + 16 * BKP) * 2 + ko);
#pragma unroll
                for (int mf = 0; mf < 4; mf++) {
                    uint32_t ah0, ah1, ah2, ah3, al0, al1, al2, al3;
                    LDSM4(ah0, ah1, ah2, ah3, bb + (aoff + mf * 16 * BKP) * 2 + ko);
                    LDSM4(al0, al1, al2, al3, bb + ATILE * 2 + (aoff + mf * 16 * BKP) * 2 + ko);
#pragma unroll
                    for (int nf = 0; nf < 4; nf++) {
                        mma_f16f32(acc [mf][nf], ah0, ah1, ah2, ah3, bf[nf][0], bf[nf][1]);
                        mma_f16f32(acc2[mf][nf], al0, al1, al2, al3, bf[nf][0], bf[nf][1]);
                    }
                }
            }

            if (it + 1 < NIT) {
                __syncthreads();
                QSTORE(buf ^ 1);
                __syncthreads();
            }
        }
#undef QLOAD
#undef QSTORE

#pragma unroll
        for (int mf = 0; mf < 4; mf++) {
            int r0 = m0 + wm * 64 + mf * 16 + g;
#pragma unroll
            for (int nf = 0; nf < 4; nf++) {
                int col = n0 + wn * 32 + nf * 8 + tg * 2;
                float v00 = acc[mf][nf][0] + acc2[mf][nf][0] * INV2048;
                float v01 = acc[mf][nf][1] + acc2[mf][nf][1] * INV2048;
                float v10 = acc[mf][nf][2] + acc2[mf][nf][2] * INV2048;
                float v11 = acc[mf][nf][3] + acc2[mf][nf][3] * INV2048;
                uint32_t h0, l0, h1, l1;
                split2(make_float2(v00, v01), h0, l0);
                split2(make_float2(v10, v11), h1, l1);
                *(uint32_t*)&Qh[(size_t)r0 * KK + col]       = h0;
                *(uint32_t*)&Ql[(size_t)r0 * KK + col]       = l0;
                *(uint32_t*)&Qh[(size_t)(r0 + 8) * KK + col] = h1;
                *(uint32_t*)&Ql[(size_t)(r0 + 8) * KK + col] = l1;
            }
        }

    } else if (z == 1) {
        const float* Bgp = Wk + (size_t)n0 * KK;

#define KLOAD(k0) do { \
    _Pragma("unroll") \
    for (int j = 0; j < 4; j++) { \
        int ix = j * 256 + tid; int row = ix >> 3; int c4 = ix & 7; \
        ra[j] = *(const float4*)(x + (size_t)sidx[row] * KK + (k0) + c4 * 4); \
        rb[j] = *(const float4*)(Bgp + (size_t)row * KK + (k0) + c4 * 4); \
    } } while (0)

#define KSTORE(bsel) do { \
    _Pragma("unroll") \
    for (int j = 0; j < 4; j++) { \
        int ix = j * 256 + tid; int row = ix >> 3; int c4 = ix & 7; \
        uint32_t off = (uint32_t)((bsel) * 4 * ATILE + row * BKP + c4 * 4) * 2; \
        uint32_t h0, l0, h1, l1; \
        split2(make_float2(ra[j].x, ra[j].y), h0, l0); \
        split2(make_float2(ra[j].z, ra[j].w), h1, l1); \
        *(uint32_t*)(smraw + off)                 = h0; \
        *(uint32_t*)(smraw + off + 4)             = h1; \
        *(uint32_t*)(smraw + off + ATILE * 2)     = l0; \
        *(uint32_t*)(smraw + off + ATILE * 2 + 4) = l1; \
        split2(make_float2(rb[j].x, rb[j].y), h0, l0); \
        split2(make_float2(rb[j].z, rb[j].w), h1, l1); \
        *(uint32_t*)(smraw + off + 2 * ATILE * 2)     = h0; \
        *(uint32_t*)(smraw + off + 2 * ATILE * 2 + 4) = h1; \
        *(uint32_t*)(smraw + off + 3 * ATILE * 2)     = l0; \
        *(uint32_t*)(smraw + off + 3 * ATILE * 2 + 4) = l1; \
    } } while (0)

        float acc[4][4][4];
#pragma unroll
        for (int i = 0; i < 4; i++)
#pragma unroll
            for (int j = 0; j < 4; j++)
#pragma unroll
                for (int r = 0; r < 4; r++) acc[i][j][r] = 0.f;

        KLOAD(0);
        KSTORE(0);
        __syncthreads();

        for (int it = 0; it < NIT; it++) {
            const int buf = it & 1;
            if (it + 1 < NIT) KLOAD((it + 1) * GBK);

            const uint32_t bb = sbase + (uint32_t)(buf * 4 * ATILE) * 2;
#pragma unroll
            for (int ks = 0; ks < 2; ks++) {
                const uint32_t ko = ks * 32;
                uint32_t bh[4][2], bl[4][2];
                LDSM4(bh[0][0], bh[0][1], bh[1][0], bh[1][1],
                      bb + 2 * ATILE * 2 + boff * 2 + ko);
                LDSM4(bh[2][0], bh[2][1], bh[3][0], bh[3][1],
                      bb + 2 * ATILE * 2 + (boff + 16 * BKP) * 2 + ko);
                LDSM4(bl[0][0], bl[0][1], bl[1][0], bl[1][1],
                      bb + 3 * ATILE * 2 + boff * 2 + ko);
                LDSM4(bl[2][0], bl[2][1], bl[3][0], bl[3][1],
                      bb + 3 * ATILE * 2 + (boff + 16 * BKP) * 2 + ko);
#pragma unroll
                for (int mf = 0; mf < 4; mf++) {
                    uint32_t ah0, ah1, ah2, ah3, al0, al1, al2, al3;
                    LDSM4(ah0, ah1, ah2, ah3, bb + (aoff + mf * 16 * BKP) * 2 + ko);
                    LDSM4(al0, al1, al2, al3, bb + ATILE * 2 + (aoff + mf * 16 * BKP) * 2 + ko);
#pragma unroll
                    for (int nf = 0; nf < 4; nf++) {
                        mma_bf16(acc[mf][nf], ah0, ah1, ah2, ah3, bh[nf][0], bh[nf][1]);
                        mma_bf16(acc[mf][nf], ah0, ah1, ah2, ah3, bl[nf][0], bl[nf][1]);
                        mma_bf16(acc[mf][nf], al0, al1, al2, al3, bh[nf][0], bh[nf][1]);
                    }
                }
            }

            if (it + 1 < NIT) {
                __syncthreads();
                KSTORE(buf ^ 1);
                __syncthreads();
            }
        }
#undef KLOAD
#undef KSTORE

#pragma unroll
        for (int mf = 0; mf < 4; mf++) {
            int r0 = m0 + wm * 64 + mf * 16 + g;
#pragma unroll
            for (int nf = 0; nf < 4; nf++) {
                int col = n0 + wn * 32 + nf * 8 + tg * 2;
                uint32_t h0, l0, h1, l1;
                split2(make_float2(acc[mf][nf][0], acc[mf][nf][1]), h0, l0);
                split2(make_float2(acc[mf][nf][2], acc[mf][nf][3]), h1, l1);
                *(uint32_t*)&Kh[(size_t)r0 * KK + col]       = h0;
                *(uint32_t*)&Kl[(size_t)r0 * KK + col]       = l0;
                *(uint32_t*)&Kh[(size_t)(r0 + 8) * KK + col] = h1;
                *(uint32_t*)&Kl[(size_t)(r0 + 8) * KK + col] = l1;
            }
        }

    } else {
        const float* Bgp = Wv + (size_t)n0 * KK;

#define VLOAD(k0) do { \
    _Pragma("unroll") \
    for (int j = 0; j < 4; j++) { \
        int ix = j * 256 + tid; int row = ix >> 3; int c4 = ix & 7; \
        ra[j] = *(const float4*)(x + (size_t)sidx[row] * KK + (k0) + c4 * 4); \
        rb[j] = *(const float4*)(Bgp + (size_t)row * KK + (k0) + c4 * 4); \
    } } while (0)

#define VSTORE(bsel) do { \
    _Pragma("unroll") \
    for (int j = 0; j < 4; j++) { \
        int ix = j * 256 + tid; int row = ix >> 3; int c4 = ix & 7; \
        uint32_t off = (uint32_t)((bsel) * 2 * ATILE + row * BKP + c4 * 4) * 2; \
        *(uint32_t*)(smraw + off)     = pack_h2(make_float2(ra[j].x, ra[j].y)); \
        *(uint32_t*)(smraw + off + 4) = pack_h2(make_float2(ra[j].z, ra[j].w)); \
        *(uint32_t*)(smraw + off + ATILE * 2)     = pack_h2(make_float2(rb[j].x, rb[j].y)); \
        *(uint32_t*)(smraw + off + ATILE * 2 + 4) = pack_h2(make_float2(rb[j].z, rb[j].w)); \
    } } while (0)

        float acc[4][4][4];
#pragma unroll
        for (int i = 0; i < 4; i++)
#pragma unroll
            for (int j = 0; j < 4; j++)
#pragma unroll
                for (int r = 0; r < 4; r++) acc[i][j][r] = 0.f;

        VLOAD(0);
        VSTORE(0);
        __syncthreads();

        for (int it = 0; it < NIT; it++) {
            const int buf = it & 1;
            if (it + 1 < NIT) VLOAD((it + 1) * GBK);

            const uint32_t bb = sbase + (uint32_t)(buf * 2 * ATILE) * 2;
#pragma unroll
            for (int ks = 0; ks < 2; ks++) {
                const uint32_t ko = ks * 32;
                uint32_t bf[4][2];
                LDSM4(bf[0][0], bf[0][1], bf[1][0], bf[1][1],
                      bb + ATILE * 2 + boff * 2 + ko);
                LDSM4(bf[2][0], bf[2][1], bf[3][0], bf[3][1],
                      bb + ATILE * 2 + (boff + 16 * BKP) * 2 + ko);
#pragma unroll
                for (int mf = 0; mf < 4; mf++) {
                    uint32_t a0, a1, a2, a3;
                    LDSM4(a0, a1, a2, a3, bb + (aoff + mf * 16 * BKP) * 2 + ko);
#pragma unroll
                    for (int nf = 0; nf < 4; nf++)
                        mma_f16f32(acc[mf][nf], a0, a1, a2, a3, bf[nf][0], bf[nf][1]);
                }
            }

            if (it + 1 < NIT) {
                __syncthreads();
                VSTORE(buf ^ 1);
                __syncthreads();
            }
        }
#undef VLOAD
#undef VSTORE

#pragma unroll
        for (int mf = 0; mf < 4; mf++) {
            int r0 = m0 + wm * 64 + mf * 16 + g;
#pragma unroll
            for (int nf = 0; nf < 4; nf++) {
                int col = n0 + wn * 32 + nf * 8 + tg * 2;
                *(uint32_t*)&Vf[(size_t)r0 * KK + col] =
                    pack_h2(make_float2(acc[mf][nf][0], acc[mf][nf][1]));
                *(uint32_t*)&Vf[(size_t)(r0 + 8) * KK + col] =
                    pack_h2(make_float2(acc[mf][nf][2], acc[mf][nf][3]));
            }
        }
    }
}

// ============================================================================
// gemm1: 1-term fp16 via cp.async (U projection only).
// ============================================================================
#define G1SMEM (4 * ATILE * 2)   // 40960 B

__global__ void __launch_bounds__(256)
gemm1_kernel(const __half* __restrict__ Ag,
             const __half* __restrict__ Bg,
             const float* __restrict__ bias,
             float* __restrict__ Cf,
             int M, int N)
{
    extern __shared__ __half sm1[];
    const uint32_t sbase = smem_u32(sm1);

    const int tid  = threadIdx.x;
    const int lane = tid & 31;
    const int wid  = tid >> 5;
    const int g    = lane >> 2;
    const int tg   = lane & 3;
    const int wm   = wid & 1;
    const int wn   = wid >> 1;
    const int m0   = blockIdx.y * 128;
    const int n0   = blockIdx.x * 128;

    const __half* gsrc[2] = { Ag + (size_t)m0 * KK, Bg + (size_t)n0 * KK };

    const uint32_t aoff = (uint32_t)((wm * 64 + (lane & 15)) * BKP + ((lane & 16) ? 8 : 0));
    const uint32_t boff = (uint32_t)((wn * 32 + (lane & 7) + ((lane & 16) ? 8 : 0)) * BKP
                                     + ((lane & 8) ? 8 : 0));

#define G1ISSUE(k0, bsel) do { \
    _Pragma("unroll") \
    for (int a = 0; a < 2; a++) { \
        uint32_t sd = sbase + (uint32_t)(((bsel) * 2 + a) * ATILE) * 2; \
        _Pragma("unroll") \
        for (int j = 0; j < 2; j++) { \
            int row = j * 64 + (tid >> 2); int cc = tid & 3; \
            uint32_t s = sd + (uint32_t)(row * BKP + cc * 8) * 2; \
            const __half* gp = gsrc[a] + (size_t)row * KK + (k0) + cc * 8; \
            asm volatile("cp.async.cg.shared.global [%0], [%1], 16;" :: "r"(s), "l"(gp)); \
        } \
    } \
    asm volatile("cp.async.commit_group;"); \
} while (0)

    float acc[4][4][4];
#pragma unroll
    for (int i = 0; i < 4; i++)
#pragma unroll
        for (int j = 0; j < 4; j++)
#pragma unroll
            for (int r = 0; r < 4; r++) acc[i][j][r] = 0.f;

    G1ISSUE(0, 0);

    for (int it = 0; it < NIT; it++) {
        const int buf = it & 1;
        asm volatile("cp.async.wait_group 0;");
        __syncthreads();
        if (it + 1 < NIT) G1ISSUE((it + 1) * GBK, buf ^ 1);

        const uint32_t bb = sbase + (uint32_t)(buf * 2 * ATILE) * 2;
#pragma unroll
        for (int ks = 0; ks < 2; ks++) {
            const uint32_t ko = ks * 32;
            uint32_t bf[4][2];
            LDSM4(bf[0][0], bf[0][1], bf[1][0], bf[1][1],
                  bb + ATILE * 2 + boff * 2 + ko);
            LDSM4(bf[2][0], bf[2][1], bf[3][0], bf[3][1],
                  bb + ATILE * 2 + (boff + 16 * BKP) * 2 + ko);
#pragma unroll
            for (int mf = 0; mf < 4; mf++) {
                uint32_t a0, a1, a2, a3;
                LDSM4(a0, a1, a2, a3, bb + (aoff + mf * 16 * BKP) * 2 + ko);
#pragma unroll
                for (int nf = 0; nf < 4; nf++)
                    mma_f16f32(acc[mf][nf], a0, a1, a2, a3, bf[nf][0], bf[nf][1]);
            }
        }
    }
#undef G1ISSUE

#pragma unroll
    for (int mf = 0; mf < 4; mf++) {
        int r0 = m0 + wm * 64 + mf * 16 + g;
#pragma unroll
        for (int nf = 0; nf < 4; nf++) {
            int col = n0 + wn * 32 + nf * 8 + tg * 2;
            float b0 = __ldg(&bias[col]), b1 = __ldg(&bias[col + 1]);
            float2 o0 = { acc[mf][nf][0] + b0, acc[mf][nf][1] + b1 };
            float2 o1 = { acc[mf][nf][2] + b0, acc[mf][nf][3] + b1 };
            *(float2*)&Cf[(size_t)r0 * N + col]       = o0;
            *(float2*)&Cf[(size_t)(r0 + 8) * N + col] = o1;
        }
    }
}

// ============================================================================
// Flash attention v2: cp.async double-buffered K/V stages (row-major),
// ldmatrix.trans for V fragments. Compacted K/V, split-bf16 QK^T, fp16 PV.
// ============================================================================
#define AST 72
#define KVTILE (64 * AST * 2)         // bytes per array per stage (9216)
#define ASTAGE (3 * KVTILE)           // kh, kl, vf (27648)
#define ATTN_SMEM (2 * ASTAGE)        // 55296

__global__ __launch_bounds__(128, 2)
void attn_tc_kernel(const __nv_bfloat16* __restrict__ Qh_,
                    const __nv_bfloat16* __restrict__ Ql_,
                    const __nv_bfloat16* __restrict__ Kh_,
                    const __nv_bfloat16* __restrict__ Kl_,
                    const __half* __restrict__ Vf_,
                    const int* __restrict__ nvp,
                    __half* __restrict__ ysf)
{
    extern __shared__ char asmem[];
    const uint32_t sbase = smem_u32(asmem);

    const int tid  = threadIdx.x;
    const int lane = tid & 31;
    const int w    = tid >> 5;
    const int g    = lane >> 2;
    const int tg   = lane & 3;
    const int b    = blockIdx.z;
    const int h    = blockIdx.y;
    const int q0   = blockIdx.x * 128;

    const int nvb    = nvp[b];
    const int ntiles = (nvb + 63) >> 6;

    const __nv_bfloat16* Qhb = Qh_ + (size_t)(b * TT + q0 + w * 32) * KK + h * SS;
    const __nv_bfloat16* Qlb = Ql_ + (size_t)(b * TT + q0 + w * 32) * KK + h * SS;
    uint32_t qh_[2][4][4], ql_[2][4][4];
#pragma unroll
    for (int m = 0; m < 2; m++) {
#pragma unroll
        for (int ks = 0; ks < 4; ks++) {
            int r0 = m * 16 + g, r1 = r0 + 8;
            int d0 = ks * 16 + 2 * tg;
            qh_[m][ks][0] = *(const uint32_t*)(Qhb + (size_t)r0 * KK + d0);
            qh_[m][ks][1] = *(const uint32_t*)(Qhb + (size_t)r1 * KK + d0);
            qh_[m][ks][2] = *(const uint32_t*)(Qhb + (size_t)r0 * KK + d0 + 8);
            qh_[m][ks][3] = *(const uint32_t*)(Qhb + (size_t)r1 * KK + d0 + 8);
            ql_[m][ks][0] = *(const uint32_t*)(Qlb + (size_t)r0 * KK + d0);
            ql_[m][ks][1] = *(const uint32_t*)(Qlb + (size_t)r1 * KK + d0);
            ql_[m][ks][2] = *(const uint32_t*)(Qlb + (size_t)r0 * KK + d0 + 8);
            ql_[m][ks][3] = *(const uint32_t*)(Qlb + (size_t)r1 * KK + d0 + 8);
        }
    }

    float o[2][8][4];
#pragma unroll
    for (int m = 0; m < 2; m++)
#pragma unroll
        for (int nt = 0; nt < 8; nt++)
#pragma unroll
            for (int c = 0; c < 4; c++) o[m][nt][c] = 0.f;
    float mr[2][2] = { {-1e30f, -1e30f}, {-1e30f, -1e30f} };
    float lr[2][2] = { {0.f, 0.f}, {0.f, 0.f} };

    const __nv_bfloat16* Khb = Kh_ + (size_t)b * TT * KK + h * SS;
    const __nv_bfloat16* Klb = Kl_ + (size_t)b * TT * KK + h * SS;
    const __half*        Vfb = Vf_ + (size_t)b * TT * KK + h * SS;

    // V ldmatrix.trans per-lane base (bytes): row = key (lane&15), d-half (lane&16)
    const uint32_t vlb = (uint32_t)((lane & 15) * AST + ((lane & 16) ? 8 : 0)) * 2;

    // cp.async issue: 64 rows x 8 chunks of 16B per array, 128 threads -> 4 iters
#define AISSUE(kt, st) do { \
    uint32_t sd = sbase + (uint32_t)(st) * ASTAGE; \
    _Pragma("unroll") \
    for (int i = 0; i < 4; i++) { \
        int ix = i * 128 + tid; int row = ix >> 3; int ch = ix & 7; \
        uint32_t dd = sd + (uint32_t)(row * AST * 2 + ch * 16); \
        const __nv_bfloat16* s0 = Khb + (size_t)((kt) * 64 + row) * KK + ch * 8; \
        const __nv_bfloat16* s1 = Klb + (size_t)((kt) * 64 + row) * KK + ch * 8; \
        const __half*        s2 = Vfb + (size_t)((kt) * 64 + row) * KK + ch * 8; \
        asm volatile("cp.async.cg.shared.global [%0], [%1], 16;" :: "r"(dd), "l"(s0)); \
        asm volatile("cp.async.cg.shared.global [%0], [%1], 16;" :: "r"(dd + KVTILE), "l"(s1)); \
        asm volatile("cp.async.cg.shared.global [%0], [%1], 16;" :: "r"(dd + 2 * KVTILE), "l"(s2)); \
    } \
    asm volatile("cp.async.commit_group;"); \
} while (0)

    AISSUE(0, 0);

    for (int kt = 0; kt < ntiles; kt++) {
        const int st = kt & 1;
        __syncthreads();   // all warps done reading stage st (from tile kt-2 era / prev compute)
        if (kt + 1 < ntiles) {
            AISSUE(kt + 1, st ^ 1);
            asm volatile("cp.async.wait_group 1;");
        } else {
            asm volatile("cp.async.wait_group 0;");
        }
        __syncthreads();   // stage st data visible to all

        const char* stage = asmem + st * ASTAGE;
        const __nv_bfloat16* kh = (const __nv_bfloat16*)stage;
        const __nv_bfloat16* kl = (const __nv_bfloat16*)(stage + KVTILE);
        const uint32_t vbase = sbase + (uint32_t)st * ASTAGE + 2 * KVTILE;

        // ---- S = Q K^T (bf16 3-term) ----
        float s[2][8][4];
#pragma unroll
        for (int m = 0; m < 2; m++)
#pragma unroll
            for (int nt = 0; nt < 8; nt++)
#pragma unroll
                for (int c = 0; c < 4; c++) s[m][nt][c] = 0.f;

#pragma unroll
        for (int ks = 0; ks < 4; ks++) {
            const int kk = ks * 16 + 2 * tg;
#pragma unroll
            for (int nt = 0; nt < 8; nt++) {
                const int rr = (nt * 8 + g) * AST + kk;
                uint32_t bh0 = *(const uint32_t*)&kh[rr];
                uint32_t bh1 = *(const uint32_t*)&kh[rr + 8];
                uint32_t bl0 = *(const uint32_t*)&kl[rr];
                uint32_t bl1 = *(const uint32_t*)&kl[rr + 8];
#pragma unroll
                for (int m = 0; m < 2; m++) {
                    mma_bf16(s[m][nt], qh_[m][ks][0], qh_[m][ks][1], qh_[m][ks][2], qh_[m][ks][3], bh0, bh1);
                    mma_bf16(s[m][nt], qh_[m][ks][0], qh_[m][ks][1], qh_[m][ks][2], qh_[m][ks][3], bl0, bl1);
                    mma_bf16(s[m][nt], ql_[m][ks][0], ql_[m][ks][1], ql_[m][ks][2], ql_[m][ks][3], bh0, bh1);
                }
            }
        }

        // ---- tail masking ----
        if (kt * 64 + 64 > nvb) {
#pragma unroll
            for (int nt = 0; nt < 8; nt++) {
                int c0 = kt * 64 + nt * 8 + 2 * tg;
                if (c0 >= nvb) {
                    s[0][nt][0] = s[0][nt][2] = -1e30f;
                    s[1][nt][0] = s[1][nt][2] = -1e30f;
                }
                if (c0 + 1 >= nvb) {
                    s[0][nt][1] = s[0][nt][3] = -1e30f;
                    s[1][nt][1] = s[1][nt][3] = -1e30f;
                }
            }
        }

        // ---- online softmax ----
#pragma unroll
        for (int m = 0; m < 2; m++) {
#pragma unroll
            for (int r2 = 0; r2 < 2; r2++) {
                const int c0 = r2 * 2;
                float tmax = -1e30f;
#pragma unroll
                for (int nt = 0; nt < 8; nt++) {
                    tmax = fmaxf(tmax, s[m][nt][c0]);
                    tmax = fmaxf(tmax, s[m][nt][c0 + 1]);
                }
                tmax = fmaxf(tmax, __shfl_xor_sync(0xffffffffu, tmax, 1));
                tmax = fmaxf(tmax, __shfl_xor_sync(0xffffffffu, tmax, 2));
                float mn = fmaxf(mr[m][r2], tmax);
                float sc = __expf(mr[m][r2] - mn);
                mr[m][r2] = mn;
                float ts = 0.f;
#pragma unroll
                for (int nt = 0; nt < 8; nt++) {
                    float p0 = __expf(s[m][nt][c0]     - mn);
                    float p1 = __expf(s[m][nt][c0 + 1] - mn);
                    s[m][nt][c0]     = p0;
                    s[m][nt][c0 + 1] = p1;
                    ts += p0 + p1;
                }
                ts += __shfl_xor_sync(0xffffffffu, ts, 1);
                ts += __shfl_xor_sync(0xffffffffu, ts, 2);
                lr[m][r2] = lr[m][r2] * sc + ts;
#pragma unroll
                for (int nt = 0; nt < 8; nt++) {
                    o[m][nt][c0]     *= sc;
                    o[m][nt][c0 + 1] *= sc;
                }
            }
        }

        // ---- O += P V: V fragments via ldmatrix.x4.trans on row-major V ----
#pragma unroll
        for (int ks = 0; ks < 4; ks++) {
            uint32_t ph[2][4];
#pragma unroll
            for (int m = 0; m < 2; m++) {
                ph[m][0] = pack_h2(make_float2(s[m][2*ks][0],   s[m][2*ks][1]));
                ph[m][1] = pack_h2(make_float2(s[m][2*ks][2],   s[m][2*ks][3]));
                ph[m][2] = pack_h2(make_float2(s[m][2*ks+1][0], s[m][2*ks+1][1]));
                ph[m][3] = pack_h2(make_float2(s[m][2*ks+1][2], s[m][2*ks+1][3]));
            }
            const uint32_t krow = (uint32_t)(ks * 16 * AST * 2);
#pragma unroll
            for (int dp = 0; dp < 4; dp++) {
                uint32_t v0, v1, v2, v3;
                LDSM4T(v0, v1, v2, v3, vbase + krow + (uint32_t)(dp * 32) + vlb);
#pragma unroll
                for (int m = 0; m < 2; m++) {
                    mma_f16f32(o[m][2*dp],     ph[m][0], ph[m][1], ph[m][2], ph[m][3], v0, v1);
                    mma_f16f32(o[m][2*dp + 1], ph[m][0], ph[m][1], ph[m][2], ph[m][3], v2, v3);
                }
            }
        }
    }
#undef AISSUE

    // ---- epilogue: normalize, emit fp16 ----
#pragma unroll
    for (int m = 0; m < 2; m++) {
#pragma unroll
        for (int r2 = 0; r2 < 2; r2++) {
            float inv = 1.f / lr[m][r2];
            int row = q0 + w * 32 + m * 16 + g + r2 * 8;
            size_t off = (size_t)(b * TT + row) * KK + h * SS;
#pragma unroll
            for (int nt = 0; nt < 8; nt++) {
                *(uint32_t*)&ysf[off + nt * 8 + 2 * tg] =
                    pack_h2(make_float2(o[m][nt][r2*2] * inv, o[m][nt][r2*2+1] * inv));
            }
        }
    }
}

// ============================================================================
// launch
// ============================================================================
extern "C" void kernel_launch(void* const* d_in, const int* in_sizes, int n_in,
                              void* d_out, int out_size)
{
    const float* x    = (const float*)d_in[0];
    const int*   mask = (const int*)  d_in[1];
    const float* Wk   = (const float*)d_in[2];
    const float* Wq   = (const float*)d_in[3];
    const float* Wv   = (const float*)d_in[4];
    const float* Wu   = (const float*)d_in[5];
    const float* bu   = (const float*)d_in[6];
    float* out = (float*)d_out;

    __nv_bfloat16 *Qh, *Ql, *Kh, *Kl;
    __half *Wuf, *Vf, *ysf;
    int *idx, *nv;
    cudaGetSymbolAddress((void**)&Qh,  g_Qh);  cudaGetSymbolAddress((void**)&Ql,  g_Ql);
    cudaGetSymbolAddress((void**)&Kh,  g_Kh);  cudaGetSymbolAddress((void**)&Kl,  g_Kl);
    cudaGetSymbolAddress((void**)&Wuf, g_Wuf);
    cudaGetSymbolAddress((void**)&Vf,  g_Vf);  cudaGetSymbolAddress((void**)&ysf, g_ysf);
    cudaGetSymbolAddress((void**)&idx, g_idx); cudaGetSymbolAddress((void**)&nv,  g_nv);

    cudaFuncSetAttribute(proj_kernel,
                         cudaFuncAttributeMaxDynamicSharedMemorySize, PROJ_SMEM);
    cudaFuncSetAttribute(gemm1_kernel,
                         cudaFuncAttributeMaxDynamicSharedMemorySize, G1SMEM);
    cudaFuncSetAttribute(attn_tc_kernel,
                         cudaFuncAttributeMaxDynamicSharedMemorySize, ATTN_SMEM);

    compact_kernel<<<BB, 1024>>>(mask, idx, nv);
    prep_wu_kernel<<<KK * KK / 2 / 256, 256>>>(Wu, Wuf);

    dim3 gp(KK / 128, MROWS / 128, 3);   // (8, 32, 3): z = Q/K/V
    proj_kernel<<<gp, 256, PROJ_SMEM>>>(x, Wq, Wk, Wv, idx, nv,
                                        Qh, Ql, Kh, Kl, Vf);

    dim3 ga(TT / 128, HH, BB);           // (16, 16, 2)
    attn_tc_kernel<<<ga, 128, ATTN_SMEM>>>(Qh, Ql, Kh, Kl, Vf, nv, ysf);

    dim3 gu(KK / 128, MROWS / 128);      // (8, 32)
    gemm1_kernel<<<gu, 256, G1SMEM>>>(ysf, Wuf, bu, out, MROWS, KK);
}

// round 15
// speedup vs baseline: 3.0499x; 1.0175x over previous
#include <cuda_runtime.h>
#include <cuda_bf16.h>
#include <cuda_fp16.h>
#include <cstdint>

#define BB   2
#define TT   2048
#define KK   1024
#define HH   16
#define SS   64
#define MROWS (BB*TT)   // 4096
#define INV2048 4.8828125e-4f

// ---- scratch (static device globals; no allocation allowed) ----
__device__ __nv_bfloat16 g_Qh[MROWS*KK], g_Ql[MROWS*KK];
__device__ __nv_bfloat16 g_Kh[MROWS*KK], g_Kl[MROWS*KK];      // compacted K
__device__ __half g_Wuf[KK*KK];
__device__ __half g_Vf [MROWS*KK];                             // compacted V
__device__ __half g_ysf[MROWS*KK];
__device__ int g_idx[BB*TT];
__device__ int g_nv [BB];

// ============================================================================
// helpers
// ============================================================================
__device__ __forceinline__ uint32_t smem_u32(const void* p) {
    uint32_t a;
    asm("{ .reg .u64 t; cvta.to.shared.u64 t, %1; cvt.u32.u64 %0, t; }"
        : "=r"(a) : "l"(p));
    return a;
}

__device__ __forceinline__ void mma_bf16(float d[4],
                                         uint32_t a0, uint32_t a1, uint32_t a2, uint32_t a3,
                                         uint32_t b0, uint32_t b1) {
    asm volatile(
        "mma.sync.aligned.m16n8k16.row.col.f32.bf16.bf16.f32 "
        "{%0,%1,%2,%3}, {%4,%5,%6,%7}, {%8,%9}, {%0,%1,%2,%3};"
        : "+f"(d[0]), "+f"(d[1]), "+f"(d[2]), "+f"(d[3])
        : "r"(a0), "r"(a1), "r"(a2), "r"(a3), "r"(b0), "r"(b1));
}

__device__ __forceinline__ void mma_f16f32(float d[4],
                                           uint32_t a0, uint32_t a1, uint32_t a2, uint32_t a3,
                                           uint32_t b0, uint32_t b1) {
    asm volatile(
        "mma.sync.aligned.m16n8k16.row.col.f32.f16.f16.f32 "
        "{%0,%1,%2,%3}, {%4,%5,%6,%7}, {%8,%9}, {%0,%1,%2,%3};"
        : "+f"(d[0]), "+f"(d[1]), "+f"(d[2]), "+f"(d[3])
        : "r"(a0), "r"(a1), "r"(a2), "r"(a3), "r"(b0), "r"(b1));
}

#define LDSM4(r0, r1, r2, r3, addr) \
    asm volatile("ldmatrix.sync.aligned.m8n8.x4.shared.b16 {%0,%1,%2,%3}, [%4];" \
                 : "=r"(r0), "=r"(r1), "=r"(r2), "=r"(r3) : "r"(addr))

#define LDSM4T(r0, r1, r2, r3, addr) \
    asm volatile("ldmatrix.sync.aligned.m8n8.x4.trans.shared.b16 {%0,%1,%2,%3}, [%4];" \
                 : "=r"(r0), "=r"(r1), "=r"(r2), "=r"(r3) : "r"(addr))

__device__ __forceinline__ void split2(float2 f, uint32_t& h, uint32_t& l) {
    __nv_bfloat162 hh = __float22bfloat162_rn(f);
    float2 hf = __bfloat1622float2(hh);
    __nv_bfloat162 ll = __float22bfloat162_rn(make_float2(f.x - hf.x, f.y - hf.y));
    h = *(uint32_t*)&hh;
    l = *(uint32_t*)&ll;
}

__device__ __forceinline__ void split2h(float2 f, uint32_t& h, uint32_t& l) {
    __half2 hh = __float22half2_rn(f);
    float2 hf = __half22float2(hh);
    __half2 ll = __float22half2_rn(make_float2((f.x - hf.x) * 2048.f,
                                               (f.y - hf.y) * 2048.f));
    h = *(uint32_t*)&hh;
    l = *(uint32_t*)&ll;
}

__device__ __forceinline__ uint32_t pack_h2(float2 f) {
    __half2 hh = __float22half2_rn(f);
    return *(uint32_t*)&hh;
}

// ============================================================================
// merged: mask compaction (blocks 0..1) + Wu fp32->fp16 (blocks 2..)
// ============================================================================
__global__ __launch_bounds__(1024)
void compact_prep_kernel(const int* __restrict__ mask, int* __restrict__ idx,
                         int* __restrict__ nv,
                         const float* __restrict__ Wu, __half* __restrict__ Wuf)
{
    if (blockIdx.x >= 2) {
        int i = (blockIdx.x - 2) * 1024 + threadIdx.x;   // over KK*KK/2 float2
        ((uint32_t*)Wuf)[i] = pack_h2(((const float2*)Wu)[i]);
        return;
    }
    __shared__ int s[1024];
    const int b = blockIdx.x;
    const int t = threadIdx.x;
    const int m0 = mask[b * TT + 2 * t];
    const int m1 = mask[b * TT + 2 * t + 1];
    const int c  = m0 + m1;
    s[t] = c;
    __syncthreads();
    for (int off = 1; off < 1024; off <<= 1) {
        int v = s[t];
        int u = (t >= off) ? s[t - off] : 0;
        __syncthreads();
        s[t] = v + u;
        __syncthreads();
    }
    const int incl = s[t];
    const int excl = incl - c;
    if (m0) idx[b * TT + excl] = 2 * t;
    if (m1) idx[b * TT + excl + m0] = 2 * t + 1;
    if (t == 1023) nv[b] = incl;
}

// ============================================================================
// common GEMM geometry
// ============================================================================
#define GBK 32
#define NIT (KK / GBK)          // 32
#define BKP 40
#define ATILE (128 * BKP)
#define PROJ_SMEM (8 * ATILE * 2)   // 81920 B

// ============================================================================
// Fused Q/K/V projection kernel, FLAT LPT-ordered grid (768 CTAs):
//   bid [0,256):   K-tiles (3 MMA units, heaviest first; ~half early-exit)
//   bid [256,512): Q-tiles (2 units, all active)
//   bid [512,768): V-tiles (1 unit, lightest last; ~half early-exit)
// 32 m-tiles x 8 n-tiles per matrix.
// ============================================================================
__global__ void __launch_bounds__(256)
proj_kernel(const float* __restrict__ x,
            const float* __restrict__ Wq,
            const float* __restrict__ Wk,
            const float* __restrict__ Wv,
            const int* __restrict__ idx,
            const int* __restrict__ nvp,
            __nv_bfloat16* __restrict__ Qh, __nv_bfloat16* __restrict__ Ql,
            __nv_bfloat16* __restrict__ Kh, __nv_bfloat16* __restrict__ Kl,
            __half* __restrict__ Vf)
{
    extern __shared__ char smraw[];
    __shared__ int sidx[128];
    const uint32_t sbase = smem_u32(smraw);

    const int bid = blockIdx.x;
    int z, lbid;
    if (bid < 256)      { z = 1; lbid = bid; }
    else if (bid < 512) { z = 0; lbid = bid - 256; }
    else                { z = 2; lbid = bid - 512; }
    const int mt    = lbid >> 3;    // 0..31
    const int ntile = lbid & 7;     // 0..7

    const int tid  = threadIdx.x;
    const int lane = tid & 31;
    const int wid  = tid >> 5;
    const int g    = lane >> 2;
    const int tg   = lane & 3;
    const int wm   = wid & 1;
    const int wn   = wid >> 1;
    const int m0   = mt * 128;
    const int n0   = ntile * 128;

    if (z >= 1) {
        const int b = m0 / TT;
        const int s = m0 - b * TT;
        const int nvb = nvp[b];
        if (s >= nvb) return;
        if (tid < 128) {
            int ss = s + tid;
            sidx[tid] = b * TT + idx[b * TT + (ss < nvb ? ss : 0)];
        }
        __syncthreads();
    }

    const uint32_t aoff = (uint32_t)((wm * 64 + (lane & 15)) * BKP + ((lane & 16) ? 8 : 0));
    const uint32_t boff = (uint32_t)((wn * 32 + (lane & 7) + ((lane & 16) ? 8 : 0)) * BKP
                                     + ((lane & 8) ? 8 : 0));

    float4 ra[4], rb[4];

    if (z == 0) {
        const float* Agp = x  + (size_t)m0 * KK;
        const float* Bgp = Wq + (size_t)n0 * KK;

#define QLOAD(k0) do { \
    _Pragma("unroll") \
    for (int j = 0; j < 4; j++) { \
        int ix = j * 256 + tid; int row = ix >> 3; int c4 = ix & 7; \
        ra[j] = *(const float4*)(Agp + (size_t)row * KK + (k0) + c4 * 4); \
        rb[j] = *(const float4*)(Bgp + (size_t)row * KK + (k0) + c4 * 4); \
    } } while (0)

#define QSTORE(bsel) do { \
    _Pragma("unroll") \
    for (int j = 0; j < 4; j++) { \
        int ix = j * 256 + tid; int row = ix >> 3; int c4 = ix & 7; \
        uint32_t off = (uint32_t)((bsel) * 3 * ATILE + row * BKP + c4 * 4) * 2; \
        uint32_t h0, l0, h1, l1; \
        split2h(make_float2(ra[j].x, ra[j].y), h0, l0); \
        split2h(make_float2(ra[j].z, ra[j].w), h1, l1); \
        *(uint32_t*)(smraw + off)                 = h0; \
        *(uint32_t*)(smraw + off + 4)             = h1; \
        *(uint32_t*)(smraw + off + ATILE * 2)     = l0; \
        *(uint32_t*)(smraw + off + ATILE * 2 + 4) = l1; \
        *(uint32_t*)(smraw + off + 2 * ATILE * 2)     = pack_h2(make_float2(rb[j].x, rb[j].y)); \
        *(uint32_t*)(smraw + off + 2 * ATILE * 2 + 4) = pack_h2(make_float2(rb[j].z, rb[j].w)); \
    } } while (0)

        float acc [4][4][4];
        float acc2[4][4][4];
#pragma unroll
        for (int i = 0; i < 4; i++)
#pragma unroll
            for (int j = 0; j < 4; j++)
#pragma unroll
                for (int r = 0; r < 4; r++) { acc[i][j][r] = 0.f; acc2[i][j][r] = 0.f; }

        QLOAD(0);
        QSTORE(0);
        __syncthreads();

        for (int it = 0; it < NIT; it++) {
            const int buf = it & 1;
            if (it + 1 < NIT) QLOAD((it + 1) * GBK);

            const uint32_t bb = sbase + (uint32_t)(buf * 3 * ATILE) * 2;
#pragma unroll
            for (int ks = 0; ks < 2; ks++) {
                const uint32_t ko = ks * 32;
                uint32_t bf[4][2];
                LDSM4(bf[0][0], bf[0][1], bf[1][0], bf[1][1],
                      bb + 2 * ATILE * 2 + boff * 2 + ko);
                LDSM4(bf[2][0], bf[2][1], bf[3][0], bf[3][1],
                      bb + 2 * ATILE * 2 + (boff + 16 * BKP) * 2 + ko);
#pragma unroll
                for (int mf = 0; mf < 4; mf++) {
                    uint32_t ah0, ah1, ah2, ah3, al0, al1, al2, al3;
                    LDSM4(ah0, ah1, ah2, ah3, bb + (aoff + mf * 16 * BKP) * 2 + ko);
                    LDSM4(al0, al1, al2, al3, bb + ATILE * 2 + (aoff + mf * 16 * BKP) * 2 + ko);
#pragma unroll
                    for (int nf = 0; nf < 4; nf++) {
                        mma_f16f32(acc [mf][nf], ah0, ah1, ah2, ah3, bf[nf][0], bf[nf][1]);
                        mma_f16f32(acc2[mf][nf], al0, al1, al2, al3, bf[nf][0], bf[nf][1]);
                    }
                }
            }

            if (it + 1 < NIT) {
                __syncthreads();
                QSTORE(buf ^ 1);
                __syncthreads();
            }
        }
#undef QLOAD
#undef QSTORE

#pragma unroll
        for (int mf = 0; mf < 4; mf++) {
            int r0 = m0 + wm * 64 + mf * 16 + g;
#pragma unroll
            for (int nf = 0; nf < 4; nf++) {
                int col = n0 + wn * 32 + nf * 8 + tg * 2;
                float v00 = acc[mf][nf][0] + acc2[mf][nf][0] * INV2048;
                float v01 = acc[mf][nf][1] + acc2[mf][nf][1] * INV2048;
                float v10 = acc[mf][nf][2] + acc2[mf][nf][2] * INV2048;
                float v11 = acc[mf][nf][3] + acc2[mf][nf][3] * INV2048;
                uint32_t h0, l0, h1, l1;
                split2(make_float2(v00, v01), h0, l0);
                split2(make_float2(v10, v11), h1, l1);
                *(uint32_t*)&Qh[(size_t)r0 * KK + col]       = h0;
                *(uint32_t*)&Ql[(size_t)r0 * KK + col]       = l0;
                *(uint32_t*)&Qh[(size_t)(r0 + 8) * KK + col] = h1;
                *(uint32_t*)&Ql[(size_t)(r0 + 8) * KK + col] = l1;
            }
        }

    } else if (z == 1) {
        const float* Bgp = Wk + (size_t)n0 * KK;

#define KLOAD(k0) do { \
    _Pragma("unroll") \
    for (int j = 0; j < 4; j++) { \
        int ix = j * 256 + tid; int row = ix >> 3; int c4 = ix & 7; \
        ra[j] = *(const float4*)(x + (size_t)sidx[row] * KK + (k0) + c4 * 4); \
        rb[j] = *(const float4*)(Bgp + (size_t)row * KK + (k0) + c4 * 4); \
    } } while (0)

#define KSTORE(bsel) do { \
    _Pragma("unroll") \
    for (int j = 0; j < 4; j++) { \
        int ix = j * 256 + tid; int row = ix >> 3; int c4 = ix & 7; \
        uint32_t off = (uint32_t)((bsel) * 4 * ATILE + row * BKP + c4 * 4) * 2; \
        uint32_t h0, l0, h1, l1; \
        split2(make_float2(ra[j].x, ra[j].y), h0, l0); \
        split2(make_float2(ra[j].z, ra[j].w), h1, l1); \
        *(uint32_t*)(smraw + off)                 = h0; \
        *(uint32_t*)(smraw + off + 4)             = h1; \
        *(uint32_t*)(smraw + off + ATILE * 2)     = l0; \
        *(uint32_t*)(smraw + off + ATILE * 2 + 4) = l1; \
        split2(make_float2(rb[j].x, rb[j].y), h0, l0); \
        split2(make_float2(rb[j].z, rb[j].w), h1, l1); \
        *(uint32_t*)(smraw + off + 2 * ATILE * 2)     = h0; \
        *(uint32_t*)(smraw + off + 2 * ATILE * 2 + 4) = h1; \
        *(uint32_t*)(smraw + off + 3 * ATILE * 2)     = l0; \
        *(uint32_t*)(smraw + off + 3 * ATILE * 2 + 4) = l1; \
    } } while (0)

        float acc[4][4][4];
#pragma unroll
        for (int i = 0; i < 4; i++)
#pragma unroll
            for (int j = 0; j < 4; j++)
#pragma unroll
                for (int r = 0; r < 4; r++) acc[i][j][r] = 0.f;

        KLOAD(0);
        KSTORE(0);
        __syncthreads();

        for (int it = 0; it < NIT; it++) {
            const int buf = it & 1;
            if (it + 1 < NIT) KLOAD((it + 1) * GBK);

            const uint32_t bb = sbase + (uint32_t)(buf * 4 * ATILE) * 2;
#pragma unroll
            for (int ks = 0; ks < 2; ks++) {
                const uint32_t ko = ks * 32;
                uint32_t bh[4][2], bl[4][2];
                LDSM4(bh[0][0], bh[0][1], bh[1][0], bh[1][1],
                      bb + 2 * ATILE * 2 + boff * 2 + ko);
                LDSM4(bh[2][0], bh[2][1], bh[3][0], bh[3][1],
                      bb + 2 * ATILE * 2 + (boff + 16 * BKP) * 2 + ko);
                LDSM4(bl[0][0], bl[0][1], bl[1][0], bl[1][1],
                      bb + 3 * ATILE * 2 + boff * 2 + ko);
                LDSM4(bl[2][0], bl[2][1], bl[3][0], bl[3][1],
                      bb + 3 * ATILE * 2 + (boff + 16 * BKP) * 2 + ko);
#pragma unroll
                for (int mf = 0; mf < 4; mf++) {
                    uint32_t ah0, ah1, ah2, ah3, al0, al1, al2, al3;
                    LDSM4(ah0, ah1, ah2, ah3, bb + (aoff + mf * 16 * BKP) * 2 + ko);
                    LDSM4(al0, al1, al2, al3, bb + ATILE * 2 + (aoff + mf * 16 * BKP) * 2 + ko);
#pragma unroll
                    for (int nf = 0; nf < 4; nf++) {
                        mma_bf16(acc[mf][nf], ah0, ah1, ah2, ah3, bh[nf][0], bh[nf][1]);
                        mma_bf16(acc[mf][nf], ah0, ah1, ah2, ah3, bl[nf][0], bl[nf][1]);
                        mma_bf16(acc[mf][nf], al0, al1, al2, al3, bh[nf][0], bh[nf][1]);
                    }
                }
            }

            if (it + 1 < NIT) {
                __syncthreads();
                KSTORE(buf ^ 1);
                __syncthreads();
            }
        }
#undef KLOAD
#undef KSTORE

#pragma unroll
        for (int mf = 0; mf < 4; mf++) {
            int r0 = m0 + wm * 64 + mf * 16 + g;
#pragma unroll
            for (int nf = 0; nf < 4; nf++) {
                int col = n0 + wn * 32 + nf * 8 + tg * 2;
                uint32_t h0, l0, h1, l1;
                split2(make_float2(acc[mf][nf][0], acc[mf][nf][1]), h0, l0);
                split2(make_float2(acc[mf][nf][2], acc[mf][nf][3]), h1, l1);
                *(uint32_t*)&Kh[(size_t)r0 * KK + col]       = h0;
                *(uint32_t*)&Kl[(size_t)r0 * KK + col]       = l0;
                *(uint32_t*)&Kh[(size_t)(r0 + 8) * KK + col] = h1;
                *(uint32_t*)&Kl[(size_t)(r0 + 8) * KK + col] = l1;
            }
        }

    } else {
        const float* Bgp = Wv + (size_t)n0 * KK;

#define VLOAD(k0) do { \
    _Pragma("unroll") \
    for (int j = 0; j < 4; j++) { \
        int ix = j * 256 + tid; int row = ix >> 3; int c4 = ix & 7; \
        ra[j] = *(const float4*)(x + (size_t)sidx[row] * KK + (k0) + c4 * 4); \
        rb[j] = *(const float4*)(Bgp + (size_t)row * KK + (k0) + c4 * 4); \
    } } while (0)

#define VSTORE(bsel) do { \
    _Pragma("unroll") \
    for (int j = 0; j < 4; j++) { \
        int ix = j * 256 + tid; int row = ix >> 3; int c4 = ix & 7; \
        uint32_t off = (uint32_t)((bsel) * 2 * ATILE + row * BKP + c4 * 4) * 2; \
        *(uint32_t*)(smraw + off)     = pack_h2(make_float2(ra[j].x, ra[j].y)); \
        *(uint32_t*)(smraw + off + 4) = pack_h2(make_float2(ra[j].z, ra[j].w)); \
        *(uint32_t*)(smraw + off + ATILE * 2)     = pack_h2(make_float2(rb[j].x, rb[j].y)); \
        *(uint32_t*)(smraw + off + ATILE * 2 + 4) = pack_h2(make_float2(rb[j].z, rb[j].w)); \
    } } while (0)

        float acc[4][4][4];
#pragma unroll
        for (int i = 0; i < 4; i++)
#pragma unroll
            for (int j = 0; j < 4; j++)
#pragma unroll
                for (int r = 0; r < 4; r++) acc[i][j][r] = 0.f;

        VLOAD(0);
        VSTORE(0);
        __syncthreads();

        for (int it = 0; it < NIT; it++) {
            const int buf = it & 1;
            if (it + 1 < NIT) VLOAD((it + 1) * GBK);

            const uint32_t bb = sbase + (uint32_t)(buf * 2 * ATILE) * 2;
#pragma unroll
            for (int ks = 0; ks < 2; ks++) {
                const uint32_t ko = ks * 32;
                uint32_t bf[4][2];
                LDSM4(bf[0][0], bf[0][1], bf[1][0], bf[1][1],
                      bb + ATILE * 2 + boff * 2 + ko);
                LDSM4(bf[2][0], bf[2][1], bf[3][0], bf[3][1],
                      bb + ATILE * 2 + (boff + 16 * BKP) * 2 + ko);
#pragma unroll
                for (int mf = 0; mf < 4; mf++) {
                    uint32_t a0, a1, a2, a3;
                    LDSM4(a0, a1, a2, a3, bb + (aoff + mf * 16 * BKP) * 2 + ko);
#pragma unroll
                    for (int nf = 0; nf < 4; nf++)
                        mma_f16f32(acc[mf][nf], a0, a1, a2, a3, bf[nf][0], bf[nf][1]);
                }
            }

            if (it + 1 < NIT) {
                __syncthreads();
                VSTORE(buf ^ 1);
                __syncthreads();
            }
        }
#undef VLOAD
#undef VSTORE

#pragma unroll
        for (int mf = 0; mf < 4; mf++) {
            int r0 = m0 + wm * 64 + mf * 16 + g;
#pragma unroll
            for (int nf = 0; nf < 4; nf++) {
                int col = n0 + wn * 32 + nf * 8 + tg * 2;
                *(uint32_t*)&Vf[(size_t)r0 * KK + col] =
                    pack_h2(make_float2(acc[mf][nf][0], acc[mf][nf][1]));
                *(uint32_t*)&Vf[(size_t)(r0 + 8) * KK + col] =
                    pack_h2(make_float2(acc[mf][nf][2], acc[mf][nf][3]));
            }
        }
    }
}

// ============================================================================
// gemm1: 1-term fp16 via cp.async (U projection). 2 CTAs/SM.
// ============================================================================
#define G1SMEM (4 * ATILE * 2)   // 40960 B

__global__ void __launch_bounds__(256, 2)
gemm1_kernel(const __half* __restrict__ Ag,
             const __half* __restrict__ Bg,
             const float* __restrict__ bias,
             float* __restrict__ Cf,
             int M, int N)
{
    extern __shared__ __half sm1[];
    const uint32_t sbase = smem_u32(sm1);

    const int tid  = threadIdx.x;
    const int lane = tid & 31;
    const int wid  = tid >> 5;
    const int g    = lane >> 2;
    const int tg   = lane & 3;
    const int wm   = wid & 1;
    const int wn   = wid >> 1;
    const int m0   = blockIdx.y * 128;
    const int n0   = blockIdx.x * 128;

    const __half* gsrc[2] = { Ag + (size_t)m0 * KK, Bg + (size_t)n0 * KK };

    const uint32_t aoff = (uint32_t)((wm * 64 + (lane & 15)) * BKP + ((lane & 16) ? 8 : 0));
    const uint32_t boff = (uint32_t)((wn * 32 + (lane & 7) + ((lane & 16) ? 8 : 0)) * BKP
                                     + ((lane & 8) ? 8 : 0));

#define G1ISSUE(k0, bsel) do { \
    _Pragma("unroll") \
    for (int a = 0; a < 2; a++) { \
        uint32_t sd = sbase + (uint32_t)(((bsel) * 2 + a) * ATILE) * 2; \
        _Pragma("unroll") \
        for (int j = 0; j < 2; j++) { \
            int row = j * 64 + (tid >> 2); int cc = tid & 3; \
            uint32_t s = sd + (uint32_t)(row * BKP + cc * 8) * 2; \
            const __half* gp = gsrc[a] + (size_t)row * KK + (k0) + cc * 8; \
            asm volatile("cp.async.cg.shared.global [%0], [%1], 16;" :: "r"(s), "l"(gp)); \
        } \
    } \
    asm volatile("cp.async.commit_group;"); \
} while (0)

    float acc[4][4][4];
#pragma unroll
    for (int i = 0; i < 4; i++)
#pragma unroll
        for (int j = 0; j < 4; j++)
#pragma unroll
            for (int r = 0; r < 4; r++) acc[i][j][r] = 0.f;

    G1ISSUE(0, 0);

    for (int it = 0; it < NIT; it++) {
        const int buf = it & 1;
        asm volatile("cp.async.wait_group 0;");
        __syncthreads();
        if (it + 1 < NIT) G1ISSUE((it + 1) * GBK, buf ^ 1);

        const uint32_t bb = sbase + (uint32_t)(buf * 2 * ATILE) * 2;
#pragma unroll
        for (int ks = 0; ks < 2; ks++) {
            const uint32_t ko = ks * 32;
            uint32_t bf[4][2];
            LDSM4(bf[0][0], bf[0][1], bf[1][0], bf[1][1],
                  bb + ATILE * 2 + boff * 2 + ko);
            LDSM4(bf[2][0], bf[2][1], bf[3][0], bf[3][1],
                  bb + ATILE * 2 + (boff + 16 * BKP) * 2 + ko);
#pragma unroll
            for (int mf = 0; mf < 4; mf++) {
                uint32_t a0, a1, a2, a3;
                LDSM4(a0, a1, a2, a3, bb + (aoff + mf * 16 * BKP) * 2 + ko);
#pragma unroll
                for (int nf = 0; nf < 4; nf++)
                    mma_f16f32(acc[mf][nf], a0, a1, a2, a3, bf[nf][0], bf[nf][1]);
            }
        }
    }
#undef G1ISSUE

#pragma unroll
    for (int mf = 0; mf < 4; mf++) {
        int r0 = m0 + wm * 64 + mf * 16 + g;
#pragma unroll
        for (int nf = 0; nf < 4; nf++) {
            int col = n0 + wn * 32 + nf * 8 + tg * 2;
            float b0 = __ldg(&bias[col]), b1 = __ldg(&bias[col + 1]);
            float2 o0 = { acc[mf][nf][0] + b0, acc[mf][nf][1] + b1 };
            float2 o1 = { acc[mf][nf][2] + b0, acc[mf][nf][3] + b1 };
            *(float2*)&Cf[(size_t)r0 * N + col]       = o0;
            *(float2*)&Cf[(size_t)(r0 + 8) * N + col] = o1;
        }
    }
}

// ============================================================================
// Flash attention (proven round-13 body).
// ============================================================================
#define AST 72
#define KVTILE (64 * AST * 2)
#define ASTAGE (3 * KVTILE)
#define ATTN_SMEM (2 * ASTAGE)

__global__ __launch_bounds__(128, 2)
void attn_tc_kernel(const __nv_bfloat16* __restrict__ Qh_,
                    const __nv_bfloat16* __restrict__ Ql_,
                    const __nv_bfloat16* __restrict__ Kh_,
                    const __nv_bfloat16* __restrict__ Kl_,
                    const __half* __restrict__ Vf_,
                    const int* __restrict__ nvp,
                    __half* __restrict__ ysf)
{
    extern __shared__ char asmem[];
    const uint32_t sbase = smem_u32(asmem);

    const int tid  = threadIdx.x;
    const int lane = tid & 31;
    const int w    = tid >> 5;
    const int g    = lane >> 2;
    const int tg   = lane & 3;
    const int b    = blockIdx.z;
    const int h    = blockIdx.y;
    const int q0   = blockIdx.x * 128;

    const int nvb    = nvp[b];
    const int ntiles = (nvb + 63) >> 6;

    const __nv_bfloat16* Qhb = Qh_ + (size_t)(b * TT + q0 + w * 32) * KK + h * SS;
    const __nv_bfloat16* Qlb = Ql_ + (size_t)(b * TT + q0 + w * 32) * KK + h * SS;
    uint32_t qh_[2][4][4], ql_[2][4][4];
#pragma unroll
    for (int m = 0; m < 2; m++) {
#pragma unroll
        for (int ks = 0; ks < 4; ks++) {
            int r0 = m * 16 + g, r1 = r0 + 8;
            int d0 = ks * 16 + 2 * tg;
            qh_[m][ks][0] = *(const uint32_t*)(Qhb + (size_t)r0 * KK + d0);
            qh_[m][ks][1] = *(const uint32_t*)(Qhb + (size_t)r1 * KK + d0);
            qh_[m][ks][2] = *(const uint32_t*)(Qhb + (size_t)r0 * KK + d0 + 8);
            qh_[m][ks][3] = *(const uint32_t*)(Qhb + (size_t)r1 * KK + d0 + 8);
            ql_[m][ks][0] = *(const uint32_t*)(Qlb + (size_t)r0 * KK + d0);
            ql_[m][ks][1] = *(const uint32_t*)(Qlb + (size_t)r1 * KK + d0);
            ql_[m][ks][2] = *(const uint32_t*)(Qlb + (size_t)r0 * KK + d0 + 8);
            ql_[m][ks][3] = *(const uint32_t*)(Qlb + (size_t)r1 * KK + d0 + 8);
        }
    }

    float o[2][8][4];
#pragma unroll
    for (int m = 0; m < 2; m++)
#pragma unroll
        for (int nt = 0; nt < 8; nt++)
#pragma unroll
            for (int c = 0; c < 4; c++) o[m][nt][c] = 0.f;
    float mr[2][2] = { {-1e30f, -1e30f}, {-1e30f, -1e30f} };
    float lr[2][2] = { {0.f, 0.f}, {0.f, 0.f} };

    const __nv_bfloat16* Khb = Kh_ + (size_t)b * TT * KK + h * SS;
    const __nv_bfloat16* Klb = Kl_ + (size_t)b * TT * KK + h * SS;
    const __half*        Vfb = Vf_ + (size_t)b * TT * KK + h * SS;

    const uint32_t vlb = (uint32_t)((lane & 15) * AST + ((lane & 16) ? 8 : 0)) * 2;

#define AISSUE(kt, st) do { \
    uint32_t sd = sbase + (uint32_t)(st) * ASTAGE; \
    _Pragma("unroll") \
    for (int i = 0; i < 4; i++) { \
        int ix = i * 128 + tid; int row = ix >> 3; int ch = ix & 7; \
        uint32_t dd = sd + (uint32_t)(row * AST * 2 + ch * 16); \
        const __nv_bfloat16* s0 = Khb + (size_t)((kt) * 64 + row) * KK + ch * 8; \
        const __nv_bfloat16* s1 = Klb + (size_t)((kt) * 64 + row) * KK + ch * 8; \
        const __half*        s2 = Vfb + (size_t)((kt) * 64 + row) * KK + ch * 8; \
        asm volatile("cp.async.cg.shared.global [%0], [%1], 16;" :: "r"(dd), "l"(s0)); \
        asm volatile("cp.async.cg.shared.global [%0], [%1], 16;" :: "r"(dd + KVTILE), "l"(s1)); \
        asm volatile("cp.async.cg.shared.global [%0], [%1], 16;" :: "r"(dd + 2 * KVTILE), "l"(s2)); \
    } \
    asm volatile("cp.async.commit_group;"); \
} while (0)

    AISSUE(0, 0);

    for (int kt = 0; kt < ntiles; kt++) {
        const int st = kt & 1;
        __syncthreads();
        if (kt + 1 < ntiles) {
            AISSUE(kt + 1, st ^ 1);
            asm volatile("cp.async.wait_group 1;");
        } else {
            asm volatile("cp.async.wait_group 0;");
        }
        __syncthreads();

        const char* stage = asmem + st * ASTAGE;
        const __nv_bfloat16* kh = (const __nv_bfloat16*)stage;
        const __nv_bfloat16* kl = (const __nv_bfloat16*)(stage + KVTILE);
        const uint32_t vbase = sbase + (uint32_t)st * ASTAGE + 2 * KVTILE;

        float s[2][8][4];
#pragma unroll
        for (int m = 0; m < 2; m++)
#pragma unroll
            for (int nt = 0; nt < 8; nt++)
#pragma unroll
                for (int c = 0; c < 4; c++) s[m][nt][c] = 0.f;

#pragma unroll
        for (int ks = 0; ks < 4; ks++) {
            const int kk = ks * 16 + 2 * tg;
#pragma unroll
            for (int nt = 0; nt < 8; nt++) {
                const int rr = (nt * 8 + g) * AST + kk;
                uint32_t bh0 = *(const uint32_t*)&kh[rr];
                uint32_t bh1 = *(const uint32_t*)&kh[rr + 8];
                uint32_t bl0 = *(const uint32_t*)&kl[rr];
                uint32_t bl1 = *(const uint32_t*)&kl[rr + 8];
#pragma unroll
                for (int m = 0; m < 2; m++) {
                    mma_bf16(s[m][nt], qh_[m][ks][0], qh_[m][ks][1], qh_[m][ks][2], qh_[m][ks][3], bh0, bh1);
                    mma_bf16(s[m][nt], qh_[m][ks][0], qh_[m][ks][1], qh_[m][ks][2], qh_[m][ks][3], bl0, bl1);
                    mma_bf16(s[m][nt], ql_[m][ks][0], ql_[m][ks][1], ql_[m][ks][2], ql_[m][ks][3], bh0, bh1);
                }
            }
        }

        if (kt * 64 + 64 > nvb) {
#pragma unroll
            for (int nt = 0; nt < 8; nt++) {
                int c0 = kt * 64 + nt * 8 + 2 * tg;
                if (c0 >= nvb) {
                    s[0][nt][0] = s[0][nt][2] = -1e30f;
                    s[1][nt][0] = s[1][nt][2] = -1e30f;
                }
                if (c0 + 1 >= nvb) {
                    s[0][nt][1] = s[0][nt][3] = -1e30f;
                    s[1][nt][1] = s[1][nt][3] = -1e30f;
                }
            }
        }

#pragma unroll
        for (int m = 0; m < 2; m++) {
#pragma unroll
            for (int r2 = 0; r2 < 2; r2++) {
                const int c0 = r2 * 2;
                float tmax = -1e30f;
#pragma unroll
                for (int nt = 0; nt < 8; nt++) {
                    tmax = fmaxf(tmax, s[m][nt][c0]);
                    tmax = fmaxf(tmax, s[m][nt][c0 + 1]);
                }
                tmax = fmaxf(tmax, __shfl_xor_sync(0xffffffffu, tmax, 1));
                tmax = fmaxf(tmax, __shfl_xor_sync(0xffffffffu, tmax, 2));
                float mn = fmaxf(mr[m][r2], tmax);
                float sc = __expf(mr[m][r2] - mn);
                mr[m][r2] = mn;
                float ts = 0.f;
#pragma unroll
                for (int nt = 0; nt < 8; nt++) {
                    float p0 = __expf(s[m][nt][c0]     - mn);
                    float p1 = __expf(s[m][nt][c0 + 1] - mn);
                    s[m][nt][c0]     = p0;
                    s[m][nt][c0 + 1] = p1;
                    ts += p0 + p1;
                }
                ts += __shfl_xor_sync(0xffffffffu, ts, 1);
                ts += __shfl_xor_sync(0xffffffffu, ts, 2);
                lr[m][r2] = lr[m][r2] * sc + ts;
#pragma unroll
                for (int nt = 0; nt < 8; nt++) {
                    o[m][nt][c0]     *= sc;
                    o[m][nt][c0 + 1] *= sc;
                }
            }
        }

#pragma unroll
        for (int ks = 0; ks < 4; ks++) {
            uint32_t ph[2][4];
#pragma unroll
            for (int m = 0; m < 2; m++) {
                ph[m][0] = pack_h2(make_float2(s[m][2*ks][0],   s[m][2*ks][1]));
                ph[m][1] = pack_h2(make_float2(s[m][2*ks][2],   s[m][2*ks][3]));
                ph[m][2] = pack_h2(make_float2(s[m][2*ks+1][0], s[m][2*ks+1][1]));
                ph[m][3] = pack_h2(make_float2(s[m][2*ks+1][2], s[m][2*ks+1][3]));
            }
            const uint32_t krow = (uint32_t)(ks * 16 * AST * 2);
#pragma unroll
            for (int dp = 0; dp < 4; dp++) {
                uint32_t v0, v1, v2, v3;
                LDSM4T(v0, v1, v2, v3, vbase + krow + (uint32_t)(dp * 32) + vlb);
#pragma unroll
                for (int m = 0; m < 2; m++) {
                    mma_f16f32(o[m][2*dp],     ph[m][0], ph[m][1], ph[m][2], ph[m][3], v0, v1);
                    mma_f16f32(o[m][2*dp + 1], ph[m][0], ph[m][1], ph[m][2], ph[m][3], v2, v3);
                }
            }
        }
    }
#undef AISSUE

#pragma unroll
    for (int m = 0; m < 2; m++) {
#pragma unroll
        for (int r2 = 0; r2 < 2; r2++) {
            float inv = 1.f / lr[m][r2];
            int row = q0 + w * 32 + m * 16 + g + r2 * 8;
            size_t off = (size_t)(b * TT + row) * KK + h * SS;
#pragma unroll
            for (int nt = 0; nt < 8; nt++) {
                *(uint32_t*)&ysf[off + nt * 8 + 2 * tg] =
                    pack_h2(make_float2(o[m][nt][r2*2] * inv, o[m][nt][r2*2+1] * inv));
            }
        }
    }
}

// ============================================================================
// launch
// ============================================================================
extern "C" void kernel_launch(void* const* d_in, const int* in_sizes, int n_in,
                              void* d_out, int out_size)
{
    const float* x    = (const float*)d_in[0];
    const int*   mask = (const int*)  d_in[1];
    const float* Wk   = (const float*)d_in[2];
    const float* Wq   = (const float*)d_in[3];
    const float* Wv   = (const float*)d_in[4];
    const float* Wu   = (const float*)d_in[5];
    const float* bu   = (const float*)d_in[6];
    float* out = (float*)d_out;

    __nv_bfloat16 *Qh, *Ql, *Kh, *Kl;
    __half *Wuf, *Vf, *ysf;
    int *idx, *nv;
    cudaGetSymbolAddress((void**)&Qh,  g_Qh);  cudaGetSymbolAddress((void**)&Ql,  g_Ql);
    cudaGetSymbolAddress((void**)&Kh,  g_Kh);  cudaGetSymbolAddress((void**)&Kl,  g_Kl);
    cudaGetSymbolAddress((void**)&Wuf, g_Wuf);
    cudaGetSymbolAddress((void**)&Vf,  g_Vf);  cudaGetSymbolAddress((void**)&ysf, g_ysf);
    cudaGetSymbolAddress((void**)&idx, g_idx); cudaGetSymbolAddress((void**)&nv,  g_nv);

    cudaFuncSetAttribute(proj_kernel,
                         cudaFuncAttributeMaxDynamicSharedMemorySize, PROJ_SMEM);
    cudaFuncSetAttribute(gemm1_kernel,
                         cudaFuncAttributeMaxDynamicSharedMemorySize, G1SMEM);
    cudaFuncSetAttribute(attn_tc_kernel,
                         cudaFuncAttributeMaxDynamicSharedMemorySize, ATTN_SMEM);

    // blocks 0-1: mask compaction; blocks 2..513: Wu fp32->fp16
    compact_prep_kernel<<<2 + KK * KK / 2 / 1024, 1024>>>(mask, idx, nv, Wu, Wuf);

    // LPT-ordered flat grid: 256 K-tiles, 256 Q-tiles, 256 V-tiles
    proj_kernel<<<768, 256, PROJ_SMEM>>>(x, Wq, Wk, Wv, idx, nv,
                                         Qh, Ql, Kh, Kl, Vf);

    dim3 ga(TT / 128, HH, BB);           // (16, 16, 2)
    attn_tc_kernel<<<ga, 128, ATTN_SMEM>>>(Qh, Ql, Kh, Kl, Vf, nv, ysf);

    dim3 gu(KK / 128, MROWS / 128);      // (8, 32)
    gemm1_kernel<<<gu, 256, G1SMEM>>>(ysf, Wuf, bu, out, MROWS, KK);
}

// round 16
// speedup vs baseline: 3.0579x; 1.0026x over previous
#include <cuda_runtime.h>
#include <cuda_bf16.h>
#include <cuda_fp16.h>
#include <cstdint>

#define BB   2
#define TT   2048
#define KK   1024
#define HH   16
#define SS   64
#define MROWS (BB*TT)   // 4096
#define INV2048 4.8828125e-4f

// ---- scratch (static device globals; no allocation allowed) ----
__device__ __nv_bfloat16 g_Qh[MROWS*KK], g_Ql[MROWS*KK];
__device__ __nv_bfloat16 g_Kh[MROWS*KK], g_Kl[MROWS*KK];      // compacted K
__device__ __half g_Wuf[KK*KK];
__device__ __half g_Vf [MROWS*KK];                             // compacted V
__device__ __half g_ysf[MROWS*KK];
__device__ int g_idx[BB*TT];
__device__ int g_nv [BB];

// ============================================================================
// helpers
// ============================================================================
__device__ __forceinline__ uint32_t smem_u32(const void* p) {
    uint32_t a;
    asm("{ .reg .u64 t; cvta.to.shared.u64 t, %1; cvt.u32.u64 %0, t; }"
        : "=r"(a) : "l"(p));
    return a;
}

__device__ __forceinline__ void mma_bf16(float d[4],
                                         uint32_t a0, uint32_t a1, uint32_t a2, uint32_t a3,
                                         uint32_t b0, uint32_t b1) {
    asm volatile(
        "mma.sync.aligned.m16n8k16.row.col.f32.bf16.bf16.f32 "
        "{%0,%1,%2,%3}, {%4,%5,%6,%7}, {%8,%9}, {%0,%1,%2,%3};"
        : "+f"(d[0]), "+f"(d[1]), "+f"(d[2]), "+f"(d[3])
        : "r"(a0), "r"(a1), "r"(a2), "r"(a3), "r"(b0), "r"(b1));
}

__device__ __forceinline__ void mma_f16f32(float d[4],
                                           uint32_t a0, uint32_t a1, uint32_t a2, uint32_t a3,
                                           uint32_t b0, uint32_t b1) {
    asm volatile(
        "mma.sync.aligned.m16n8k16.row.col.f32.f16.f16.f32 "
        "{%0,%1,%2,%3}, {%4,%5,%6,%7}, {%8,%9}, {%0,%1,%2,%3};"
        : "+f"(d[0]), "+f"(d[1]), "+f"(d[2]), "+f"(d[3])
        : "r"(a0), "r"(a1), "r"(a2), "r"(a3), "r"(b0), "r"(b1));
}

#define LDSM4(r0, r1, r2, r3, addr) \
    asm volatile("ldmatrix.sync.aligned.m8n8.x4.shared.b16 {%0,%1,%2,%3}, [%4];" \
                 : "=r"(r0), "=r"(r1), "=r"(r2), "=r"(r3) : "r"(addr))

#define LDSM4T(r0, r1, r2, r3, addr) \
    asm volatile("ldmatrix.sync.aligned.m8n8.x4.trans.shared.b16 {%0,%1,%2,%3}, [%4];" \
                 : "=r"(r0), "=r"(r1), "=r"(r2), "=r"(r3) : "r"(addr))

__device__ __forceinline__ void split2(float2 f, uint32_t& h, uint32_t& l) {
    __nv_bfloat162 hh = __float22bfloat162_rn(f);
    float2 hf = __bfloat1622float2(hh);
    __nv_bfloat162 ll = __float22bfloat162_rn(make_float2(f.x - hf.x, f.y - hf.y));
    h = *(uint32_t*)&hh;
    l = *(uint32_t*)&ll;
}

__device__ __forceinline__ void split2h(float2 f, uint32_t& h, uint32_t& l) {
    __half2 hh = __float22half2_rn(f);
    float2 hf = __half22float2(hh);
    __half2 ll = __float22half2_rn(make_float2((f.x - hf.x) * 2048.f,
                                               (f.y - hf.y) * 2048.f));
    h = *(uint32_t*)&hh;
    l = *(uint32_t*)&ll;
}

__device__ __forceinline__ uint32_t pack_h2(float2 f) {
    __half2 hh = __float22half2_rn(f);
    return *(uint32_t*)&hh;
}

// ============================================================================
// mask compaction (2 blocks, proven)
// ============================================================================
__global__ __launch_bounds__(1024)
void compact_kernel(const int* __restrict__ mask, int* __restrict__ idx,
                    int* __restrict__ nv)
{
    __shared__ int s[1024];
    const int b = blockIdx.x;
    const int t = threadIdx.x;
    const int m0 = mask[b * TT + 2 * t];
    const int m1 = mask[b * TT + 2 * t + 1];
    const int c  = m0 + m1;
    s[t] = c;
    __syncthreads();
    for (int off = 1; off < 1024; off <<= 1) {
        int v = s[t];
        int u = (t >= off) ? s[t - off] : 0;
        __syncthreads();
        s[t] = v + u;
        __syncthreads();
    }
    const int incl = s[t];
    const int excl = incl - c;
    if (m0) idx[b * TT + excl] = 2 * t;
    if (m1) idx[b * TT + excl + m0] = 2 * t + 1;
    if (t == 1023) nv[b] = incl;
}

// ============================================================================
// common GEMM geometry
// ============================================================================
#define GBK 32
#define NIT (KK / GBK)          // 32
#define BKP 40
#define ATILE (128 * BKP)
#define PROJ_SMEM (8 * ATILE * 2)   // 81920 B

// ============================================================================
// Fused Q/K/V projection + Wu-prep kernel. FLAT LPT-ordered grid (832 CTAs):
//   bid [0,256):   K-tiles (3 MMA units, heaviest first; ~half early-exit)
//   bid [256,512): Q-tiles (2 units, all active)
//   bid [512,768): V-tiles (1 unit, lightest; ~half early-exit)
//   bid [768,832): Wu fp32->fp16 conversion filler (runs in the tail bubbles)
// ============================================================================
__global__ void __launch_bounds__(256)
proj_kernel(const float* __restrict__ x,
            const float* __restrict__ Wq,
            const float* __restrict__ Wk,
            const float* __restrict__ Wv,
            const float* __restrict__ Wu,
            const int* __restrict__ idx,
            const int* __restrict__ nvp,
            __nv_bfloat16* __restrict__ Qh, __nv_bfloat16* __restrict__ Ql,
            __nv_bfloat16* __restrict__ Kh, __nv_bfloat16* __restrict__ Kl,
            __half* __restrict__ Vf, __half* __restrict__ Wuf)
{
    extern __shared__ char smraw[];
    __shared__ int sidx[128];
    const uint32_t sbase = smem_u32(smraw);

    const int bid = blockIdx.x;

    if (bid >= 768) {
        // ---- Wu fp32 -> fp16 filler: 64 CTAs x 256 threads x 16 float4 ----
        const int base = (bid - 768) * 256 * 16 + threadIdx.x;   // float4 index
#pragma unroll
        for (int j = 0; j < 16; j++) {
            int i = base + j * 256;
            float4 f = ((const float4*)Wu)[i];
            uint2 o = { pack_h2(make_float2(f.x, f.y)), pack_h2(make_float2(f.z, f.w)) };
            ((uint2*)Wuf)[i] = o;
        }
        return;
    }

    int z, lbid;
    if (bid < 256)      { z = 1; lbid = bid; }
    else if (bid < 512) { z = 0; lbid = bid - 256; }
    else                { z = 2; lbid = bid - 512; }
    const int mt    = lbid >> 3;    // 0..31
    const int ntile = lbid & 7;     // 0..7

    const int tid  = threadIdx.x;
    const int lane = tid & 31;
    const int wid  = tid >> 5;
    const int g    = lane >> 2;
    const int tg   = lane & 3;
    const int wm   = wid & 1;
    const int wn   = wid >> 1;
    const int m0   = mt * 128;
    const int n0   = ntile * 128;

    if (z >= 1) {
        const int b = m0 / TT;
        const int s = m0 - b * TT;
        const int nvb = nvp[b];
        if (s >= nvb) return;
        if (tid < 128) {
            int ss = s + tid;
            sidx[tid] = b * TT + idx[b * TT + (ss < nvb ? ss : 0)];
        }
        __syncthreads();
    }

    const uint32_t aoff = (uint32_t)((wm * 64 + (lane & 15)) * BKP + ((lane & 16) ? 8 : 0));
    const uint32_t boff = (uint32_t)((wn * 32 + (lane & 7) + ((lane & 16) ? 8 : 0)) * BKP
                                     + ((lane & 8) ? 8 : 0));

    float4 ra[4], rb[4];

    if (z == 0) {
        const float* Agp = x  + (size_t)m0 * KK;
        const float* Bgp = Wq + (size_t)n0 * KK;

#define QLOAD(k0) do { \
    _Pragma("unroll") \
    for (int j = 0; j < 4; j++) { \
        int ix = j * 256 + tid; int row = ix >> 3; int c4 = ix & 7; \
        ra[j] = *(const float4*)(Agp + (size_t)row * KK + (k0) + c4 * 4); \
        rb[j] = *(const float4*)(Bgp + (size_t)row * KK + (k0) + c4 * 4); \
    } } while (0)

#define QSTORE(bsel) do { \
    _Pragma("unroll") \
    for (int j = 0; j < 4; j++) { \
        int ix = j * 256 + tid; int row = ix >> 3; int c4 = ix & 7; \
        uint32_t off = (uint32_t)((bsel) * 3 * ATILE + row * BKP + c4 * 4) * 2; \
        uint32_t h0, l0, h1, l1; \
        split2h(make_float2(ra[j].x, ra[j].y), h0, l0); \
        split2h(make_float2(ra[j].z, ra[j].w), h1, l1); \
        *(uint32_t*)(smraw + off)                 = h0; \
        *(uint32_t*)(smraw + off + 4)             = h1; \
        *(uint32_t*)(smraw + off + ATILE * 2)     = l0; \
        *(uint32_t*)(smraw + off + ATILE * 2 + 4) = l1; \
        *(uint32_t*)(smraw + off + 2 * ATILE * 2)     = pack_h2(make_float2(rb[j].x, rb[j].y)); \
        *(uint32_t*)(smraw + off + 2 * ATILE * 2 + 4) = pack_h2(make_float2(rb[j].z, rb[j].w)); \
    } } while (0)

        float acc [4][4][4];
        float acc2[4][4][4];
#pragma unroll
        for (int i = 0; i < 4; i++)
#pragma unroll
            for (int j = 0; j < 4; j++)
#pragma unroll
                for (int r = 0; r < 4; r++) { acc[i][j][r] = 0.f; acc2[i][j][r] = 0.f; }

        QLOAD(0);
        QSTORE(0);
        __syncthreads();

        for (int it = 0; it < NIT; it++) {
            const int buf = it & 1;
            if (it + 1 < NIT) QLOAD((it + 1) * GBK);

            const uint32_t bb = sbase + (uint32_t)(buf * 3 * ATILE) * 2;
#pragma unroll
            for (int ks = 0; ks < 2; ks++) {
                const uint32_t ko = ks * 32;
                uint32_t bf[4][2];
                LDSM4(bf[0][0], bf[0][1], bf[1][0], bf[1][1],
                      bb + 2 * ATILE * 2 + boff * 2 + ko);
                LDSM4(bf[2][0], bf[2][1], bf[3][0], bf[3][1],
                      bb + 2 * ATILE * 2 + (boff + 16 * BKP) * 2 + ko);
#pragma unroll
                for (int mf = 0; mf < 4; mf++) {
                    uint32_t ah0, ah1, ah2, ah3, al0, al1, al2, al3;
                    LDSM4(ah0, ah1, ah2, ah3, bb + (aoff + mf * 16 * BKP) * 2 + ko);
                    LDSM4(al0, al1, al2, al3, bb + ATILE * 2 + (aoff + mf * 16 * BKP) * 2 + ko);
#pragma unroll
                    for (int nf = 0; nf < 4; nf++) {
                        mma_f16f32(acc [mf][nf], ah0, ah1, ah2, ah3, bf[nf][0], bf[nf][1]);
                        mma_f16f32(acc2[mf][nf], al0, al1, al2, al3, bf[nf][0], bf[nf][1]);
                    }
                }
            }

            if (it + 1 < NIT) {
                __syncthreads();
                QSTORE(buf ^ 1);
                __syncthreads();
            }
        }
#undef QLOAD
#undef QSTORE

#pragma unroll
        for (int mf = 0; mf < 4; mf++) {
            int r0 = m0 + wm * 64 + mf * 16 + g;
#pragma unroll
            for (int nf = 0; nf < 4; nf++) {
                int col = n0 + wn * 32 + nf * 8 + tg * 2;
                float v00 = acc[mf][nf][0] + acc2[mf][nf][0] * INV2048;
                float v01 = acc[mf][nf][1] + acc2[mf][nf][1] * INV2048;
                float v10 = acc[mf][nf][2] + acc2[mf][nf][2] * INV2048;
                float v11 = acc[mf][nf][3] + acc2[mf][nf][3] * INV2048;
                uint32_t h0, l0, h1, l1;
                split2(make_float2(v00, v01), h0, l0);
                split2(make_float2(v10, v11), h1, l1);
                *(uint32_t*)&Qh[(size_t)r0 * KK + col]       = h0;
                *(uint32_t*)&Ql[(size_t)r0 * KK + col]       = l0;
                *(uint32_t*)&Qh[(size_t)(r0 + 8) * KK + col] = h1;
                *(uint32_t*)&Ql[(size_t)(r0 + 8) * KK + col] = l1;
            }
        }

    } else if (z == 1) {
        const float* Bgp = Wk + (size_t)n0 * KK;

#define KLOAD(k0) do { \
    _Pragma("unroll") \
    for (int j = 0; j < 4; j++) { \
        int ix = j * 256 + tid; int row = ix >> 3; int c4 = ix & 7; \
        ra[j] = *(const float4*)(x + (size_t)sidx[row] * KK + (k0) + c4 * 4); \
        rb[j] = *(const float4*)(Bgp + (size_t)row * KK + (k0) + c4 * 4); \
    } } while (0)

#define KSTORE(bsel) do { \
    _Pragma("unroll") \
    for (int j = 0; j < 4; j++) { \
        int ix = j * 256 + tid; int row = ix >> 3; int c4 = ix & 7; \
        uint32_t off = (uint32_t)((bsel) * 4 * ATILE + row * BKP + c4 * 4) * 2; \
        uint32_t h0, l0, h1, l1; \
        split2(make_float2(ra[j].x, ra[j].y), h0, l0); \
        split2(make_float2(ra[j].z, ra[j].w), h1, l1); \
        *(uint32_t*)(smraw + off)                 = h0; \
        *(uint32_t*)(smraw + off + 4)             = h1; \
        *(uint32_t*)(smraw + off + ATILE * 2)     = l0; \
        *(uint32_t*)(smraw + off + ATILE * 2 + 4) = l1; \
        split2(make_float2(rb[j].x, rb[j].y), h0, l0); \
        split2(make_float2(rb[j].z, rb[j].w), h1, l1); \
        *(uint32_t*)(smraw + off + 2 * ATILE * 2)     = h0; \
        *(uint32_t*)(smraw + off + 2 * ATILE * 2 + 4) = h1; \
        *(uint32_t*)(smraw + off + 3 * ATILE * 2)     = l0; \
        *(uint32_t*)(smraw + off + 3 * ATILE * 2 + 4) = l1; \
    } } while (0)

        float acc[4][4][4];
#pragma unroll
        for (int i = 0; i < 4; i++)
#pragma unroll
            for (int j = 0; j < 4; j++)
#pragma unroll
                for (int r = 0; r < 4; r++) acc[i][j][r] = 0.f;

        KLOAD(0);
        KSTORE(0);
        __syncthreads();

        for (int it = 0; it < NIT; it++) {
            const int buf = it & 1;
            if (it + 1 < NIT) KLOAD((it + 1) * GBK);

            const uint32_t bb = sbase + (uint32_t)(buf * 4 * ATILE) * 2;
#pragma unroll
            for (int ks = 0; ks < 2; ks++) {
                const uint32_t ko = ks * 32;
                uint32_t bh[4][2], bl[4][2];
                LDSM4(bh[0][0], bh[0][1], bh[1][0], bh[1][1],
                      bb + 2 * ATILE * 2 + boff * 2 + ko);
                LDSM4(bh[2][0], bh[2][1], bh[3][0], bh[3][1],
                      bb + 2 * ATILE * 2 + (boff + 16 * BKP) * 2 + ko);
                LDSM4(bl[0][0], bl[0][1], bl[1][0], bl[1][1],
                      bb + 3 * ATILE * 2 + boff * 2 + ko);
                LDSM4(bl[2][0], bl[2][1], bl[3][0], bl[3][1],
                      bb + 3 * ATILE * 2 + (boff + 16 * BKP) * 2 + ko);
#pragma unroll
                for (int mf = 0; mf < 4; mf++) {
                    uint32_t ah0, ah1, ah2, ah3, al0, al1, al2, al3;
                    LDSM4(ah0, ah1, ah2, ah3, bb + (aoff + mf * 16 * BKP) * 2 + ko);
                    LDSM4(al0, al1, al2, al3, bb + ATILE * 2 + (aoff + mf * 16 * BKP) * 2 + ko);
#pragma unroll
                    for (int nf = 0; nf < 4; nf++) {
                        mma_bf16(acc[mf][nf], ah0, ah1, ah2, ah3, bh[nf][0], bh[nf][1]);
                        mma_bf16(acc[mf][nf], ah0, ah1, ah2, ah3, bl[nf][0], bl[nf][1]);
                        mma_bf16(acc[mf][nf], al0, al1, al2, al3, bh[nf][0], bh[nf][1]);
                    }
                }
            }

            if (it + 1 < NIT) {
                __syncthreads();
                KSTORE(buf ^ 1);
                __syncthreads();
            }
        }
#undef KLOAD
#undef KSTORE

#pragma unroll
        for (int mf = 0; mf < 4; mf++) {
            int r0 = m0 + wm * 64 + mf * 16 + g;
#pragma unroll
            for (int nf = 0; nf < 4; nf++) {
                int col = n0 + wn * 32 + nf * 8 + tg * 2;
                uint32_t h0, l0, h1, l1;
                split2(make_float2(acc[mf][nf][0], acc[mf][nf][1]), h0, l0);
                split2(make_float2(acc[mf][nf][2], acc[mf][nf][3]), h1, l1);
                *(uint32_t*)&Kh[(size_t)r0 * KK + col]       = h0;
                *(uint32_t*)&Kl[(size_t)r0 * KK + col]       = l0;
                *(uint32_t*)&Kh[(size_t)(r0 + 8) * KK + col] = h1;
                *(uint32_t*)&Kl[(size_t)(r0 + 8) * KK + col] = l1;
            }
        }

    } else {
        const float* Bgp = Wv + (size_t)n0 * KK;

#define VLOAD(k0) do { \
    _Pragma("unroll") \
    for (int j = 0; j < 4; j++) { \
        int ix = j * 256 + tid; int row = ix >> 3; int c4 = ix & 7; \
        ra[j] = *(const float4*)(x + (size_t)sidx[row] * KK + (k0) + c4 * 4); \
        rb[j] = *(const float4*)(Bgp + (size_t)row * KK + (k0) + c4 * 4); \
    } } while (0)

#define VSTORE(bsel) do { \
    _Pragma("unroll") \
    for (int j = 0; j < 4; j++) { \
        int ix = j * 256 + tid; int row = ix >> 3; int c4 = ix & 7; \
        uint32_t off = (uint32_t)((bsel) * 2 * ATILE + row * BKP + c4 * 4) * 2; \
        *(uint32_t*)(smraw + off)     = pack_h2(make_float2(ra[j].x, ra[j].y)); \
        *(uint32_t*)(smraw + off + 4) = pack_h2(make_float2(ra[j].z, ra[j].w)); \
        *(uint32_t*)(smraw + off + ATILE * 2)     = pack_h2(make_float2(rb[j].x, rb[j].y)); \
        *(uint32_t*)(smraw + off + ATILE * 2 + 4) = pack_h2(make_float2(rb[j].z, rb[j].w)); \
    } } while (0)

        float acc[4][4][4];
#pragma unroll
        for (int i = 0; i < 4; i++)
#pragma unroll
            for (int j = 0; j < 4; j++)
#pragma unroll
                for (int r = 0; r < 4; r++) acc[i][j][r] = 0.f;

        VLOAD(0);
        VSTORE(0);
        __syncthreads();

        for (int it = 0; it < NIT; it++) {
            const int buf = it & 1;
            if (it + 1 < NIT) VLOAD((it + 1) * GBK);

            const uint32_t bb = sbase + (uint32_t)(buf * 2 * ATILE) * 2;
#pragma unroll
            for (int ks = 0; ks < 2; ks++) {
                const uint32_t ko = ks * 32;
                uint32_t bf[4][2];
                LDSM4(bf[0][0], bf[0][1], bf[1][0], bf[1][1],
                      bb + ATILE * 2 + boff * 2 + ko);
                LDSM4(bf[2][0], bf[2][1], bf[3][0], bf[3][1],
                      bb + ATILE * 2 + (boff + 16 * BKP) * 2 + ko);
#pragma unroll
                for (int mf = 0; mf < 4; mf++) {
                    uint32_t a0, a1, a2, a3;
                    LDSM4(a0, a1, a2, a3, bb + (aoff + mf * 16 * BKP) * 2 + ko);
#pragma unroll
                    for (int nf = 0; nf < 4; nf++)
                        mma_f16f32(acc[mf][nf], a0, a1, a2, a3, bf[nf][0], bf[nf][1]);
                }
            }

            if (it + 1 < NIT) {
                __syncthreads();
                VSTORE(buf ^ 1);
                __syncthreads();
            }
        }
#undef VLOAD
#undef VSTORE

#pragma unroll
        for (int mf = 0; mf < 4; mf++) {
            int r0 = m0 + wm * 64 + mf * 16 + g;
#pragma unroll
            for (int nf = 0; nf < 4; nf++) {
                int col = n0 + wn * 32 + nf * 8 + tg * 2;
                *(uint32_t*)&Vf[(size_t)r0 * KK + col] =
                    pack_h2(make_float2(acc[mf][nf][0], acc[mf][nf][1]));
                *(uint32_t*)&Vf[(size_t)(r0 + 8) * KK + col] =
                    pack_h2(make_float2(acc[mf][nf][2], acc[mf][nf][3]));
            }
        }
    }
}

// ============================================================================
// gemm1: 1-term fp16 via cp.async (U projection). 2 CTAs/SM.
// ============================================================================
#define G1SMEM (4 * ATILE * 2)   // 40960 B

__global__ void __launch_bounds__(256, 2)
gemm1_kernel(const __half* __restrict__ Ag,
             const __half* __restrict__ Bg,
             const float* __restrict__ bias,
             float* __restrict__ Cf,
             int M, int N)
{
    extern __shared__ __half sm1[];
    const uint32_t sbase = smem_u32(sm1);

    const int tid  = threadIdx.x;
    const int lane = tid & 31;
    const int wid  = tid >> 5;
    const int g    = lane >> 2;
    const int tg   = lane & 3;
    const int wm   = wid & 1;
    const int wn   = wid >> 1;
    const int m0   = blockIdx.y * 128;
    const int n0   = blockIdx.x * 128;

    const __half* gsrc[2] = { Ag + (size_t)m0 * KK, Bg + (size_t)n0 * KK };

    const uint32_t aoff = (uint32_t)((wm * 64 + (lane & 15)) * BKP + ((lane & 16) ? 8 : 0));
    const uint32_t boff = (uint32_t)((wn * 32 + (lane & 7) + ((lane & 16) ? 8 : 0)) * BKP
                                     + ((lane & 8) ? 8 : 0));

#define G1ISSUE(k0, bsel) do { \
    _Pragma("unroll") \
    for (int a = 0; a < 2; a++) { \
        uint32_t sd = sbase + (uint32_t)(((bsel) * 2 + a) * ATILE) * 2; \
        _Pragma("unroll") \
        for (int j = 0; j < 2; j++) { \
            int row = j * 64 + (tid >> 2); int cc = tid & 3; \
            uint32_t s = sd + (uint32_t)(row * BKP + cc * 8) * 2; \
            const __half* gp = gsrc[a] + (size_t)row * KK + (k0) + cc * 8; \
            asm volatile("cp.async.cg.shared.global [%0], [%1], 16;" :: "r"(s), "l"(gp)); \
        } \
    } \
    asm volatile("cp.async.commit_group;"); \
} while (0)

    float acc[4][4][4];
#pragma unroll
    for (int i = 0; i < 4; i++)
#pragma unroll
        for (int j = 0; j < 4; j++)
#pragma unroll
            for (int r = 0; r < 4; r++) acc[i][j][r] = 0.f;

    G1ISSUE(0, 0);

    for (int it = 0; it < NIT; it++) {
        const int buf = it & 1;
        asm volatile("cp.async.wait_group 0;");
        __syncthreads();
        if (it + 1 < NIT) G1ISSUE((it + 1) * GBK, buf ^ 1);

        const uint32_t bb = sbase + (uint32_t)(buf * 2 * ATILE) * 2;
#pragma unroll
        for (int ks = 0; ks < 2; ks++) {
            const uint32_t ko = ks * 32;
            uint32_t bf[4][2];
            LDSM4(bf[0][0], bf[0][1], bf[1][0], bf[1][1],
                  bb + ATILE * 2 + boff * 2 + ko);
            LDSM4(bf[2][0], bf[2][1], bf[3][0], bf[3][1],
                  bb + ATILE * 2 + (boff + 16 * BKP) * 2 + ko);
#pragma unroll
            for (int mf = 0; mf < 4; mf++) {
                uint32_t a0, a1, a2, a3;
                LDSM4(a0, a1, a2, a3, bb + (aoff + mf * 16 * BKP) * 2 + ko);
#pragma unroll
                for (int nf = 0; nf < 4; nf++)
                    mma_f16f32(acc[mf][nf], a0, a1, a2, a3, bf[nf][0], bf[nf][1]);
            }
        }
    }
#undef G1ISSUE

#pragma unroll
    for (int mf = 0; mf < 4; mf++) {
        int r0 = m0 + wm * 64 + mf * 16 + g;
#pragma unroll
        for (int nf = 0; nf < 4; nf++) {
            int col = n0 + wn * 32 + nf * 8 + tg * 2;
            float b0 = __ldg(&bias[col]), b1 = __ldg(&bias[col + 1]);
            float2 o0 = { acc[mf][nf][0] + b0, acc[mf][nf][1] + b1 };
            float2 o1 = { acc[mf][nf][2] + b0, acc[mf][nf][3] + b1 };
            *(float2*)&Cf[(size_t)r0 * N + col]       = o0;
            *(float2*)&Cf[(size_t)(r0 + 8) * N + col] = o1;
        }
    }
}

// ============================================================================
// Flash attention (proven round-13 body).
// ============================================================================
#define AST 72
#define KVTILE (64 * AST * 2)
#define ASTAGE (3 * KVTILE)
#define ATTN_SMEM (2 * ASTAGE)

__global__ __launch_bounds__(128, 2)
void attn_tc_kernel(const __nv_bfloat16* __restrict__ Qh_,
                    const __nv_bfloat16* __restrict__ Ql_,
                    const __nv_bfloat16* __restrict__ Kh_,
                    const __nv_bfloat16* __restrict__ Kl_,
                    const __half* __restrict__ Vf_,
                    const int* __restrict__ nvp,
                    __half* __restrict__ ysf)
{
    extern __shared__ char asmem[];
    const uint32_t sbase = smem_u32(asmem);

    const int tid  = threadIdx.x;
    const int lane = tid & 31;
    const int w    = tid >> 5;
    const int g    = lane >> 2;
    const int tg   = lane & 3;
    const int b    = blockIdx.z;
    const int h    = blockIdx.y;
    const int q0   = blockIdx.x * 128;

    const int nvb    = nvp[b];
    const int ntiles = (nvb + 63) >> 6;

    const __nv_bfloat16* Qhb = Qh_ + (size_t)(b * TT + q0 + w * 32) * KK + h * SS;
    const __nv_bfloat16* Qlb = Ql_ + (size_t)(b * TT + q0 + w * 32) * KK + h * SS;
    uint32_t qh_[2][4][4], ql_[2][4][4];
#pragma unroll
    for (int m = 0; m < 2; m++) {
#pragma unroll
        for (int ks = 0; ks < 4; ks++) {
            int r0 = m * 16 + g, r1 = r0 + 8;
            int d0 = ks * 16 + 2 * tg;
            qh_[m][ks][0] = *(const uint32_t*)(Qhb + (size_t)r0 * KK + d0);
            qh_[m][ks][1] = *(const uint32_t*)(Qhb + (size_t)r1 * KK + d0);
            qh_[m][ks][2] = *(const uint32_t*)(Qhb + (size_t)r0 * KK + d0 + 8);
            qh_[m][ks][3] = *(const uint32_t*)(Qhb + (size_t)r1 * KK + d0 + 8);
            ql_[m][ks][0] = *(const uint32_t*)(Qlb + (size_t)r0 * KK + d0);
            ql_[m][ks][1] = *(const uint32_t*)(Qlb + (size_t)r1 * KK + d0);
            ql_[m][ks][2] = *(const uint32_t*)(Qlb + (size_t)r0 * KK + d0 + 8);
            ql_[m][ks][3] = *(const uint32_t*)(Qlb + (size_t)r1 * KK + d0 + 8);
        }
    }

    float o[2][8][4];
#pragma unroll
    for (int m = 0; m < 2; m++)
#pragma unroll
        for (int nt = 0; nt < 8; nt++)
#pragma unroll
            for (int c = 0; c < 4; c++) o[m][nt][c] = 0.f;
    float mr[2][2] = { {-1e30f, -1e30f}, {-1e30f, -1e30f} };
    float lr[2][2] = { {0.f, 0.f}, {0.f, 0.f} };

    const __nv_bfloat16* Khb = Kh_ + (size_t)b * TT * KK + h * SS;
    const __nv_bfloat16* Klb = Kl_ + (size_t)b * TT * KK + h * SS;
    const __half*        Vfb = Vf_ + (size_t)b * TT * KK + h * SS;

    const uint32_t vlb = (uint32_t)((lane & 15) * AST + ((lane & 16) ? 8 : 0)) * 2;

#define AISSUE(kt, st) do { \
    uint32_t sd = sbase + (uint32_t)(st) * ASTAGE; \
    _Pragma("unroll") \
    for (int i = 0; i < 4; i++) { \
        int ix = i * 128 + tid; int row = ix >> 3; int ch = ix & 7; \
        uint32_t dd = sd + (uint32_t)(row * AST * 2 + ch * 16); \
        const __nv_bfloat16* s0 = Khb + (size_t)((kt) * 64 + row) * KK + ch * 8; \
        const __nv_bfloat16* s1 = Klb + (size_t)((kt) * 64 + row) * KK + ch * 8; \
        const __half*        s2 = Vfb + (size_t)((kt) * 64 + row) * KK + ch * 8; \
        asm volatile("cp.async.cg.shared.global [%0], [%1], 16;" :: "r"(dd), "l"(s0)); \
        asm volatile("cp.async.cg.shared.global [%0], [%1], 16;" :: "r"(dd + KVTILE), "l"(s1)); \
        asm volatile("cp.async.cg.shared.global [%0], [%1], 16;" :: "r"(dd + 2 * KVTILE), "l"(s2)); \
    } \
    asm volatile("cp.async.commit_group;"); \
} while (0)

    AISSUE(0, 0);

    for (int kt = 0; kt < ntiles; kt++) {
        const int st = kt & 1;
        __syncthreads();
        if (kt + 1 < ntiles) {
            AISSUE(kt + 1, st ^ 1);
            asm volatile("cp.async.wait_group 1;");
        } else {
            asm volatile("cp.async.wait_group 0;");
        }
        __syncthreads();

        const char* stage = asmem + st * ASTAGE;
        const __nv_bfloat16* kh = (const __nv_bfloat16*)stage;
        const __nv_bfloat16* kl = (const __nv_bfloat16*)(stage + KVTILE);
        const uint32_t vbase = sbase + (uint32_t)st * ASTAGE + 2 * KVTILE;

        float s[2][8][4];
#pragma unroll
        for (int m = 0; m < 2; m++)
#pragma unroll
            for (int nt = 0; nt < 8; nt++)
#pragma unroll
                for (int c = 0; c < 4; c++) s[m][nt][c] = 0.f;

#pragma unroll
        for (int ks = 0; ks < 4; ks++) {
            const int kk = ks * 16 + 2 * tg;
#pragma unroll
            for (int nt = 0; nt < 8; nt++) {
                const int rr = (nt * 8 + g) * AST + kk;
                uint32_t bh0 = *(const uint32_t*)&kh[rr];
                uint32_t bh1 = *(const uint32_t*)&kh[rr + 8];
                uint32_t bl0 = *(const uint32_t*)&kl[rr];
                uint32_t bl1 = *(const uint32_t*)&kl[rr + 8];
#pragma unroll
                for (int m = 0; m < 2; m++) {
                    mma_bf16(s[m][nt], qh_[m][ks][0], qh_[m][ks][1], qh_[m][ks][2], qh_[m][ks][3], bh0, bh1);
                    mma_bf16(s[m][nt], qh_[m][ks][0], qh_[m][ks][1], qh_[m][ks][2], qh_[m][ks][3], bl0, bl1);
                    mma_bf16(s[m][nt], ql_[m][ks][0], ql_[m][ks][1], ql_[m][ks][2], ql_[m][ks][3], bh0, bh1);
                }
            }
        }

        if (kt * 64 + 64 > nvb) {
#pragma unroll
            for (int nt = 0; nt < 8; nt++) {
                int c0 = kt * 64 + nt * 8 + 2 * tg;
                if (c0 >= nvb) {
                    s[0][nt][0] = s[0][nt][2] = -1e30f;
                    s[1][nt][0] = s[1][nt][2] = -1e30f;
                }
                if (c0 + 1 >= nvb) {
                    s[0][nt][1] = s[0][nt][3] = -1e30f;
                    s[1][nt][1] = s[1][nt][3] = -1e30f;
                }
            }
        }

#pragma unroll
        for (int m = 0; m < 2; m++) {
#pragma unroll
            for (int r2 = 0; r2 < 2; r2++) {
                const int c0 = r2 * 2;
                float tmax = -1e30f;
#pragma unroll
                for (int nt = 0; nt < 8; nt++) {
                    tmax = fmaxf(tmax, s[m][nt][c0]);
                    tmax = fmaxf(tmax, s[m][nt][c0 + 1]);
                }
                tmax = fmaxf(tmax, __shfl_xor_sync(0xffffffffu, tmax, 1));
                tmax = fmaxf(tmax, __shfl_xor_sync(0xffffffffu, tmax, 2));
                float mn = fmaxf(mr[m][r2], tmax);
                float sc = __expf(mr[m][r2] - mn);
                mr[m][r2] = mn;
                float ts = 0.f;
#pragma unroll
                for (int nt = 0; nt < 8; nt++) {
                    float p0 = __expf(s[m][nt][c0]     - mn);
                    float p1 = __expf(s[m][nt][c0 + 1] - mn);
                    s[m][nt][c0]     = p0;
                    s[m][nt][c0 + 1] = p1;
                    ts += p0 + p1;
                }
                ts += __shfl_xor_sync(0xffffffffu, ts, 1);
                ts += __shfl_xor_sync(0xffffffffu, ts, 2);
                lr[m][r2] = lr[m][r2] * sc + ts;
#pragma unroll
                for (int nt = 0; nt < 8; nt++) {
                    o[m][nt][c0]     *= sc;
                    o[m][nt][c0 + 1] *= sc;
                }
            }
        }

#pragma unroll
        for (int ks = 0; ks < 4; ks++) {
            uint32_t ph[2][4];
#pragma unroll
            for (int m = 0; m < 2; m++) {
                ph[m][0] = pack_h2(make_float2(s[m][2*ks][0],   s[m][2*ks][1]));
                ph[m][1] = pack_h2(make_float2(s[m][2*ks][2],   s[m][2*ks][3]));
                ph[m][2] = pack_h2(make_float2(s[m][2*ks+1][0], s[m][2*ks+1][1]));
                ph[m][3] = pack_h2(make_float2(s[m][2*ks+1][2], s[m][2*ks+1][3]));
            }
            const uint32_t krow = (uint32_t)(ks * 16 * AST * 2);
#pragma unroll
            for (int dp = 0; dp < 4; dp++) {
                uint32_t v0, v1, v2, v3;
                LDSM4T(v0, v1, v2, v3, vbase + krow + (uint32_t)(dp * 32) + vlb);
#pragma unroll
                for (int m = 0; m < 2; m++) {
                    mma_f16f32(o[m][2*dp],     ph[m][0], ph[m][1], ph[m][2], ph[m][3], v0, v1);
                    mma_f16f32(o[m][2*dp + 1], ph[m][0], ph[m][1], ph[m][2], ph[m][3], v2, v3);
                }
            }
        }
    }
#undef AISSUE

#pragma unroll
    for (int m = 0; m < 2; m++) {
#pragma unroll
        for (int r2 = 0; r2 < 2; r2++) {
            float inv = 1.f / lr[m][r2];
            int row = q0 + w * 32 + m * 16 + g + r2 * 8;
            size_t off = (size_t)(b * TT + row) * KK + h * SS;
#pragma unroll
            for (int nt = 0; nt < 8; nt++) {
                *(uint32_t*)&ysf[off + nt * 8 + 2 * tg] =
                    pack_h2(make_float2(o[m][nt][r2*2] * inv, o[m][nt][r2*2+1] * inv));
            }
        }
    }
}

// ============================================================================
// launch
// ============================================================================
extern "C" void kernel_launch(void* const* d_in, const int* in_sizes, int n_in,
                              void* d_out, int out_size)
{
    const float* x    = (const float*)d_in[0];
    const int*   mask = (const int*)  d_in[1];
    const float* Wk   = (const float*)d_in[2];
    const float* Wq   = (const float*)d_in[3];
    const float* Wv   = (const float*)d_in[4];
    const float* Wu   = (const float*)d_in[5];
    const float* bu   = (const float*)d_in[6];
    float* out = (float*)d_out;

    __nv_bfloat16 *Qh, *Ql, *Kh, *Kl;
    __half *Wuf, *Vf, *ysf;
    int *idx, *nv;
    cudaGetSymbolAddress((void**)&Qh,  g_Qh);  cudaGetSymbolAddress((void**)&Ql,  g_Ql);
    cudaGetSymbolAddress((void**)&Kh,  g_Kh);  cudaGetSymbolAddress((void**)&Kl,  g_Kl);
    cudaGetSymbolAddress((void**)&Wuf, g_Wuf);
    cudaGetSymbolAddress((void**)&Vf,  g_Vf);  cudaGetSymbolAddress((void**)&ysf, g_ysf);
    cudaGetSymbolAddress((void**)&idx, g_idx); cudaGetSymbolAddress((void**)&nv,  g_nv);

    cudaFuncSetAttribute(proj_kernel,
                         cudaFuncAttributeMaxDynamicSharedMemorySize, PROJ_SMEM);
    cudaFuncSetAttribute(gemm1_kernel,
                         cudaFuncAttributeMaxDynamicSharedMemorySize, G1SMEM);
    cudaFuncSetAttribute(attn_tc_kernel,
                         cudaFuncAttributeMaxDynamicSharedMemorySize, ATTN_SMEM);

    compact_kernel<<<BB, 1024>>>(mask, idx, nv);

    // LPT flat grid: 256 K + 256 Q + 256 V tiles, then 64 Wu-prep fillers
    proj_kernel<<<832, 256, PROJ_SMEM>>>(x, Wq, Wk, Wv, Wu, idx, nv,
                                         Qh, Ql, Kh, Kl, Vf, Wuf);

    dim3 ga(TT / 128, HH, BB);           // (16, 16, 2)
    attn_tc_kernel<<<ga, 128, ATTN_SMEM>>>(Qh, Ql, Kh, Kl, Vf, nv, ysf);

    dim3 gu(KK / 128, MROWS / 128);      // (8, 32)
    gemm1_kernel<<<gu, 256, G1SMEM>>>(ysf, Wuf, bu, out, MROWS, KK);
}